// round 1
// baseline (speedup 1.0000x reference)
#include <cuda_runtime.h>
#include <cuda_bf16.h>
#include <math.h>
#include <float.h>

// Problem constants
#define B_  2
#define S_  2048
#define HID_ 4096
#define H_  32
#define HKV_ 8
#define D_  128
#define M_  (B_ * S_)   // 4096 rows of x

// Scratch (device globals; allocation in kernel_launch is forbidden)
__device__ float g_q[(size_t)B_ * S_ * H_ * D_];     // 67 MB
__device__ float g_k[(size_t)B_ * S_ * HKV_ * D_];   // 16.8 MB
__device__ float g_v[(size_t)B_ * S_ * HKV_ * D_];   // 16.8 MB
__device__ float g_o[(size_t)B_ * S_ * H_ * D_];     // 67 MB

// ---------------------------------------------------------------------------
// SGEMM: C[M,N] = A[M,K] @ B[K,N], all row-major fp32.
// 128x128 block tile, BK=8, 256 threads, 8x8 register tile per thread.
// All dims used are multiples of 128 (M=4096, N in {4096,1024}, K=4096).
// ---------------------------------------------------------------------------
__global__ __launch_bounds__(256) void sgemm_k(const float* __restrict__ A,
                                               const float* __restrict__ Bm,
                                               float* __restrict__ C,
                                               int M, int N, int K)
{
    constexpr int BM = 128, BN = 128, BK = 8, TM = 8, TN = 8;
    __shared__ float As[BK][BM];   // A tile stored transposed
    __shared__ float Bs[BK][BN];

    const int tid = threadIdx.x;
    const float* Ab = A + (size_t)blockIdx.y * BM * K;
    const float* Bb = Bm + (size_t)blockIdx.x * BN;
    float* Cb = C + (size_t)blockIdx.y * BM * N + (size_t)blockIdx.x * BN;

    const int aRow = tid >> 1;            // 0..127
    const int aCol = (tid & 1) << 2;      // 0 or 4
    const int bRow = tid >> 5;            // 0..7
    const int bCol = (tid & 31) << 2;     // 0..124
    const int tRow = (tid >> 4) * TM;     // 0..120
    const int tCol = (tid & 15) * TN;     // 0..120

    float acc[TM][TN];
    #pragma unroll
    for (int i = 0; i < TM; ++i)
        #pragma unroll
        for (int j = 0; j < TN; ++j) acc[i][j] = 0.f;

    for (int k0 = 0; k0 < K; k0 += BK) {
        float4 a4 = *reinterpret_cast<const float4*>(Ab + (size_t)aRow * K + k0 + aCol);
        As[aCol + 0][aRow] = a4.x;
        As[aCol + 1][aRow] = a4.y;
        As[aCol + 2][aRow] = a4.z;
        As[aCol + 3][aRow] = a4.w;
        *reinterpret_cast<float4*>(&Bs[bRow][bCol]) =
            *reinterpret_cast<const float4*>(Bb + (size_t)(k0 + bRow) * N + bCol);
        __syncthreads();

        #pragma unroll
        for (int kk = 0; kk < BK; ++kk) {
            float ra[TM], rb[TN];
            *reinterpret_cast<float4*>(ra)     = *reinterpret_cast<float4*>(&As[kk][tRow]);
            *reinterpret_cast<float4*>(ra + 4) = *reinterpret_cast<float4*>(&As[kk][tRow + 4]);
            *reinterpret_cast<float4*>(rb)     = *reinterpret_cast<float4*>(&Bs[kk][tCol]);
            *reinterpret_cast<float4*>(rb + 4) = *reinterpret_cast<float4*>(&Bs[kk][tCol + 4]);
            #pragma unroll
            for (int i = 0; i < TM; ++i)
                #pragma unroll
                for (int j = 0; j < TN; ++j)
                    acc[i][j] += ra[i] * rb[j];
        }
        __syncthreads();
    }

    #pragma unroll
    for (int i = 0; i < TM; ++i)
        #pragma unroll
        for (int j = 0; j < TN; j += 4) {
            float4 v = make_float4(acc[i][j], acc[i][j+1], acc[i][j+2], acc[i][j+3]);
            *reinterpret_cast<float4*>(Cb + (size_t)(tRow + i) * N + tCol + j) = v;
        }
}

// ---------------------------------------------------------------------------
// RoPE in-place on [B, S, nh, D] fp32. One thread per (b,s,h,i), i < D/2.
// ---------------------------------------------------------------------------
__global__ void rope_k(float* __restrict__ x, int nh, int total)
{
    int idx = blockIdx.x * blockDim.x + threadIdx.x;
    if (idx >= total) return;
    const int half = D_ / 2;  // 64
    int i = idx & (half - 1);
    int rest = idx >> 6;             // / 64
    int h = rest % nh;
    rest /= nh;
    int s = rest % S_;
    int b = rest / S_;

    float inv = __expf(-logf(10000.0f) * (float)i / (float)half);
    float ang = (float)s * inv;
    float sn, cs;
    sincosf(ang, &sn, &cs);

    float* base = x + ((size_t)((b * S_ + s) * nh + h)) * D_;
    float x1 = base[i];
    float x2 = base[i + half];
    base[i]        = x1 * cs - x2 * sn;
    base[i + half] = x2 * cs + x1 * sn;
}

// ---------------------------------------------------------------------------
// Flash attention (fp32, causal, GQA rep=4).
// Grid (S/64, H, B), 256 threads. 64-row Q tile, 64-row KV tiles, online softmax.
// ---------------------------------------------------------------------------
__global__ __launch_bounds__(256) void flash_k(const float* __restrict__ Qg,
                                               const float* __restrict__ Kg,
                                               const float* __restrict__ Vg,
                                               float* __restrict__ Og)
{
    constexpr int QS = 132;   // padded row stride (floats) for Q/K/V tiles
    constexpr int SS = 65;    // padded row stride for score tile
    extern __shared__ float sm[];
    float* Qs  = sm;                    // 64*132
    float* Ks  = Qs + 64 * QS;          // 64*132
    float* Vs  = Ks + 64 * QS;          // 64*132
    float* Sc  = Vs + 64 * QS;          // 64*65
    float* m_s = Sc + 64 * SS;          // 64
    float* l_s = m_s + 64;              // 64
    float* a_s = l_s + 64;              // 64

    const int tid   = threadIdx.x;
    const int qtile = blockIdx.x;
    const int h     = blockIdx.y;
    const int b     = blockIdx.z;
    const int q0    = qtile * 64;
    const int kvh   = h >> 2;           // H/HKV = 4

    // Load Q tile (rows q0..q0+63 of head h)
    #pragma unroll
    for (int it = 0; it < 8; ++it) {
        int li  = it * 256 + tid;        // float4 index, 0..2047
        int row = li >> 5;               // 32 float4 per 128-float row
        int c4  = (li & 31) << 2;
        const float* src = Qg + ((size_t)((b * S_ + q0 + row) * H_ + h)) * D_ + c4;
        *reinterpret_cast<float4*>(&Qs[row * QS + c4]) =
            *reinterpret_cast<const float4*>(src);
    }
    if (tid < 64) { m_s[tid] = -INFINITY; l_s[tid] = 0.f; }

    float o[32];
    #pragma unroll
    for (int j = 0; j < 32; ++j) o[j] = 0.f;

    const int r_pv = tid >> 2;          // PV mapping: row
    const int dseg = (tid & 3) * 32;    // PV mapping: 32-col slice of D
    const int tRow = tid >> 4;          // score mapping: 0..15
    const int tCol = tid & 15;          // score mapping: 0..15
    const float scale = 0.08838834764831845f;  // 1/sqrt(128)

    __syncthreads();

    for (int t = 0; t <= qtile; ++t) {
        const int kv0 = t * 64;

        // Load K tile
        #pragma unroll
        for (int it = 0; it < 8; ++it) {
            int li  = it * 256 + tid;
            int row = li >> 5;
            int c4  = (li & 31) << 2;
            const float* src = Kg + ((size_t)((b * S_ + kv0 + row) * HKV_ + kvh)) * D_ + c4;
            *reinterpret_cast<float4*>(&Ks[row * QS + c4]) =
                *reinterpret_cast<const float4*>(src);
        }
        __syncthreads();

        // Scores: thread computes rows (tRow + 16i), cols (tCol + 16j)
        float s[4][4];
        #pragma unroll
        for (int i = 0; i < 4; ++i)
            #pragma unroll
            for (int j = 0; j < 4; ++j) s[i][j] = 0.f;

        for (int d = 0; d < D_; d += 4) {
            float4 q4[4], k4[4];
            #pragma unroll
            for (int i = 0; i < 4; ++i)
                q4[i] = *reinterpret_cast<float4*>(&Qs[(tRow + 16 * i) * QS + d]);
            #pragma unroll
            for (int j = 0; j < 4; ++j)
                k4[j] = *reinterpret_cast<float4*>(&Ks[(tCol + 16 * j) * QS + d]);
            #pragma unroll
            for (int i = 0; i < 4; ++i)
                #pragma unroll
                for (int j = 0; j < 4; ++j) {
                    s[i][j] += q4[i].x * k4[j].x;
                    s[i][j] += q4[i].y * k4[j].y;
                    s[i][j] += q4[i].z * k4[j].z;
                    s[i][j] += q4[i].w * k4[j].w;
                }
        }

        // Store scaled + causally-masked scores
        #pragma unroll
        for (int i = 0; i < 4; ++i)
            #pragma unroll
            for (int j = 0; j < 4; ++j) {
                int r = tRow + 16 * i, c = tCol + 16 * j;
                float val = s[i][j] * scale;
                if (kv0 + c > q0 + r) val = -1e30f;
                Sc[r * SS + c] = val;
            }

        // Load V tile (independent buffer; visible after next barrier)
        #pragma unroll
        for (int it = 0; it < 8; ++it) {
            int li  = it * 256 + tid;
            int row = li >> 5;
            int c4  = (li & 31) << 2;
            const float* src = Vg + ((size_t)((b * S_ + kv0 + row) * HKV_ + kvh)) * D_ + c4;
            *reinterpret_cast<float4*>(&Vs[row * QS + c4]) =
                *reinterpret_cast<const float4*>(src);
        }
        __syncthreads();

        // Online softmax bookkeeping: one thread per row
        if (tid < 64) {
            const int r = tid;
            float mo = m_s[r];
            float mx = mo;
            #pragma unroll 8
            for (int c = 0; c < 64; ++c) mx = fmaxf(mx, Sc[r * SS + c]);
            float alpha = (mo == -INFINITY) ? 0.f : __expf(fmaxf(mo - mx, -80.f));
            float sum = 0.f;
            #pragma unroll 8
            for (int c = 0; c < 64; ++c) {
                float p = __expf(fmaxf(Sc[r * SS + c] - mx, -80.f));
                Sc[r * SS + c] = p;
                sum += p;
            }
            l_s[r] = l_s[r] * alpha + sum;
            m_s[r] = mx;
            a_s[r] = alpha;
        }
        __syncthreads();

        // Rescale accumulator and add P @ V
        {
            float alpha = a_s[r_pv];
            #pragma unroll
            for (int j = 0; j < 32; ++j) o[j] *= alpha;
            #pragma unroll 4
            for (int c = 0; c < 64; ++c) {
                float p = Sc[r_pv * SS + c];
                const float* vrow = &Vs[c * QS + dseg];
                #pragma unroll
                for (int j4 = 0; j4 < 8; ++j4) {
                    float4 v = *reinterpret_cast<const float4*>(vrow + j4 * 4);
                    o[j4 * 4 + 0] += p * v.x;
                    o[j4 * 4 + 1] += p * v.y;
                    o[j4 * 4 + 2] += p * v.z;
                    o[j4 * 4 + 3] += p * v.w;
                }
            }
        }
        __syncthreads();
    }

    // Finalize: divide by l, write out
    float inv_l = 1.f / l_s[r_pv];
    float* dst = Og + ((size_t)((b * S_ + q0 + r_pv) * H_ + h)) * D_ + dseg;
    #pragma unroll
    for (int j4 = 0; j4 < 8; ++j4) {
        float4 v = make_float4(o[j4*4+0] * inv_l, o[j4*4+1] * inv_l,
                               o[j4*4+2] * inv_l, o[j4*4+3] * inv_l);
        *reinterpret_cast<float4*>(dst + j4 * 4) = v;
    }
}

// ---------------------------------------------------------------------------
// Launcher
// ---------------------------------------------------------------------------
extern "C" void kernel_launch(void* const* d_in, const int* in_sizes, int n_in,
                              void* d_out, int out_size)
{
    const float* x  = (const float*)d_in[0];
    const float* wq = (const float*)d_in[1];
    const float* wk = (const float*)d_in[2];
    const float* wv = (const float*)d_in[3];
    const float* wo = (const float*)d_in[4];
    float* out = (float*)d_out;

    float *qp, *kp, *vp, *op;
    cudaGetSymbolAddress((void**)&qp, g_q);
    cudaGetSymbolAddress((void**)&kp, g_k);
    cudaGetSymbolAddress((void**)&vp, g_v);
    cudaGetSymbolAddress((void**)&op, g_o);

    // QKV projections
    sgemm_k<<<dim3(HID_ / 128, M_ / 128), 256>>>(x, wq, qp, M_, HID_, HID_);
    sgemm_k<<<dim3((HKV_ * D_) / 128, M_ / 128), 256>>>(x, wk, kp, M_, HKV_ * D_, HID_);
    sgemm_k<<<dim3((HKV_ * D_) / 128, M_ / 128), 256>>>(x, wv, vp, M_, HKV_ * D_, HID_);

    // RoPE on q and k
    {
        int totq = B_ * S_ * H_ * (D_ / 2);
        rope_k<<<(totq + 255) / 256, 256>>>(qp, H_, totq);
        int totk = B_ * S_ * HKV_ * (D_ / 2);
        rope_k<<<(totk + 255) / 256, 256>>>(kp, HKV_, totk);
    }

    // Flash attention
    {
        const int smem_bytes = (3 * 64 * 132 + 64 * 65 + 3 * 64) * (int)sizeof(float);
        cudaFuncSetAttribute(flash_k, cudaFuncAttributeMaxDynamicSharedMemorySize, smem_bytes);
        flash_k<<<dim3(S_ / 64, H_, B_), 256, smem_bytes>>>(qp, kp, vp, op);
    }

    // Output projection
    sgemm_k<<<dim3(HID_ / 128, M_ / 128), 256>>>(op, wo, out, M_, HID_, HID_);
}

// round 2
// speedup vs baseline: 1.1563x; 1.1563x over previous
#include <cuda_runtime.h>
#include <cuda_bf16.h>
#include <mma.h>
#include <math.h>
#include <float.h>

using namespace nvcuda;

// Problem constants
#define B_  2
#define S_  2048
#define HID_ 4096
#define H_  32
#define HKV_ 8
#define D_  128
#define M_  (B_ * S_)   // 4096 rows of x

// Scratch (device globals; allocation in kernel_launch is forbidden)
__device__ float g_q[(size_t)B_ * S_ * H_ * D_];     // 67 MB
__device__ float g_k[(size_t)B_ * S_ * HKV_ * D_];   // 16.8 MB
__device__ float g_v[(size_t)B_ * S_ * HKV_ * D_];   // 16.8 MB
__device__ float g_o[(size_t)B_ * S_ * H_ * D_];     // 67 MB

// ---------------------------------------------------------------------------
// TF32 tensor-core GEMM: C[M,N] = A[M,K] @ B[K,N], row-major fp32 in/out.
// 128x128 block tile, BK=32, 256 threads (8 warps in 4x2 grid),
// warp tile 32x64 = 2x4 wmma m16n16k8 fragments.
// Requires M%128==0, N%128==0, K%32==0 (true for all uses here).
// ---------------------------------------------------------------------------
constexpr int GBM = 128, GBN = 128, GBK = 32;
constexpr int GLDA = GBK + 8;   // 40 floats  (pad vs bank conflicts)
constexpr int GLDB = GBN + 8;   // 136 floats

__global__ __launch_bounds__(256) void gemm_tf32(const float* __restrict__ A,
                                                 const float* __restrict__ Bm,
                                                 float* __restrict__ C,
                                                 int M, int N, int K)
{
    __shared__ float As[GBM * GLDA];
    __shared__ float Bs[GBK * GLDB];

    const int tid  = threadIdx.x;
    const int warp = tid >> 5;
    const int wr   = warp >> 1;       // 0..3 -> 32-row strip
    const int wc   = warp & 1;        // 0..1 -> 64-col strip

    const size_t bm0 = (size_t)blockIdx.y * GBM;
    const size_t bn0 = (size_t)blockIdx.x * GBN;

    wmma::fragment<wmma::accumulator, 16, 16, 8, float> acc[2][4];
    #pragma unroll
    for (int m = 0; m < 2; ++m)
        #pragma unroll
        for (int n = 0; n < 4; ++n)
            wmma::fill_fragment(acc[m][n], 0.0f);

    for (int k0 = 0; k0 < K; k0 += GBK) {
        // Load A tile: 128 x 32 floats (1024 float4, 4 per thread)
        #pragma unroll
        for (int i = 0; i < 4; ++i) {
            int idx = i * 256 + tid;
            int row = idx >> 3;
            int col = (idx & 7) << 2;
            float4 v = *reinterpret_cast<const float4*>(
                A + (bm0 + row) * K + k0 + col);
            *reinterpret_cast<float4*>(&As[row * GLDA + col]) = v;
        }
        // Load B tile: 32 x 128 floats (1024 float4, 4 per thread)
        #pragma unroll
        for (int i = 0; i < 4; ++i) {
            int idx = i * 256 + tid;
            int row = idx >> 5;
            int col = (idx & 31) << 2;
            float4 v = *reinterpret_cast<const float4*>(
                Bm + (size_t)(k0 + row) * N + bn0 + col);
            *reinterpret_cast<float4*>(&Bs[row * GLDB + col]) = v;
        }
        __syncthreads();

        #pragma unroll
        for (int kk = 0; kk < GBK; kk += 8) {
            wmma::fragment<wmma::matrix_a, 16, 16, 8, wmma::precision::tf32,
                           wmma::row_major> af[2];
            wmma::fragment<wmma::matrix_b, 16, 16, 8, wmma::precision::tf32,
                           wmma::row_major> bf[4];
            #pragma unroll
            for (int m = 0; m < 2; ++m) {
                wmma::load_matrix_sync(af[m],
                    &As[(wr * 32 + m * 16) * GLDA + kk], GLDA);
                #pragma unroll
                for (int e = 0; e < af[m].num_elements; ++e)
                    af[m].x[e] = wmma::__float_to_tf32(af[m].x[e]);
            }
            #pragma unroll
            for (int n = 0; n < 4; ++n) {
                wmma::load_matrix_sync(bf[n],
                    &Bs[kk * GLDB + wc * 64 + n * 16], GLDB);
                #pragma unroll
                for (int e = 0; e < bf[n].num_elements; ++e)
                    bf[n].x[e] = wmma::__float_to_tf32(bf[n].x[e]);
            }
            #pragma unroll
            for (int m = 0; m < 2; ++m)
                #pragma unroll
                for (int n = 0; n < 4; ++n)
                    wmma::mma_sync(acc[m][n], af[m], bf[n], acc[m][n]);
        }
        __syncthreads();
    }

    #pragma unroll
    for (int m = 0; m < 2; ++m)
        #pragma unroll
        for (int n = 0; n < 4; ++n)
            wmma::store_matrix_sync(
                C + (bm0 + wr * 32 + m * 16) * N + bn0 + wc * 64 + n * 16,
                acc[m][n], N, wmma::mem_row_major);
}

// ---------------------------------------------------------------------------
// RoPE in-place on [B, S, nh, D] fp32. One thread per (b,s,h,i), i < D/2.
// ---------------------------------------------------------------------------
__global__ void rope_k(float* __restrict__ x, int nh, int total)
{
    int idx = blockIdx.x * blockDim.x + threadIdx.x;
    if (idx >= total) return;
    const int half = D_ / 2;  // 64
    int i = idx & (half - 1);
    int rest = idx >> 6;             // / 64
    int h = rest % nh;
    rest /= nh;
    int s = rest % S_;
    int b = rest / S_;

    float inv = __expf(-logf(10000.0f) * (float)i / (float)half);
    float ang = (float)s * inv;
    float sn, cs;
    sincosf(ang, &sn, &cs);

    float* base = x + ((size_t)((b * S_ + s) * nh + h)) * D_;
    float x1 = base[i];
    float x2 = base[i + half];
    base[i]        = x1 * cs - x2 * sn;
    base[i + half] = x2 * cs + x1 * sn;
}

// ---------------------------------------------------------------------------
// Flash attention (fp32, causal, GQA rep=4).
// Grid (S/64, H, B), 256 threads. 64-row Q tile, 64-row KV tiles, online softmax.
// ---------------------------------------------------------------------------
__global__ __launch_bounds__(256) void flash_k(const float* __restrict__ Qg,
                                               const float* __restrict__ Kg,
                                               const float* __restrict__ Vg,
                                               float* __restrict__ Og)
{
    constexpr int QS = 132;   // padded row stride (floats) for Q/K/V tiles
    constexpr int SS = 65;    // padded row stride for score tile
    extern __shared__ float sm[];
    float* Qs  = sm;                    // 64*132
    float* Ks  = Qs + 64 * QS;          // 64*132
    float* Vs  = Ks + 64 * QS;          // 64*132
    float* Sc  = Vs + 64 * QS;          // 64*65
    float* m_s = Sc + 64 * SS;          // 64
    float* l_s = m_s + 64;              // 64
    float* a_s = l_s + 64;              // 64

    const int tid   = threadIdx.x;
    const int qtile = blockIdx.x;
    const int h     = blockIdx.y;
    const int b     = blockIdx.z;
    const int q0    = qtile * 64;
    const int kvh   = h >> 2;           // H/HKV = 4

    // Load Q tile (rows q0..q0+63 of head h)
    #pragma unroll
    for (int it = 0; it < 8; ++it) {
        int li  = it * 256 + tid;        // float4 index, 0..2047
        int row = li >> 5;               // 32 float4 per 128-float row
        int c4  = (li & 31) << 2;
        const float* src = Qg + ((size_t)((b * S_ + q0 + row) * H_ + h)) * D_ + c4;
        *reinterpret_cast<float4*>(&Qs[row * QS + c4]) =
            *reinterpret_cast<const float4*>(src);
    }
    if (tid < 64) { m_s[tid] = -INFINITY; l_s[tid] = 0.f; }

    float o[32];
    #pragma unroll
    for (int j = 0; j < 32; ++j) o[j] = 0.f;

    const int r_pv = tid >> 2;          // PV mapping: row
    const int dseg = (tid & 3) * 32;    // PV mapping: 32-col slice of D
    const int tRow = tid >> 4;          // score mapping: 0..15
    const int tCol = tid & 15;          // score mapping: 0..15
    const float scale = 0.08838834764831845f;  // 1/sqrt(128)

    __syncthreads();

    for (int t = 0; t <= qtile; ++t) {
        const int kv0 = t * 64;

        // Load K tile
        #pragma unroll
        for (int it = 0; it < 8; ++it) {
            int li  = it * 256 + tid;
            int row = li >> 5;
            int c4  = (li & 31) << 2;
            const float* src = Kg + ((size_t)((b * S_ + kv0 + row) * HKV_ + kvh)) * D_ + c4;
            *reinterpret_cast<float4*>(&Ks[row * QS + c4]) =
                *reinterpret_cast<const float4*>(src);
        }
        __syncthreads();

        // Scores: thread computes rows (tRow + 16i), cols (tCol + 16j)
        float s[4][4];
        #pragma unroll
        for (int i = 0; i < 4; ++i)
            #pragma unroll
            for (int j = 0; j < 4; ++j) s[i][j] = 0.f;

        for (int d = 0; d < D_; d += 4) {
            float4 q4[4], k4[4];
            #pragma unroll
            for (int i = 0; i < 4; ++i)
                q4[i] = *reinterpret_cast<float4*>(&Qs[(tRow + 16 * i) * QS + d]);
            #pragma unroll
            for (int j = 0; j < 4; ++j)
                k4[j] = *reinterpret_cast<float4*>(&Ks[(tCol + 16 * j) * QS + d]);
            #pragma unroll
            for (int i = 0; i < 4; ++i)
                #pragma unroll
                for (int j = 0; j < 4; ++j) {
                    s[i][j] += q4[i].x * k4[j].x;
                    s[i][j] += q4[i].y * k4[j].y;
                    s[i][j] += q4[i].z * k4[j].z;
                    s[i][j] += q4[i].w * k4[j].w;
                }
        }

        // Store scaled + causally-masked scores
        #pragma unroll
        for (int i = 0; i < 4; ++i)
            #pragma unroll
            for (int j = 0; j < 4; ++j) {
                int r = tRow + 16 * i, c = tCol + 16 * j;
                float val = s[i][j] * scale;
                if (kv0 + c > q0 + r) val = -1e30f;
                Sc[r * SS + c] = val;
            }

        // Load V tile (independent buffer; visible after next barrier)
        #pragma unroll
        for (int it = 0; it < 8; ++it) {
            int li  = it * 256 + tid;
            int row = li >> 5;
            int c4  = (li & 31) << 2;
            const float* src = Vg + ((size_t)((b * S_ + kv0 + row) * HKV_ + kvh)) * D_ + c4;
            *reinterpret_cast<float4*>(&Vs[row * QS + c4]) =
                *reinterpret_cast<const float4*>(src);
        }
        __syncthreads();

        // Online softmax bookkeeping: one thread per row
        if (tid < 64) {
            const int r = tid;
            float mo = m_s[r];
            float mx = mo;
            #pragma unroll 8
            for (int c = 0; c < 64; ++c) mx = fmaxf(mx, Sc[r * SS + c]);
            float alpha = (mo == -INFINITY) ? 0.f : __expf(fmaxf(mo - mx, -80.f));
            float sum = 0.f;
            #pragma unroll 8
            for (int c = 0; c < 64; ++c) {
                float p = __expf(fmaxf(Sc[r * SS + c] - mx, -80.f));
                Sc[r * SS + c] = p;
                sum += p;
            }
            l_s[r] = l_s[r] * alpha + sum;
            m_s[r] = mx;
            a_s[r] = alpha;
        }
        __syncthreads();

        // Rescale accumulator and add P @ V
        {
            float alpha = a_s[r_pv];
            #pragma unroll
            for (int j = 0; j < 32; ++j) o[j] *= alpha;
            #pragma unroll 4
            for (int c = 0; c < 64; ++c) {
                float p = Sc[r_pv * SS + c];
                const float* vrow = &Vs[c * QS + dseg];
                #pragma unroll
                for (int j4 = 0; j4 < 8; ++j4) {
                    float4 v = *reinterpret_cast<const float4*>(vrow + j4 * 4);
                    o[j4 * 4 + 0] += p * v.x;
                    o[j4 * 4 + 1] += p * v.y;
                    o[j4 * 4 + 2] += p * v.z;
                    o[j4 * 4 + 3] += p * v.w;
                }
            }
        }
        __syncthreads();
    }

    // Finalize: divide by l, write out
    float inv_l = 1.f / l_s[r_pv];
    float* dst = Og + ((size_t)((b * S_ + q0 + r_pv) * H_ + h)) * D_ + dseg;
    #pragma unroll
    for (int j4 = 0; j4 < 8; ++j4) {
        float4 v = make_float4(o[j4*4+0] * inv_l, o[j4*4+1] * inv_l,
                               o[j4*4+2] * inv_l, o[j4*4+3] * inv_l);
        *reinterpret_cast<float4*>(dst + j4 * 4) = v;
    }
}

// ---------------------------------------------------------------------------
// Launcher
// ---------------------------------------------------------------------------
extern "C" void kernel_launch(void* const* d_in, const int* in_sizes, int n_in,
                              void* d_out, int out_size)
{
    const float* x  = (const float*)d_in[0];
    const float* wq = (const float*)d_in[1];
    const float* wk = (const float*)d_in[2];
    const float* wv = (const float*)d_in[3];
    const float* wo = (const float*)d_in[4];
    float* out = (float*)d_out;

    float *qp, *kp, *vp, *op;
    cudaGetSymbolAddress((void**)&qp, g_q);
    cudaGetSymbolAddress((void**)&kp, g_k);
    cudaGetSymbolAddress((void**)&vp, g_v);
    cudaGetSymbolAddress((void**)&op, g_o);

    // QKV projections (TF32 tensor cores)
    gemm_tf32<<<dim3(HID_ / GBN, M_ / GBM), 256>>>(x, wq, qp, M_, HID_, HID_);
    gemm_tf32<<<dim3((HKV_ * D_) / GBN, M_ / GBM), 256>>>(x, wk, kp, M_, HKV_ * D_, HID_);
    gemm_tf32<<<dim3((HKV_ * D_) / GBN, M_ / GBM), 256>>>(x, wv, vp, M_, HKV_ * D_, HID_);

    // RoPE on q and k
    {
        int totq = B_ * S_ * H_ * (D_ / 2);
        rope_k<<<(totq + 255) / 256, 256>>>(qp, H_, totq);
        int totk = B_ * S_ * HKV_ * (D_ / 2);
        rope_k<<<(totk + 255) / 256, 256>>>(kp, HKV_, totk);
    }

    // Flash attention
    {
        const int smem_bytes = (3 * 64 * 132 + 64 * 65 + 3 * 64) * (int)sizeof(float);
        cudaFuncSetAttribute(flash_k, cudaFuncAttributeMaxDynamicSharedMemorySize, smem_bytes);
        flash_k<<<dim3(S_ / 64, H_, B_), 256, smem_bytes>>>(qp, kp, vp, op);
    }

    // Output projection (TF32 tensor cores)
    gemm_tf32<<<dim3(HID_ / GBN, M_ / GBM), 256>>>(op, wo, out, M_, HID_, HID_);
}

// round 3
// speedup vs baseline: 2.2153x; 1.9159x over previous
#include <cuda_runtime.h>
#include <cuda_bf16.h>
#include <mma.h>
#include <math.h>
#include <float.h>

using namespace nvcuda;

// Problem constants
#define B_  2
#define S_  2048
#define HID_ 4096
#define H_  32
#define HKV_ 8
#define D_  128
#define M_  (B_ * S_)   // 4096 rows of x

// Scratch (device globals; allocation in kernel_launch is forbidden)
__device__ float g_q[(size_t)B_ * S_ * H_ * D_];
__device__ float g_k[(size_t)B_ * S_ * HKV_ * D_];
__device__ float g_v[(size_t)B_ * S_ * HKV_ * D_];
__device__ float g_o[(size_t)B_ * S_ * H_ * D_];

// ---------------------------------------------------------------------------
// TF32 tensor-core GEMM v2: C[M,N] = A[M,K] @ B[K,N], row-major fp32 in/out.
// 128x128 block tile, BK=32, 256 threads (8 warps: 4 row-strips x 2 col-strips,
// warp tile 32x64). Double-buffered smem; TF32 rounding done once at STS.
// Requires M%128==0, N%128==0, K%32==0.
// ---------------------------------------------------------------------------
constexpr int GBM = 128, GBN = 128, GBK = 32;
constexpr int GLDA = GBK + 8;    // 40
constexpr int GLDB = GBN + 8;    // 136
constexpr int ASZ  = GBM * GLDA; // 5120 floats / buffer
constexpr int BSZ  = GBK * GLDB; // 4352 floats / buffer
constexpr int GEMM_SMEM_BYTES = (int)((2 * (ASZ + BSZ)) * sizeof(float)); // 75776

__global__ __launch_bounds__(256, 2) void gemm_tf32(const float* __restrict__ A,
                                                    const float* __restrict__ Bm,
                                                    float* __restrict__ C,
                                                    int M, int N, int K)
{
    extern __shared__ float gsm[];
    float* Asb[2] = { gsm,            gsm + ASZ };
    float* Bsb[2] = { gsm + 2 * ASZ,  gsm + 2 * ASZ + BSZ };

    const int tid  = threadIdx.x;
    const int warp = tid >> 5;
    const int wr   = warp >> 1;       // 0..3 -> 32-row strip
    const int wc   = warp & 1;        // 0..1 -> 64-col strip

    const size_t bm0 = (size_t)blockIdx.y * GBM;
    const size_t bn0 = (size_t)blockIdx.x * GBN;

    // Per-thread tile-load mapping (16 floats = 4 float4 from A and from B)
    const int aRow = tid >> 1;                 // 0..127
    const int aCol = (tid & 1) << 4;           // 0 or 16
    const int bRow = tid >> 3;                 // 0..31
    const int bCol = (tid & 7) << 4;           // 0..112

    wmma::fragment<wmma::accumulator, 16, 16, 8, float> acc[2][4];
    #pragma unroll
    for (int m = 0; m < 2; ++m)
        #pragma unroll
        for (int n = 0; n < 4; ++n)
            wmma::fill_fragment(acc[m][n], 0.0f);

    float4 ra[4], rb[4];

    auto ldg_tile = [&](int k0) {
        #pragma unroll
        for (int j = 0; j < 4; ++j)
            ra[j] = *reinterpret_cast<const float4*>(
                A + (bm0 + aRow) * K + k0 + aCol + 4 * j);
        #pragma unroll
        for (int j = 0; j < 4; ++j)
            rb[j] = *reinterpret_cast<const float4*>(
                Bm + (size_t)(k0 + bRow) * N + bn0 + bCol + 4 * j);
    };
    auto sts_tile = [&](int buf) {
        float* As = Asb[buf];
        float* Bs = Bsb[buf];
        #pragma unroll
        for (int j = 0; j < 4; ++j) {
            float4 v = ra[j];
            v.x = wmma::__float_to_tf32(v.x);
            v.y = wmma::__float_to_tf32(v.y);
            v.z = wmma::__float_to_tf32(v.z);
            v.w = wmma::__float_to_tf32(v.w);
            *reinterpret_cast<float4*>(&As[aRow * GLDA + aCol + 4 * j]) = v;
        }
        #pragma unroll
        for (int j = 0; j < 4; ++j) {
            float4 v = rb[j];
            v.x = wmma::__float_to_tf32(v.x);
            v.y = wmma::__float_to_tf32(v.y);
            v.z = wmma::__float_to_tf32(v.z);
            v.w = wmma::__float_to_tf32(v.w);
            *reinterpret_cast<float4*>(&Bs[bRow * GLDB + bCol + 4 * j]) = v;
        }
    };

    // Prologue: stage k0 = 0
    ldg_tile(0);
    sts_tile(0);
    __syncthreads();

    int buf = 0;
    for (int k0 = 0; k0 < K; k0 += GBK) {
        const bool has_next = (k0 + GBK) < K;
        if (has_next) ldg_tile(k0 + GBK);   // overlap global latency with MMA

        const float* As = Asb[buf];
        const float* Bs = Bsb[buf];
        #pragma unroll
        for (int kk = 0; kk < GBK; kk += 8) {
            wmma::fragment<wmma::matrix_a, 16, 16, 8, wmma::precision::tf32,
                           wmma::row_major> af[2];
            wmma::fragment<wmma::matrix_b, 16, 16, 8, wmma::precision::tf32,
                           wmma::row_major> bf[4];
            #pragma unroll
            for (int m = 0; m < 2; ++m)
                wmma::load_matrix_sync(af[m], &As[(wr * 32 + m * 16) * GLDA + kk], GLDA);
            #pragma unroll
            for (int n = 0; n < 4; ++n)
                wmma::load_matrix_sync(bf[n], &Bs[kk * GLDB + wc * 64 + n * 16], GLDB);
            #pragma unroll
            for (int m = 0; m < 2; ++m)
                #pragma unroll
                for (int n = 0; n < 4; ++n)
                    wmma::mma_sync(acc[m][n], af[m], bf[n], acc[m][n]);
        }

        if (has_next) {
            __syncthreads();        // everyone done reading buf^1 (iter-2 data)
            sts_tile(buf ^ 1);
            __syncthreads();
            buf ^= 1;
        }
    }

    #pragma unroll
    for (int m = 0; m < 2; ++m)
        #pragma unroll
        for (int n = 0; n < 4; ++n)
            wmma::store_matrix_sync(
                C + (bm0 + wr * 32 + m * 16) * N + bn0 + wc * 64 + n * 16,
                acc[m][n], N, wmma::mem_row_major);
}

// ---------------------------------------------------------------------------
// RoPE in-place on [B, S, nh, D] fp32.
// ---------------------------------------------------------------------------
__global__ void rope_k(float* __restrict__ x, int nh, int total)
{
    int idx = blockIdx.x * blockDim.x + threadIdx.x;
    if (idx >= total) return;
    const int half = D_ / 2;  // 64
    int i = idx & (half - 1);
    int rest = idx >> 6;
    int h = rest % nh;
    rest /= nh;
    int s = rest % S_;
    int b = rest / S_;

    float inv = __expf(-logf(10000.0f) * (float)i / (float)half);
    float ang = (float)s * inv;
    float sn, cs;
    sincosf(ang, &sn, &cs);

    float* base = x + ((size_t)((b * S_ + s) * nh + h)) * D_;
    float x1 = base[i];
    float x2 = base[i + half];
    base[i]        = x1 * cs - x2 * sn;
    base[i + half] = x2 * cs + x1 * sn;
}

// ---------------------------------------------------------------------------
// Flash attention v2 (fp32, causal, GQA rep=4).
// Grid (S/64, H, B), 256 threads. Parallel softmax (4 thr/row, shfl reduce),
// PV remapped to 4 rows x 8 cols per thread (LDS-lean, FFMA-bound).
// ---------------------------------------------------------------------------
__global__ __launch_bounds__(256) void flash_k(const float* __restrict__ Qg,
                                               const float* __restrict__ Kg,
                                               const float* __restrict__ Vg,
                                               float* __restrict__ Og)
{
    constexpr int QS = 132;
    constexpr int SS = 65;
    extern __shared__ float sm[];
    float* Qs  = sm;                    // 64*132
    float* Ks  = Qs + 64 * QS;          // 64*132
    float* Vs  = Ks + 64 * QS;          // 64*132
    float* Sc  = Vs + 64 * QS;          // 64*65
    float* m_s = Sc + 64 * SS;          // 64
    float* l_s = m_s + 64;              // 64
    float* a_s = l_s + 64;              // 64

    const int tid   = threadIdx.x;
    const int qtile = blockIdx.x;
    const int h     = blockIdx.y;
    const int b     = blockIdx.z;
    const int q0    = qtile * 64;
    const int kvh   = h >> 2;

    // Load Q tile
    #pragma unroll
    for (int it = 0; it < 8; ++it) {
        int li  = it * 256 + tid;
        int row = li >> 5;
        int c4  = (li & 31) << 2;
        const float* src = Qg + ((size_t)((b * S_ + q0 + row) * H_ + h)) * D_ + c4;
        *reinterpret_cast<float4*>(&Qs[row * QS + c4]) =
            *reinterpret_cast<const float4*>(src);
    }
    if (tid < 64) { m_s[tid] = -INFINITY; l_s[tid] = 0.f; }

    // Score mapping: rows tRow+16i, cols tCol+16j (4x4 per thread)
    const int tRow = tid >> 4;          // 0..15
    const int tCol = tid & 15;          // 0..15
    // Softmax mapping: row sr = tid>>2, quarter sq = tid&3 (16 cols each)
    const int sr = tid >> 2;
    const int sq = tid & 3;
    // PV mapping: rows tRow+16i (same as score), cols j0 and j0+64 (4 each)
    const int j0 = (tid & 15) << 2;     // 0..60
    const float scale = 0.08838834764831845f;  // 1/sqrt(128)

    float o[4][8];
    #pragma unroll
    for (int i = 0; i < 4; ++i)
        #pragma unroll
        for (int j = 0; j < 8; ++j) o[i][j] = 0.f;

    __syncthreads();

    for (int t = 0; t <= qtile; ++t) {
        const int kv0 = t * 64;

        // Load K tile
        #pragma unroll
        for (int it = 0; it < 8; ++it) {
            int li  = it * 256 + tid;
            int row = li >> 5;
            int c4  = (li & 31) << 2;
            const float* src = Kg + ((size_t)((b * S_ + kv0 + row) * HKV_ + kvh)) * D_ + c4;
            *reinterpret_cast<float4*>(&Ks[row * QS + c4]) =
                *reinterpret_cast<const float4*>(src);
        }
        __syncthreads();

        // Scores
        float s[4][4];
        #pragma unroll
        for (int i = 0; i < 4; ++i)
            #pragma unroll
            for (int j = 0; j < 4; ++j) s[i][j] = 0.f;

        for (int d = 0; d < D_; d += 4) {
            float4 q4[4], k4[4];
            #pragma unroll
            for (int i = 0; i < 4; ++i)
                q4[i] = *reinterpret_cast<float4*>(&Qs[(tRow + 16 * i) * QS + d]);
            #pragma unroll
            for (int j = 0; j < 4; ++j)
                k4[j] = *reinterpret_cast<float4*>(&Ks[(tCol + 16 * j) * QS + d]);
            #pragma unroll
            for (int i = 0; i < 4; ++i)
                #pragma unroll
                for (int j = 0; j < 4; ++j) {
                    s[i][j] += q4[i].x * k4[j].x;
                    s[i][j] += q4[i].y * k4[j].y;
                    s[i][j] += q4[i].z * k4[j].z;
                    s[i][j] += q4[i].w * k4[j].w;
                }
        }

        // Scaled + causally-masked scores to smem
        #pragma unroll
        for (int i = 0; i < 4; ++i)
            #pragma unroll
            for (int j = 0; j < 4; ++j) {
                int r = tRow + 16 * i, c = tCol + 16 * j;
                float val = s[i][j] * scale;
                if (kv0 + c > q0 + r) val = -1e30f;
                Sc[r * SS + c] = val;
            }

        // Load V tile
        #pragma unroll
        for (int it = 0; it < 8; ++it) {
            int li  = it * 256 + tid;
            int row = li >> 5;
            int c4  = (li & 31) << 2;
            const float* src = Vg + ((size_t)((b * S_ + kv0 + row) * HKV_ + kvh)) * D_ + c4;
            *reinterpret_cast<float4*>(&Vs[row * QS + c4]) =
                *reinterpret_cast<const float4*>(src);
        }
        __syncthreads();

        // Parallel online softmax: 4 threads per row, 16 cols each
        {
            float mo = m_s[sr];
            float mx = -INFINITY;
            #pragma unroll
            for (int c = 0; c < 16; ++c)
                mx = fmaxf(mx, Sc[sr * SS + sq * 16 + c]);
            mx = fmaxf(mx, __shfl_xor_sync(0xFFFFFFFFu, mx, 1));
            mx = fmaxf(mx, __shfl_xor_sync(0xFFFFFFFFu, mx, 2));
            mx = fmaxf(mx, mo);
            float sum = 0.f;
            #pragma unroll
            for (int c = 0; c < 16; ++c) {
                float p = __expf(fmaxf(Sc[sr * SS + sq * 16 + c] - mx, -80.f));
                Sc[sr * SS + sq * 16 + c] = p;
                sum += p;
            }
            sum += __shfl_xor_sync(0xFFFFFFFFu, sum, 1);
            sum += __shfl_xor_sync(0xFFFFFFFFu, sum, 2);
            if (sq == 0) {
                float alpha = (mo == -INFINITY) ? 0.f : __expf(fmaxf(mo - mx, -80.f));
                l_s[sr] = l_s[sr] * alpha + sum;
                m_s[sr] = mx;
                a_s[sr] = alpha;
            }
        }
        __syncthreads();

        // Rescale accumulator and add P @ V (4 rows x (4+4) cols per thread)
        {
            float alpha[4];
            #pragma unroll
            for (int i = 0; i < 4; ++i) alpha[i] = a_s[tRow + 16 * i];
            #pragma unroll
            for (int i = 0; i < 4; ++i)
                #pragma unroll
                for (int j = 0; j < 8; ++j) o[i][j] *= alpha[i];

            #pragma unroll 4
            for (int c = 0; c < 64; ++c) {
                float p0 = Sc[(tRow +  0) * SS + c];
                float p1 = Sc[(tRow + 16) * SS + c];
                float p2 = Sc[(tRow + 32) * SS + c];
                float p3 = Sc[(tRow + 48) * SS + c];
                float4 v0 = *reinterpret_cast<const float4*>(&Vs[c * QS + j0]);
                float4 v1 = *reinterpret_cast<const float4*>(&Vs[c * QS + j0 + 64]);
                o[0][0] += p0 * v0.x; o[0][1] += p0 * v0.y;
                o[0][2] += p0 * v0.z; o[0][3] += p0 * v0.w;
                o[0][4] += p0 * v1.x; o[0][5] += p0 * v1.y;
                o[0][6] += p0 * v1.z; o[0][7] += p0 * v1.w;
                o[1][0] += p1 * v0.x; o[1][1] += p1 * v0.y;
                o[1][2] += p1 * v0.z; o[1][3] += p1 * v0.w;
                o[1][4] += p1 * v1.x; o[1][5] += p1 * v1.y;
                o[1][6] += p1 * v1.z; o[1][7] += p1 * v1.w;
                o[2][0] += p2 * v0.x; o[2][1] += p2 * v0.y;
                o[2][2] += p2 * v0.z; o[2][3] += p2 * v0.w;
                o[2][4] += p2 * v1.x; o[2][5] += p2 * v1.y;
                o[2][6] += p2 * v1.z; o[2][7] += p2 * v1.w;
                o[3][0] += p3 * v0.x; o[3][1] += p3 * v0.y;
                o[3][2] += p3 * v0.z; o[3][3] += p3 * v0.w;
                o[3][4] += p3 * v1.x; o[3][5] += p3 * v1.y;
                o[3][6] += p3 * v1.z; o[3][7] += p3 * v1.w;
            }
        }
        __syncthreads();
    }

    // Finalize: divide by l, write out (4 rows x 2 float4 per thread)
    #pragma unroll
    for (int i = 0; i < 4; ++i) {
        int r = tRow + 16 * i;
        float inv_l = 1.f / l_s[r];
        float* dst = Og + ((size_t)((b * S_ + q0 + r) * H_ + h)) * D_;
        float4 v0 = make_float4(o[i][0] * inv_l, o[i][1] * inv_l,
                                o[i][2] * inv_l, o[i][3] * inv_l);
        float4 v1 = make_float4(o[i][4] * inv_l, o[i][5] * inv_l,
                                o[i][6] * inv_l, o[i][7] * inv_l);
        *reinterpret_cast<float4*>(dst + j0)      = v0;
        *reinterpret_cast<float4*>(dst + j0 + 64) = v1;
    }
}

// ---------------------------------------------------------------------------
// Launcher
// ---------------------------------------------------------------------------
extern "C" void kernel_launch(void* const* d_in, const int* in_sizes, int n_in,
                              void* d_out, int out_size)
{
    const float* x  = (const float*)d_in[0];
    const float* wq = (const float*)d_in[1];
    const float* wk = (const float*)d_in[2];
    const float* wv = (const float*)d_in[3];
    const float* wo = (const float*)d_in[4];
    float* out = (float*)d_out;

    float *qp, *kp, *vp, *op;
    cudaGetSymbolAddress((void**)&qp, g_q);
    cudaGetSymbolAddress((void**)&kp, g_k);
    cudaGetSymbolAddress((void**)&vp, g_v);
    cudaGetSymbolAddress((void**)&op, g_o);

    cudaFuncSetAttribute(gemm_tf32, cudaFuncAttributeMaxDynamicSharedMemorySize,
                         GEMM_SMEM_BYTES);

    // QKV projections (TF32 tensor cores, double-buffered)
    gemm_tf32<<<dim3(HID_ / GBN, M_ / GBM), 256, GEMM_SMEM_BYTES>>>(x, wq, qp, M_, HID_, HID_);
    gemm_tf32<<<dim3((HKV_ * D_) / GBN, M_ / GBM), 256, GEMM_SMEM_BYTES>>>(x, wk, kp, M_, HKV_ * D_, HID_);
    gemm_tf32<<<dim3((HKV_ * D_) / GBN, M_ / GBM), 256, GEMM_SMEM_BYTES>>>(x, wv, vp, M_, HKV_ * D_, HID_);

    // RoPE on q and k
    {
        int totq = B_ * S_ * H_ * (D_ / 2);
        rope_k<<<(totq + 255) / 256, 256>>>(qp, H_, totq);
        int totk = B_ * S_ * HKV_ * (D_ / 2);
        rope_k<<<(totk + 255) / 256, 256>>>(kp, HKV_, totk);
    }

    // Flash attention
    {
        const int smem_bytes = (3 * 64 * 132 + 64 * 65 + 3 * 64) * (int)sizeof(float);
        cudaFuncSetAttribute(flash_k, cudaFuncAttributeMaxDynamicSharedMemorySize, smem_bytes);
        flash_k<<<dim3(S_ / 64, H_, B_), 256, smem_bytes>>>(qp, kp, vp, op);
    }

    // Output projection
    gemm_tf32<<<dim3(HID_ / GBN, M_ / GBM), 256, GEMM_SMEM_BYTES>>>(op, wo, out, M_, HID_, HID_);
}

// round 4
// speedup vs baseline: 2.5013x; 1.1291x over previous
#include <cuda_runtime.h>
#include <cuda_bf16.h>
#include <mma.h>
#include <math.h>
#include <float.h>

using namespace nvcuda;

// Problem constants
#define B_  2
#define S_  2048
#define HID_ 4096
#define H_  32
#define HKV_ 8
#define D_  128
#define M_  (B_ * S_)   // 4096 rows of x

// Scratch (device globals; allocation in kernel_launch is forbidden)
__device__ float g_q[(size_t)B_ * S_ * H_ * D_];
__device__ float g_k[(size_t)B_ * S_ * HKV_ * D_];
__device__ float g_v[(size_t)B_ * S_ * HKV_ * D_];
__device__ float g_o[(size_t)B_ * S_ * H_ * D_];

// ---------------------------------------------------------------------------
// TF32 tensor-core GEMM: C[M,N] = A[M,K] @ B[K,N], row-major fp32 in/out.
// 128x128 block tile, BK=32, 256 threads, warp tile 32x64.
// Double-buffered smem, ONE barrier per K-iteration.
// ---------------------------------------------------------------------------
constexpr int GBM = 128, GBN = 128, GBK = 32;
constexpr int GLDA = GBK + 8;    // 40
constexpr int GLDB = GBN + 8;    // 136
constexpr int ASZ  = GBM * GLDA;
constexpr int BSZ  = GBK * GLDB;
constexpr int GEMM_SMEM_BYTES = (int)((2 * (ASZ + BSZ)) * sizeof(float)); // 75776

__global__ __launch_bounds__(256, 2) void gemm_tf32(const float* __restrict__ A,
                                                    const float* __restrict__ Bm,
                                                    float* __restrict__ C,
                                                    int M, int N, int K)
{
    extern __shared__ float gsm[];
    float* Asb[2] = { gsm,            gsm + ASZ };
    float* Bsb[2] = { gsm + 2 * ASZ,  gsm + 2 * ASZ + BSZ };

    const int tid  = threadIdx.x;
    const int warp = tid >> 5;
    const int wr   = warp >> 1;
    const int wc   = warp & 1;

    const size_t bm0 = (size_t)blockIdx.y * GBM;
    const size_t bn0 = (size_t)blockIdx.x * GBN;

    const int aRow = tid >> 1;
    const int aCol = (tid & 1) << 4;
    const int bRow = tid >> 3;
    const int bCol = (tid & 7) << 4;

    wmma::fragment<wmma::accumulator, 16, 16, 8, float> acc[2][4];
    #pragma unroll
    for (int m = 0; m < 2; ++m)
        #pragma unroll
        for (int n = 0; n < 4; ++n)
            wmma::fill_fragment(acc[m][n], 0.0f);

    float4 ra[4], rb[4];

    auto ldg_tile = [&](int k0) {
        #pragma unroll
        for (int j = 0; j < 4; ++j)
            ra[j] = *reinterpret_cast<const float4*>(
                A + (bm0 + aRow) * K + k0 + aCol + 4 * j);
        #pragma unroll
        for (int j = 0; j < 4; ++j)
            rb[j] = *reinterpret_cast<const float4*>(
                Bm + (size_t)(k0 + bRow) * N + bn0 + bCol + 4 * j);
    };
    auto sts_tile = [&](int buf) {
        float* As = Asb[buf];
        float* Bs = Bsb[buf];
        #pragma unroll
        for (int j = 0; j < 4; ++j) {
            float4 v = ra[j];
            v.x = wmma::__float_to_tf32(v.x);
            v.y = wmma::__float_to_tf32(v.y);
            v.z = wmma::__float_to_tf32(v.z);
            v.w = wmma::__float_to_tf32(v.w);
            *reinterpret_cast<float4*>(&As[aRow * GLDA + aCol + 4 * j]) = v;
        }
        #pragma unroll
        for (int j = 0; j < 4; ++j) {
            float4 v = rb[j];
            v.x = wmma::__float_to_tf32(v.x);
            v.y = wmma::__float_to_tf32(v.y);
            v.z = wmma::__float_to_tf32(v.z);
            v.w = wmma::__float_to_tf32(v.w);
            *reinterpret_cast<float4*>(&Bs[bRow * GLDB + bCol + 4 * j]) = v;
        }
    };

    ldg_tile(0);
    sts_tile(0);
    __syncthreads();

    int buf = 0;
    for (int k0 = 0; k0 < K; k0 += GBK) {
        const bool has_next = (k0 + GBK) < K;
        if (has_next) ldg_tile(k0 + GBK);

        const float* As = Asb[buf];
        const float* Bs = Bsb[buf];
        #pragma unroll
        for (int kk = 0; kk < GBK; kk += 8) {
            wmma::fragment<wmma::matrix_a, 16, 16, 8, wmma::precision::tf32,
                           wmma::row_major> af[2];
            wmma::fragment<wmma::matrix_b, 16, 16, 8, wmma::precision::tf32,
                           wmma::row_major> bf[4];
            #pragma unroll
            for (int m = 0; m < 2; ++m)
                wmma::load_matrix_sync(af[m], &As[(wr * 32 + m * 16) * GLDA + kk], GLDA);
            #pragma unroll
            for (int n = 0; n < 4; ++n)
                wmma::load_matrix_sync(bf[n], &Bs[kk * GLDB + wc * 64 + n * 16], GLDB);
            #pragma unroll
            for (int m = 0; m < 2; ++m)
                #pragma unroll
                for (int n = 0; n < 4; ++n)
                    wmma::mma_sync(acc[m][n], af[m], bf[n], acc[m][n]);
        }

        if (has_next) {
            sts_tile(buf ^ 1);   // disjoint from buf being read; prev barrier
            __syncthreads();     // guards reuse of buf^1
            buf ^= 1;
        }
    }

    #pragma unroll
    for (int m = 0; m < 2; ++m)
        #pragma unroll
        for (int n = 0; n < 4; ++n)
            wmma::store_matrix_sync(
                C + (bm0 + wr * 32 + m * 16) * N + bn0 + wc * 64 + n * 16,
                acc[m][n], N, wmma::mem_row_major);
}

// ---------------------------------------------------------------------------
// RoPE in-place on [B, S, nh, D] fp32.
// ---------------------------------------------------------------------------
__global__ void rope_k(float* __restrict__ x, int nh, int total)
{
    int idx = blockIdx.x * blockDim.x + threadIdx.x;
    if (idx >= total) return;
    const int half = D_ / 2;
    int i = idx & (half - 1);
    int rest = idx >> 6;
    int h = rest % nh;
    rest /= nh;
    int s = rest % S_;
    int b = rest / S_;

    float inv = __expf(-logf(10000.0f) * (float)i / (float)half);
    float ang = (float)s * inv;
    float sn, cs;
    sincosf(ang, &sn, &cs);

    float* base = x + ((size_t)((b * S_ + s) * nh + h)) * D_;
    float x1 = base[i];
    float x2 = base[i + half];
    base[i]        = x1 * cs - x2 * sn;
    base[i + half] = x2 * cs + x1 * sn;
}

// ---------------------------------------------------------------------------
// Flash attention v3: tensor-core QK^T and PV (TF32 WMMA), SIMT online softmax.
// Grid (S/64, H, B), 256 threads (8 warps: 4 row strips x 2 col strips).
// PV partial goes through smem each tile; o rescale+accumulate is SIMT.
// ---------------------------------------------------------------------------
constexpr int FQS = 132;  // Q/K/V/PV row stride (floats)
constexpr int FSS = 68;   // score row stride
constexpr int FLASH_SMEM_FLOATS = 4 * 64 * FQS + 64 * FSS + 3 * 64;
constexpr int FLASH_SMEM_BYTES  = (int)(FLASH_SMEM_FLOATS * sizeof(float)); // ~153KB

__global__ __launch_bounds__(256) void flash_k(const float* __restrict__ Qg,
                                               const float* __restrict__ Kg,
                                               const float* __restrict__ Vg,
                                               float* __restrict__ Og)
{
    extern __shared__ float sm[];
    float* Qs  = sm;                    // 64*FQS (tf32-rounded)
    float* Ks  = Qs + 64 * FQS;         // 64*FQS (tf32-rounded)
    float* Vs  = Ks + 64 * FQS;         // 64*FQS (tf32-rounded)
    float* PVp = Vs + 64 * FQS;         // 64*FQS fp32 partial
    float* Sc  = PVp + 64 * FQS;        // 64*FSS scores/probs
    float* m_s = Sc + 64 * FSS;
    float* l_s = m_s + 64;
    float* a_s = l_s + 64;

    const int tid   = threadIdx.x;
    const int warp  = tid >> 5;
    const int wr    = warp >> 1;        // 0..3: 16-row strip
    const int wc    = warp & 1;         // 0..1
    const int qtile = gridDim.x - 1 - blockIdx.x;   // heavy tiles first
    const int h     = blockIdx.y;
    const int b     = blockIdx.z;
    const int q0    = qtile * 64;
    const int kvh   = h >> 2;

    // SIMT o-update mapping
    const int tRow = tid >> 4;          // 0..15
    const int j0   = (tid & 15) << 2;   // 0..60
    // softmax mapping: 4 threads per row
    const int sr = tid >> 2;
    const int sq = tid & 3;
    const float scale = 0.08838834764831845f;  // 1/sqrt(128)

    // Load Q tile (round to tf32 at STS)
    #pragma unroll
    for (int it = 0; it < 8; ++it) {
        int li  = it * 256 + tid;
        int row = li >> 5;
        int c4  = (li & 31) << 2;
        float4 v = *reinterpret_cast<const float4*>(
            Qg + ((size_t)((b * S_ + q0 + row) * H_ + h)) * D_ + c4);
        v.x = wmma::__float_to_tf32(v.x);
        v.y = wmma::__float_to_tf32(v.y);
        v.z = wmma::__float_to_tf32(v.z);
        v.w = wmma::__float_to_tf32(v.w);
        *reinterpret_cast<float4*>(&Qs[row * FQS + c4]) = v;
    }
    if (tid < 64) { m_s[tid] = -INFINITY; l_s[tid] = 0.f; }

    float o[4][8];
    #pragma unroll
    for (int i = 0; i < 4; ++i)
        #pragma unroll
        for (int j = 0; j < 8; ++j) o[i][j] = 0.f;

    __syncthreads();

    for (int t = 0; t <= qtile; ++t) {
        const int kv0 = t * 64;

        // ---- 1. Load K and V tiles (tf32-rounded) ----
        #pragma unroll
        for (int it = 0; it < 8; ++it) {
            int li  = it * 256 + tid;
            int row = li >> 5;
            int c4  = (li & 31) << 2;
            size_t goff = ((size_t)((b * S_ + kv0 + row) * HKV_ + kvh)) * D_ + c4;
            float4 kv4 = *reinterpret_cast<const float4*>(Kg + goff);
            kv4.x = wmma::__float_to_tf32(kv4.x);
            kv4.y = wmma::__float_to_tf32(kv4.y);
            kv4.z = wmma::__float_to_tf32(kv4.z);
            kv4.w = wmma::__float_to_tf32(kv4.w);
            *reinterpret_cast<float4*>(&Ks[row * FQS + c4]) = kv4;
            float4 vv4 = *reinterpret_cast<const float4*>(Vg + goff);
            vv4.x = wmma::__float_to_tf32(vv4.x);
            vv4.y = wmma::__float_to_tf32(vv4.y);
            vv4.z = wmma::__float_to_tf32(vv4.z);
            vv4.w = wmma::__float_to_tf32(vv4.w);
            *reinterpret_cast<float4*>(&Vs[row * FQS + c4]) = vv4;
        }
        __syncthreads();

        // ---- 2. Scores: warp computes 16x32 of the 64x64 tile ----
        {
            wmma::fragment<wmma::accumulator, 16, 16, 8, float> accs[2];
            wmma::fill_fragment(accs[0], 0.0f);
            wmma::fill_fragment(accs[1], 0.0f);
            #pragma unroll
            for (int kk = 0; kk < D_; kk += 8) {
                wmma::fragment<wmma::matrix_a, 16, 16, 8, wmma::precision::tf32,
                               wmma::row_major> af;
                wmma::fragment<wmma::matrix_b, 16, 16, 8, wmma::precision::tf32,
                               wmma::col_major> bf[2];
                wmma::load_matrix_sync(af, &Qs[(wr * 16) * FQS + kk], FQS);
                #pragma unroll
                for (int n = 0; n < 2; ++n)
                    wmma::load_matrix_sync(bf[n],
                        &Ks[(wc * 32 + n * 16) * FQS + kk], FQS);
                wmma::mma_sync(accs[0], af, bf[0], accs[0]);
                wmma::mma_sync(accs[1], af, bf[1], accs[1]);
            }
            #pragma unroll
            for (int n = 0; n < 2; ++n) {
                #pragma unroll
                for (int e = 0; e < accs[n].num_elements; ++e)
                    accs[n].x[e] *= scale;
                wmma::store_matrix_sync(
                    &Sc[(wr * 16) * FSS + wc * 32 + n * 16], accs[n],
                    FSS, wmma::mem_row_major);
            }
        }
        __syncthreads();

        // ---- 3. Online softmax (4 threads/row, mask applied here) ----
        {
            float mo = m_s[sr];
            float vals[16];
            float mx = -INFINITY;
            #pragma unroll
            for (int c = 0; c < 16; ++c) {
                int col = sq * 16 + c;
                float v = Sc[sr * FSS + col];
                if (kv0 + col > q0 + sr) v = -1e30f;
                vals[c] = v;
                mx = fmaxf(mx, v);
            }
            mx = fmaxf(mx, __shfl_xor_sync(0xFFFFFFFFu, mx, 1));
            mx = fmaxf(mx, __shfl_xor_sync(0xFFFFFFFFu, mx, 2));
            mx = fmaxf(mx, mo);
            float sum = 0.f;
            #pragma unroll
            for (int c = 0; c < 16; ++c) {
                float p = __expf(fmaxf(vals[c] - mx, -80.f));
                Sc[sr * FSS + sq * 16 + c] = p;
                sum += p;
            }
            sum += __shfl_xor_sync(0xFFFFFFFFu, sum, 1);
            sum += __shfl_xor_sync(0xFFFFFFFFu, sum, 2);
            if (sq == 0) {
                float alpha = (mo == -INFINITY) ? 0.f : __expf(fmaxf(mo - mx, -80.f));
                l_s[sr] = l_s[sr] * alpha + sum;
                m_s[sr] = mx;
                a_s[sr] = alpha;
            }
        }
        __syncthreads();

        // ---- 4. PV: warp computes 16x64 of the 64x128 partial ----
        {
            wmma::fragment<wmma::accumulator, 16, 16, 8, float> accp[4];
            #pragma unroll
            for (int n = 0; n < 4; ++n) wmma::fill_fragment(accp[n], 0.0f);
            #pragma unroll
            for (int kk = 0; kk < 64; kk += 8) {
                wmma::fragment<wmma::matrix_a, 16, 16, 8, wmma::precision::tf32,
                               wmma::row_major> af;
                wmma::fragment<wmma::matrix_b, 16, 16, 8, wmma::precision::tf32,
                               wmma::row_major> bf[4];
                wmma::load_matrix_sync(af, &Sc[(wr * 16) * FSS + kk], FSS);
                #pragma unroll
                for (int e = 0; e < af.num_elements; ++e)
                    af.x[e] = wmma::__float_to_tf32(af.x[e]);
                #pragma unroll
                for (int n = 0; n < 4; ++n)
                    wmma::load_matrix_sync(bf[n],
                        &Vs[kk * FQS + wc * 64 + n * 16], FQS);
                #pragma unroll
                for (int n = 0; n < 4; ++n)
                    wmma::mma_sync(accp[n], af, bf[n], accp[n]);
            }
            #pragma unroll
            for (int n = 0; n < 4; ++n)
                wmma::store_matrix_sync(
                    &PVp[(wr * 16) * FQS + wc * 64 + n * 16], accp[n],
                    FQS, wmma::mem_row_major);
        }
        __syncthreads();

        // ---- 5. SIMT: o = o*alpha + PV partial ----
        {
            float alpha[4];
            #pragma unroll
            for (int i = 0; i < 4; ++i) alpha[i] = a_s[tRow + 16 * i];
            #pragma unroll
            for (int i = 0; i < 4; ++i) {
                int r = tRow + 16 * i;
                float4 p0 = *reinterpret_cast<const float4*>(&PVp[r * FQS + j0]);
                float4 p1 = *reinterpret_cast<const float4*>(&PVp[r * FQS + j0 + 64]);
                o[i][0] = o[i][0] * alpha[i] + p0.x;
                o[i][1] = o[i][1] * alpha[i] + p0.y;
                o[i][2] = o[i][2] * alpha[i] + p0.z;
                o[i][3] = o[i][3] * alpha[i] + p0.w;
                o[i][4] = o[i][4] * alpha[i] + p1.x;
                o[i][5] = o[i][5] * alpha[i] + p1.y;
                o[i][6] = o[i][6] * alpha[i] + p1.z;
                o[i][7] = o[i][7] * alpha[i] + p1.w;
            }
        }
        __syncthreads();
    }

    // Finalize
    #pragma unroll
    for (int i = 0; i < 4; ++i) {
        int r = tRow + 16 * i;
        float inv_l = 1.f / l_s[r];
        float* dst = Og + ((size_t)((b * S_ + q0 + r) * H_ + h)) * D_;
        float4 v0 = make_float4(o[i][0] * inv_l, o[i][1] * inv_l,
                                o[i][2] * inv_l, o[i][3] * inv_l);
        float4 v1 = make_float4(o[i][4] * inv_l, o[i][5] * inv_l,
                                o[i][6] * inv_l, o[i][7] * inv_l);
        *reinterpret_cast<float4*>(dst + j0)      = v0;
        *reinterpret_cast<float4*>(dst + j0 + 64) = v1;
    }
}

// ---------------------------------------------------------------------------
// Launcher
// ---------------------------------------------------------------------------
extern "C" void kernel_launch(void* const* d_in, const int* in_sizes, int n_in,
                              void* d_out, int out_size)
{
    const float* x  = (const float*)d_in[0];
    const float* wq = (const float*)d_in[1];
    const float* wk = (const float*)d_in[2];
    const float* wv = (const float*)d_in[3];
    const float* wo = (const float*)d_in[4];
    float* out = (float*)d_out;

    float *qp, *kp, *vp, *op;
    cudaGetSymbolAddress((void**)&qp, g_q);
    cudaGetSymbolAddress((void**)&kp, g_k);
    cudaGetSymbolAddress((void**)&vp, g_v);
    cudaGetSymbolAddress((void**)&op, g_o);

    cudaFuncSetAttribute(gemm_tf32, cudaFuncAttributeMaxDynamicSharedMemorySize,
                         GEMM_SMEM_BYTES);
    cudaFuncSetAttribute(flash_k, cudaFuncAttributeMaxDynamicSharedMemorySize,
                         FLASH_SMEM_BYTES);

    // QKV projections
    gemm_tf32<<<dim3(HID_ / GBN, M_ / GBM), 256, GEMM_SMEM_BYTES>>>(x, wq, qp, M_, HID_, HID_);
    gemm_tf32<<<dim3((HKV_ * D_) / GBN, M_ / GBM), 256, GEMM_SMEM_BYTES>>>(x, wk, kp, M_, HKV_ * D_, HID_);
    gemm_tf32<<<dim3((HKV_ * D_) / GBN, M_ / GBM), 256, GEMM_SMEM_BYTES>>>(x, wv, vp, M_, HKV_ * D_, HID_);

    // RoPE
    {
        int totq = B_ * S_ * H_ * (D_ / 2);
        rope_k<<<(totq + 255) / 256, 256>>>(qp, H_, totq);
        int totk = B_ * S_ * HKV_ * (D_ / 2);
        rope_k<<<(totk + 255) / 256, 256>>>(kp, HKV_, totk);
    }

    // Flash attention (tensor-core)
    flash_k<<<dim3(S_ / 64, H_, B_), 256, FLASH_SMEM_BYTES>>>(qp, kp, vp, op);

    // Output projection
    gemm_tf32<<<dim3(HID_ / GBN, M_ / GBM), 256, GEMM_SMEM_BYTES>>>(op, wo, out, M_, HID_, HID_);
}

// round 6
// speedup vs baseline: 2.6888x; 1.0749x over previous
#include <cuda_runtime.h>
#include <cuda_bf16.h>
#include <mma.h>
#include <math.h>
#include <float.h>
#include <stdint.h>

using namespace nvcuda;

// Problem constants
#define B_  2
#define S_  2048
#define HID_ 4096
#define H_  32
#define HKV_ 8
#define D_  128
#define M_  (B_ * S_)   // 4096 rows of x

// Scratch (device globals; allocation in kernel_launch is forbidden)
__device__ float g_q[(size_t)B_ * S_ * H_ * D_];
__device__ float g_k[(size_t)B_ * S_ * HKV_ * D_];
__device__ float g_v[(size_t)B_ * S_ * HKV_ * D_];
__device__ float g_o[(size_t)B_ * S_ * H_ * D_];
// TF32-pre-rounded copies (so GEMMs need no in-kernel conversion)
__device__ float g_xr[(size_t)M_ * HID_];
__device__ float g_wqr[(size_t)HID_ * HID_];
__device__ float g_wkr[(size_t)HID_ * (HKV_ * D_)];
__device__ float g_wvr[(size_t)HID_ * (HKV_ * D_)];
__device__ float g_wor[(size_t)HID_ * HID_];

// ---------------------------------------------------------------------------
// cp.async helpers (sm_80+, valid on compute_103 non-'a')
// ---------------------------------------------------------------------------
__device__ __forceinline__ uint32_t smem_u32(const void* p) {
    uint32_t a;
    asm("{ .reg .u64 t; cvta.to.shared.u64 t, %1; cvt.u32.u64 %0, t; }"
        : "=r"(a) : "l"(p));
    return a;
}
#define CP_ASYNC16(dst_u32, src_ptr) \
    asm volatile("cp.async.cg.shared.global [%0], [%1], 16;" \
                 :: "r"(dst_u32), "l"(src_ptr) : "memory")
#define CP_COMMIT() asm volatile("cp.async.commit_group;" ::: "memory")
#define CP_WAIT1()  asm volatile("cp.async.wait_group 1;" ::: "memory")
#define CP_WAIT0()  asm volatile("cp.async.wait_group 0;" ::: "memory")

// ---------------------------------------------------------------------------
// Elementwise TF32 rounding: out[i] = round_tf32(in[i]) (n multiple of 4)
// ---------------------------------------------------------------------------
__global__ void round_tf32_k(const float* __restrict__ in,
                             float* __restrict__ out, int n4)
{
    int i = blockIdx.x * blockDim.x + threadIdx.x;
    if (i >= n4) return;
    float4 v = reinterpret_cast<const float4*>(in)[i];
    v.x = wmma::__float_to_tf32(v.x);
    v.y = wmma::__float_to_tf32(v.y);
    v.z = wmma::__float_to_tf32(v.z);
    v.w = wmma::__float_to_tf32(v.w);
    reinterpret_cast<float4*>(out)[i] = v;
}

// ---------------------------------------------------------------------------
// TF32 WMMA GEMM v3: C[M,N] = A[M,K] @ B[K,N], inputs pre-rounded to tf32.
// 128x256 block tile, BK=32, 256 threads (8 warps, 2x4), warp tile 64x64.
// 3-stage cp.async pipeline, no in-kernel conversions.
// Requires M%128==0, N%256==0, K%32==0.
// ---------------------------------------------------------------------------
constexpr int VBM = 128, VBN = 256, VBK = 32;
constexpr int VLDA = VBK + 4;    // 36 floats (144B rows, 16B-aligned)
constexpr int VLDB = VBN + 4;    // 260 floats (1040B rows, 16B-aligned)
constexpr int VA_FLOATS = VBM * VLDA;  // 4608
constexpr int VB_FLOATS = VBK * VLDB;  // 8320
constexpr int VSTAGE_FLOATS = VA_FLOATS + VB_FLOATS;        // 12928
constexpr int GEMM_SMEM_BYTES = 3 * VSTAGE_FLOATS * 4;       // 155136

__global__ __launch_bounds__(256, 1) void gemm_v3(const float* __restrict__ A,
                                                  const float* __restrict__ Bm,
                                                  float* __restrict__ C,
                                                  int M, int N, int K)
{
    extern __shared__ __align__(128) float vsm[];

    const int tid  = threadIdx.x;
    const int warp = tid >> 5;
    const int wr   = warp >> 2;       // 0..1: 64-row strip
    const int wcc  = warp & 3;        // 0..3: 64-col strip

    const size_t bm0 = (size_t)blockIdx.y * VBM;
    const size_t bn0 = (size_t)blockIdx.x * VBN;

    // cp.async mappings
    const int aRow = tid >> 1;               // 0..127 (2 chunks/row/thread-pair)
    const int aCC  = (tid & 1) << 2;         // chunk col base: 0 or 4 (x2 chunks)
    const int bRow = tid >> 5;               // 0..7 -> covers 32 rows in 4 steps
    const int bCC  = (tid & 31) << 1;        // 0..62 (2 chunks each)

    const uint32_t smem_base = smem_u32(vsm);

    auto issue_stage = [&](int slot, int k0) {
        const uint32_t sa = smem_base + (uint32_t)(slot * VSTAGE_FLOATS) * 4u;
        const uint32_t sb = sa + (uint32_t)VA_FLOATS * 4u;
        // A: 128x32 floats = 1024 16B-chunks; 4 per thread
        #pragma unroll
        for (int j = 0; j < 2; ++j) {
            int cc = aCC + j * 2;   // chunks 0..7 within row (wait: aCC in {0,4}, j*2 -> 0,2 / 4,6)
            const float* src = A + (bm0 + aRow) * K + k0 + cc * 4;
            CP_ASYNC16(sa + (uint32_t)(aRow * VLDA + cc * 4) * 4u, src);
            const float* src2 = A + (bm0 + aRow) * K + k0 + (cc + 1) * 4;
            CP_ASYNC16(sa + (uint32_t)(aRow * VLDA + (cc + 1) * 4) * 4u, src2);
        }
        // B: 32x256 floats = 2048 chunks; 8 per thread
        #pragma unroll
        for (int rr = 0; rr < 4; ++rr) {
            int row = bRow + rr * 8;
            #pragma unroll
            for (int j = 0; j < 2; ++j) {
                int cc = bCC + j;    // 0..63
                const float* src = Bm + (size_t)(k0 + row) * N + bn0 + cc * 4;
                CP_ASYNC16(sb + (uint32_t)(row * VLDB + cc * 4) * 4u, src);
            }
        }
        CP_COMMIT();
    };

    wmma::fragment<wmma::accumulator, 16, 16, 8, float> acc[4][4];
    #pragma unroll
    for (int m = 0; m < 4; ++m)
        #pragma unroll
        for (int n = 0; n < 4; ++n)
            wmma::fill_fragment(acc[m][n], 0.0f);

    const int NIT = K / VBK;
    issue_stage(0, 0);
    issue_stage(1, VBK);

    for (int s = 0; s < NIT; ++s) {
        if (s == NIT - 1) { CP_WAIT0(); } else { CP_WAIT1(); }
        __syncthreads();

        if (s + 2 < NIT) issue_stage((s + 2) % 3, (s + 2) * VBK);

        const float* As = vsm + (s % 3) * VSTAGE_FLOATS;
        const float* Bs = As + VA_FLOATS;

        #pragma unroll
        for (int kk = 0; kk < VBK; kk += 8) {
            wmma::fragment<wmma::matrix_a, 16, 16, 8, wmma::precision::tf32,
                           wmma::row_major> af[4];
            #pragma unroll
            for (int m = 0; m < 4; ++m)
                wmma::load_matrix_sync(af[m],
                    &As[(wr * 64 + m * 16) * VLDA + kk], VLDA);
            #pragma unroll
            for (int n = 0; n < 4; ++n) {
                wmma::fragment<wmma::matrix_b, 16, 16, 8, wmma::precision::tf32,
                               wmma::row_major> bf;
                wmma::load_matrix_sync(bf,
                    &Bs[kk * VLDB + wcc * 64 + n * 16], VLDB);
                #pragma unroll
                for (int m = 0; m < 4; ++m)
                    wmma::mma_sync(acc[m][n], af[m], bf, acc[m][n]);
            }
        }
        __syncthreads();
    }

    #pragma unroll
    for (int m = 0; m < 4; ++m)
        #pragma unroll
        for (int n = 0; n < 4; ++n)
            wmma::store_matrix_sync(
                C + (bm0 + wr * 64 + m * 16) * N + bn0 + wcc * 64 + n * 16,
                acc[m][n], N, wmma::mem_row_major);
}

// ---------------------------------------------------------------------------
// RoPE in-place on [B, S, nh, D] fp32.
// ---------------------------------------------------------------------------
__global__ void rope_k(float* __restrict__ x, int nh, int total)
{
    int idx = blockIdx.x * blockDim.x + threadIdx.x;
    if (idx >= total) return;
    const int half = D_ / 2;
    int i = idx & (half - 1);
    int rest = idx >> 6;
    int h = rest % nh;
    rest /= nh;
    int s = rest % S_;
    int b = rest / S_;

    float inv = __expf(-logf(10000.0f) * (float)i / (float)half);
    float ang = (float)s * inv;
    float sn, cs;
    sincosf(ang, &sn, &cs);

    float* base = x + ((size_t)((b * S_ + s) * nh + h)) * D_;
    float x1 = base[i];
    float x2 = base[i + half];
    base[i]        = x1 * cs - x2 * sn;
    base[i + half] = x2 * cs + x1 * sn;
}

// ---------------------------------------------------------------------------
// Flash attention (WMMA TF32 QK^T + PV, SIMT online softmax) — R4 version.
// ---------------------------------------------------------------------------
constexpr int FQS = 132;
constexpr int FSS = 68;
constexpr int FLASH_SMEM_FLOATS = 4 * 64 * FQS + 64 * FSS + 3 * 64;
constexpr int FLASH_SMEM_BYTES  = (int)(FLASH_SMEM_FLOATS * sizeof(float));

__global__ __launch_bounds__(256) void flash_k(const float* __restrict__ Qg,
                                               const float* __restrict__ Kg,
                                               const float* __restrict__ Vg,
                                               float* __restrict__ Og)
{
    extern __shared__ float smf[];
    float* Qs  = smf;
    float* Ks  = Qs + 64 * FQS;
    float* Vs  = Ks + 64 * FQS;
    float* PVp = Vs + 64 * FQS;
    float* Sc  = PVp + 64 * FQS;
    float* m_s = Sc + 64 * FSS;
    float* l_s = m_s + 64;
    float* a_s = l_s + 64;

    const int tid   = threadIdx.x;
    const int warp  = tid >> 5;
    const int wr    = warp >> 1;
    const int wc    = warp & 1;
    const int qtile = gridDim.x - 1 - blockIdx.x;
    const int h     = blockIdx.y;
    const int b     = blockIdx.z;
    const int q0    = qtile * 64;
    const int kvh   = h >> 2;

    const int tRow = tid >> 4;
    const int j0   = (tid & 15) << 2;
    const int sr = tid >> 2;
    const int sq = tid & 3;
    const float scale = 0.08838834764831845f;

    #pragma unroll
    for (int it = 0; it < 8; ++it) {
        int li  = it * 256 + tid;
        int row = li >> 5;
        int c4  = (li & 31) << 2;
        float4 v = *reinterpret_cast<const float4*>(
            Qg + ((size_t)((b * S_ + q0 + row) * H_ + h)) * D_ + c4);
        v.x = wmma::__float_to_tf32(v.x);
        v.y = wmma::__float_to_tf32(v.y);
        v.z = wmma::__float_to_tf32(v.z);
        v.w = wmma::__float_to_tf32(v.w);
        *reinterpret_cast<float4*>(&Qs[row * FQS + c4]) = v;
    }
    if (tid < 64) { m_s[tid] = -INFINITY; l_s[tid] = 0.f; }

    float o[4][8];
    #pragma unroll
    for (int i = 0; i < 4; ++i)
        #pragma unroll
        for (int j = 0; j < 8; ++j) o[i][j] = 0.f;

    __syncthreads();

    for (int t = 0; t <= qtile; ++t) {
        const int kv0 = t * 64;

        #pragma unroll
        for (int it = 0; it < 8; ++it) {
            int li  = it * 256 + tid;
            int row = li >> 5;
            int c4  = (li & 31) << 2;
            size_t goff = ((size_t)((b * S_ + kv0 + row) * HKV_ + kvh)) * D_ + c4;
            float4 kv4 = *reinterpret_cast<const float4*>(Kg + goff);
            kv4.x = wmma::__float_to_tf32(kv4.x);
            kv4.y = wmma::__float_to_tf32(kv4.y);
            kv4.z = wmma::__float_to_tf32(kv4.z);
            kv4.w = wmma::__float_to_tf32(kv4.w);
            *reinterpret_cast<float4*>(&Ks[row * FQS + c4]) = kv4;
            float4 vv4 = *reinterpret_cast<const float4*>(Vg + goff);
            vv4.x = wmma::__float_to_tf32(vv4.x);
            vv4.y = wmma::__float_to_tf32(vv4.y);
            vv4.z = wmma::__float_to_tf32(vv4.z);
            vv4.w = wmma::__float_to_tf32(vv4.w);
            *reinterpret_cast<float4*>(&Vs[row * FQS + c4]) = vv4;
        }
        __syncthreads();

        {
            wmma::fragment<wmma::accumulator, 16, 16, 8, float> accs[2];
            wmma::fill_fragment(accs[0], 0.0f);
            wmma::fill_fragment(accs[1], 0.0f);
            #pragma unroll
            for (int kk = 0; kk < D_; kk += 8) {
                wmma::fragment<wmma::matrix_a, 16, 16, 8, wmma::precision::tf32,
                               wmma::row_major> af;
                wmma::fragment<wmma::matrix_b, 16, 16, 8, wmma::precision::tf32,
                               wmma::col_major> bf[2];
                wmma::load_matrix_sync(af, &Qs[(wr * 16) * FQS + kk], FQS);
                #pragma unroll
                for (int n = 0; n < 2; ++n)
                    wmma::load_matrix_sync(bf[n],
                        &Ks[(wc * 32 + n * 16) * FQS + kk], FQS);
                wmma::mma_sync(accs[0], af, bf[0], accs[0]);
                wmma::mma_sync(accs[1], af, bf[1], accs[1]);
            }
            #pragma unroll
            for (int n = 0; n < 2; ++n) {
                #pragma unroll
                for (int e = 0; e < accs[n].num_elements; ++e)
                    accs[n].x[e] *= scale;
                wmma::store_matrix_sync(
                    &Sc[(wr * 16) * FSS + wc * 32 + n * 16], accs[n],
                    FSS, wmma::mem_row_major);
            }
        }
        __syncthreads();

        {
            float mo = m_s[sr];
            float vals[16];
            float mx = -INFINITY;
            #pragma unroll
            for (int c = 0; c < 16; ++c) {
                int col = sq * 16 + c;
                float v = Sc[sr * FSS + col];
                if (kv0 + col > q0 + sr) v = -1e30f;
                vals[c] = v;
                mx = fmaxf(mx, v);
            }
            mx = fmaxf(mx, __shfl_xor_sync(0xFFFFFFFFu, mx, 1));
            mx = fmaxf(mx, __shfl_xor_sync(0xFFFFFFFFu, mx, 2));
            mx = fmaxf(mx, mo);
            float sum = 0.f;
            #pragma unroll
            for (int c = 0; c < 16; ++c) {
                float p = __expf(fmaxf(vals[c] - mx, -80.f));
                Sc[sr * FSS + sq * 16 + c] = p;
                sum += p;
            }
            sum += __shfl_xor_sync(0xFFFFFFFFu, sum, 1);
            sum += __shfl_xor_sync(0xFFFFFFFFu, sum, 2);
            if (sq == 0) {
                float alpha = (mo == -INFINITY) ? 0.f : __expf(fmaxf(mo - mx, -80.f));
                l_s[sr] = l_s[sr] * alpha + sum;
                m_s[sr] = mx;
                a_s[sr] = alpha;
            }
        }
        __syncthreads();

        {
            wmma::fragment<wmma::accumulator, 16, 16, 8, float> accp[4];
            #pragma unroll
            for (int n = 0; n < 4; ++n) wmma::fill_fragment(accp[n], 0.0f);
            #pragma unroll
            for (int kk = 0; kk < 64; kk += 8) {
                wmma::fragment<wmma::matrix_a, 16, 16, 8, wmma::precision::tf32,
                               wmma::row_major> af;
                wmma::fragment<wmma::matrix_b, 16, 16, 8, wmma::precision::tf32,
                               wmma::row_major> bf[4];
                wmma::load_matrix_sync(af, &Sc[(wr * 16) * FSS + kk], FSS);
                #pragma unroll
                for (int e = 0; e < af.num_elements; ++e)
                    af.x[e] = wmma::__float_to_tf32(af.x[e]);
                #pragma unroll
                for (int n = 0; n < 4; ++n)
                    wmma::load_matrix_sync(bf[n],
                        &Vs[kk * FQS + wc * 64 + n * 16], FQS);
                #pragma unroll
                for (int n = 0; n < 4; ++n)
                    wmma::mma_sync(accp[n], af, bf[n], accp[n]);
            }
            #pragma unroll
            for (int n = 0; n < 4; ++n)
                wmma::store_matrix_sync(
                    &PVp[(wr * 16) * FQS + wc * 64 + n * 16], accp[n],
                    FQS, wmma::mem_row_major);
        }
        __syncthreads();

        {
            float alpha[4];
            #pragma unroll
            for (int i = 0; i < 4; ++i) alpha[i] = a_s[tRow + 16 * i];
            #pragma unroll
            for (int i = 0; i < 4; ++i) {
                int r = tRow + 16 * i;
                float4 p0 = *reinterpret_cast<const float4*>(&PVp[r * FQS + j0]);
                float4 p1 = *reinterpret_cast<const float4*>(&PVp[r * FQS + j0 + 64]);
                o[i][0] = o[i][0] * alpha[i] + p0.x;
                o[i][1] = o[i][1] * alpha[i] + p0.y;
                o[i][2] = o[i][2] * alpha[i] + p0.z;
                o[i][3] = o[i][3] * alpha[i] + p0.w;
                o[i][4] = o[i][4] * alpha[i] + p1.x;
                o[i][5] = o[i][5] * alpha[i] + p1.y;
                o[i][6] = o[i][6] * alpha[i] + p1.z;
                o[i][7] = o[i][7] * alpha[i] + p1.w;
            }
        }
        __syncthreads();
    }

    #pragma unroll
    for (int i = 0; i < 4; ++i) {
        int r = tRow + 16 * i;
        float inv_l = 1.f / l_s[r];
        float* dst = Og + ((size_t)((b * S_ + q0 + r) * H_ + h)) * D_;
        float4 v0 = make_float4(o[i][0] * inv_l, o[i][1] * inv_l,
                                o[i][2] * inv_l, o[i][3] * inv_l);
        float4 v1 = make_float4(o[i][4] * inv_l, o[i][5] * inv_l,
                                o[i][6] * inv_l, o[i][7] * inv_l);
        *reinterpret_cast<float4*>(dst + j0)      = v0;
        *reinterpret_cast<float4*>(dst + j0 + 64) = v1;
    }
}

// ---------------------------------------------------------------------------
// Launcher
// ---------------------------------------------------------------------------
extern "C" void kernel_launch(void* const* d_in, const int* in_sizes, int n_in,
                              void* d_out, int out_size)
{
    const float* x  = (const float*)d_in[0];
    const float* wq = (const float*)d_in[1];
    const float* wk = (const float*)d_in[2];
    const float* wv = (const float*)d_in[3];
    const float* wo = (const float*)d_in[4];
    float* out = (float*)d_out;

    float *qp, *kp, *vp, *op, *xr, *wqr, *wkr, *wvr, *wor;
    cudaGetSymbolAddress((void**)&qp, g_q);
    cudaGetSymbolAddress((void**)&kp, g_k);
    cudaGetSymbolAddress((void**)&vp, g_v);
    cudaGetSymbolAddress((void**)&op, g_o);
    cudaGetSymbolAddress((void**)&xr, g_xr);
    cudaGetSymbolAddress((void**)&wqr, g_wqr);
    cudaGetSymbolAddress((void**)&wkr, g_wkr);
    cudaGetSymbolAddress((void**)&wvr, g_wvr);
    cudaGetSymbolAddress((void**)&wor, g_wor);

    cudaFuncSetAttribute(gemm_v3, cudaFuncAttributeMaxDynamicSharedMemorySize,
                         GEMM_SMEM_BYTES);
    cudaFuncSetAttribute(flash_k, cudaFuncAttributeMaxDynamicSharedMemorySize,
                         FLASH_SMEM_BYTES);

    const int NKV = HKV_ * D_;   // 1024

    // Pre-round inputs to tf32 bit patterns
    {
        int n4;
        n4 = (M_ * HID_) / 4;
        round_tf32_k<<<(n4 + 255) / 256, 256>>>(x, xr, n4);
        n4 = (HID_ * HID_) / 4;
        round_tf32_k<<<(n4 + 255) / 256, 256>>>(wq, wqr, n4);
        round_tf32_k<<<(n4 + 255) / 256, 256>>>(wo, wor, n4);
        n4 = (HID_ * NKV) / 4;
        round_tf32_k<<<(n4 + 255) / 256, 256>>>(wk, wkr, n4);
        round_tf32_k<<<(n4 + 255) / 256, 256>>>(wv, wvr, n4);
    }

    // QKV projections
    gemm_v3<<<dim3(HID_ / VBN, M_ / VBM), 256, GEMM_SMEM_BYTES>>>(xr, wqr, qp, M_, HID_, HID_);
    gemm_v3<<<dim3(NKV / VBN, M_ / VBM), 256, GEMM_SMEM_BYTES>>>(xr, wkr, kp, M_, NKV, HID_);
    gemm_v3<<<dim3(NKV / VBN, M_ / VBM), 256, GEMM_SMEM_BYTES>>>(xr, wvr, vp, M_, NKV, HID_);

    // RoPE
    {
        int totq = B_ * S_ * H_ * (D_ / 2);
        rope_k<<<(totq + 255) / 256, 256>>>(qp, H_, totq);
        int totk = B_ * S_ * HKV_ * (D_ / 2);
        rope_k<<<(totk + 255) / 256, 256>>>(kp, HKV_, totk);
    }

    // Flash attention
    flash_k<<<dim3(S_ / 64, H_, B_), 256, FLASH_SMEM_BYTES>>>(qp, kp, vp, op);

    // Round attention output, then output projection
    {
        int n4 = (M_ * HID_) / 4;
        round_tf32_k<<<(n4 + 255) / 256, 256>>>(op, op, n4);
    }
    gemm_v3<<<dim3(HID_ / VBN, M_ / VBM), 256, GEMM_SMEM_BYTES>>>(op, wor, out, M_, HID_, HID_);
}

// round 7
// speedup vs baseline: 3.2073x; 1.1928x over previous
#include <cuda_runtime.h>
#include <cuda_bf16.h>
#include <mma.h>
#include <math.h>
#include <float.h>
#include <stdint.h>

using namespace nvcuda;

// Problem constants
#define B_  2
#define S_  2048
#define HID_ 4096
#define H_  32
#define HKV_ 8
#define D_  128
#define M_  (B_ * S_)   // 4096 rows of x

// Scratch (device globals; allocation in kernel_launch is forbidden)
__device__ float g_q[(size_t)B_ * S_ * H_ * D_];
__device__ float g_k[(size_t)B_ * S_ * HKV_ * D_];
__device__ float g_v[(size_t)B_ * S_ * HKV_ * D_];
__device__ float g_o[(size_t)B_ * S_ * H_ * D_];
// TF32-pre-rounded copies
__device__ float g_xr[(size_t)M_ * HID_];
__device__ float g_wqr[(size_t)HID_ * HID_];
__device__ float g_wkr[(size_t)HID_ * (HKV_ * D_)];
__device__ float g_wvr[(size_t)HID_ * (HKV_ * D_)];
__device__ float g_wor[(size_t)HID_ * HID_];

// ---------------------------------------------------------------------------
// helpers
// ---------------------------------------------------------------------------
__device__ __forceinline__ uint32_t smem_u32(const void* p) {
    uint32_t a;
    asm("{ .reg .u64 t; cvta.to.shared.u64 t, %1; cvt.u32.u64 %0, t; }"
        : "=r"(a) : "l"(p));
    return a;
}
#define CP_ASYNC16(dst_u32, src_ptr) \
    asm volatile("cp.async.cg.shared.global [%0], [%1], 16;" \
                 :: "r"(dst_u32), "l"(src_ptr) : "memory")
#define CP_COMMIT() asm volatile("cp.async.commit_group;" ::: "memory")
#define CP_WAIT1()  asm volatile("cp.async.wait_group 1;" ::: "memory")
#define CP_WAIT0()  asm volatile("cp.async.wait_group 0;" ::: "memory")

// m16n8k8 tf32 mma: D += A * B   (A row-major m16k8, B col-major k8n8)
__device__ __forceinline__ void mma_tf32(float d[4], const float a[4],
                                         float b0, float b1) {
    asm volatile(
        "mma.sync.aligned.m16n8k8.row.col.f32.tf32.tf32.f32 "
        "{%0,%1,%2,%3}, {%4,%5,%6,%7}, {%8,%9}, {%0,%1,%2,%3};"
        : "+f"(d[0]), "+f"(d[1]), "+f"(d[2]), "+f"(d[3])
        : "r"(__float_as_uint(a[0])), "r"(__float_as_uint(a[1])),
          "r"(__float_as_uint(a[2])), "r"(__float_as_uint(a[3])),
          "r"(__float_as_uint(b0)), "r"(__float_as_uint(b1)));
}

// ---------------------------------------------------------------------------
// Elementwise TF32 rounding
// ---------------------------------------------------------------------------
__global__ void round_tf32_k(const float* __restrict__ in,
                             float* __restrict__ out, int n4)
{
    int i = blockIdx.x * blockDim.x + threadIdx.x;
    if (i >= n4) return;
    float4 v = reinterpret_cast<const float4*>(in)[i];
    v.x = wmma::__float_to_tf32(v.x);
    v.y = wmma::__float_to_tf32(v.y);
    v.z = wmma::__float_to_tf32(v.z);
    v.w = wmma::__float_to_tf32(v.w);
    reinterpret_cast<float4*>(out)[i] = v;
}

// ---------------------------------------------------------------------------
// TF32 WMMA GEMM v3 (unchanged from R6): C = A @ B, pre-rounded inputs.
// ---------------------------------------------------------------------------
constexpr int VBM = 128, VBN = 256, VBK = 32;
constexpr int VLDA = VBK + 4;
constexpr int VLDB = VBN + 4;
constexpr int VA_FLOATS = VBM * VLDA;
constexpr int VB_FLOATS = VBK * VLDB;
constexpr int VSTAGE_FLOATS = VA_FLOATS + VB_FLOATS;
constexpr int GEMM_SMEM_BYTES = 3 * VSTAGE_FLOATS * 4;

__global__ __launch_bounds__(256, 1) void gemm_v3(const float* __restrict__ A,
                                                  const float* __restrict__ Bm,
                                                  float* __restrict__ C,
                                                  int M, int N, int K)
{
    extern __shared__ __align__(128) float vsm[];

    const int tid  = threadIdx.x;
    const int warp = tid >> 5;
    const int wr   = warp >> 2;
    const int wcc  = warp & 3;

    const size_t bm0 = (size_t)blockIdx.y * VBM;
    const size_t bn0 = (size_t)blockIdx.x * VBN;

    const int aRow = tid >> 1;
    const int aCC  = (tid & 1) << 2;
    const int bRow = tid >> 5;
    const int bCC  = (tid & 31) << 1;

    const uint32_t smem_base = smem_u32(vsm);

    auto issue_stage = [&](int slot, int k0) {
        const uint32_t sa = smem_base + (uint32_t)(slot * VSTAGE_FLOATS) * 4u;
        const uint32_t sb = sa + (uint32_t)VA_FLOATS * 4u;
        #pragma unroll
        for (int j = 0; j < 2; ++j) {
            int cc = aCC + j * 2;
            const float* src = A + (bm0 + aRow) * K + k0 + cc * 4;
            CP_ASYNC16(sa + (uint32_t)(aRow * VLDA + cc * 4) * 4u, src);
            const float* src2 = A + (bm0 + aRow) * K + k0 + (cc + 1) * 4;
            CP_ASYNC16(sa + (uint32_t)(aRow * VLDA + (cc + 1) * 4) * 4u, src2);
        }
        #pragma unroll
        for (int rr = 0; rr < 4; ++rr) {
            int row = bRow + rr * 8;
            #pragma unroll
            for (int j = 0; j < 2; ++j) {
                int cc = bCC + j;
                const float* src = Bm + (size_t)(k0 + row) * N + bn0 + cc * 4;
                CP_ASYNC16(sb + (uint32_t)(row * VLDB + cc * 4) * 4u, src);
            }
        }
        CP_COMMIT();
    };

    wmma::fragment<wmma::accumulator, 16, 16, 8, float> acc[4][4];
    #pragma unroll
    for (int m = 0; m < 4; ++m)
        #pragma unroll
        for (int n = 0; n < 4; ++n)
            wmma::fill_fragment(acc[m][n], 0.0f);

    const int NIT = K / VBK;
    issue_stage(0, 0);
    issue_stage(1, VBK);

    for (int s = 0; s < NIT; ++s) {
        if (s == NIT - 1) { CP_WAIT0(); } else { CP_WAIT1(); }
        __syncthreads();

        if (s + 2 < NIT) issue_stage((s + 2) % 3, (s + 2) * VBK);

        const float* As = vsm + (s % 3) * VSTAGE_FLOATS;
        const float* Bs = As + VA_FLOATS;

        #pragma unroll
        for (int kk = 0; kk < VBK; kk += 8) {
            wmma::fragment<wmma::matrix_a, 16, 16, 8, wmma::precision::tf32,
                           wmma::row_major> af[4];
            #pragma unroll
            for (int m = 0; m < 4; ++m)
                wmma::load_matrix_sync(af[m],
                    &As[(wr * 64 + m * 16) * VLDA + kk], VLDA);
            #pragma unroll
            for (int n = 0; n < 4; ++n) {
                wmma::fragment<wmma::matrix_b, 16, 16, 8, wmma::precision::tf32,
                               wmma::row_major> bf;
                wmma::load_matrix_sync(bf,
                    &Bs[kk * VLDB + wcc * 64 + n * 16], VLDB);
                #pragma unroll
                for (int m = 0; m < 4; ++m)
                    wmma::mma_sync(acc[m][n], af[m], bf, acc[m][n]);
            }
        }
        __syncthreads();
    }

    #pragma unroll
    for (int m = 0; m < 4; ++m)
        #pragma unroll
        for (int n = 0; n < 4; ++n)
            wmma::store_matrix_sync(
                C + (bm0 + wr * 64 + m * 16) * N + bn0 + wcc * 64 + n * 16,
                acc[m][n], N, wmma::mem_row_major);
}

// ---------------------------------------------------------------------------
// RoPE in-place + scale + tf32-round on [B, S, nh, D] fp32.
// ---------------------------------------------------------------------------
__global__ void rope_k(float* __restrict__ x, int nh, int total, float mul)
{
    int idx = blockIdx.x * blockDim.x + threadIdx.x;
    if (idx >= total) return;
    const int half = D_ / 2;
    int i = idx & (half - 1);
    int rest = idx >> 6;
    int h = rest % nh;
    rest /= nh;
    int s = rest % S_;
    int b = rest / S_;

    float inv = __expf(-logf(10000.0f) * (float)i / (float)half);
    float ang = (float)s * inv;
    float sn, cs;
    sincosf(ang, &sn, &cs);

    float* base = x + ((size_t)((b * S_ + s) * nh + h)) * D_;
    float x1 = base[i];
    float x2 = base[i + half];
    base[i]        = wmma::__float_to_tf32((x1 * cs - x2 * sn) * mul);
    base[i + half] = wmma::__float_to_tf32((x2 * cs + x1 * sn) * mul);
}

// ---------------------------------------------------------------------------
// Flash attention v4: raw m16n8k8 tf32 mma, register-resident FA2.
// Grid (S/128, H, B), 256 threads (8 warps x 16 Q rows).
// Q pre-scaled+rounded (rope), K rounded (rope), V rounded (round pass).
// K/V double-buffered via cp.async; 1 barrier per KV tile.
// ---------------------------------------------------------------------------
constexpr int FSTK = 132;   // K smem stride (132 % 32 == 4 -> conflict-free K-frag)
constexpr int FSTV = 136;   // V smem stride (136 % 32 == 8 -> conflict-free V-frag)
constexpr int KV_STAGE = 64 * FSTK + 64 * FSTV;   // 17152 floats
constexpr int FLASH_SMEM_BYTES = 2 * KV_STAGE * 4; // 137216

__global__ __launch_bounds__(256) void flash_k(const float* __restrict__ Qg,
                                               const float* __restrict__ Kg,
                                               const float* __restrict__ Vg,
                                               float* __restrict__ Og)
{
    extern __shared__ float smf[];
    const int tid  = threadIdx.x;
    const int warp = tid >> 5;
    const int lane = tid & 31;
    const int lr   = lane >> 2;   // 0..7
    const int lc   = lane & 3;    // 0..3
    const int qtile = gridDim.x - 1 - blockIdx.x;   // heavy first
    const int h    = blockIdx.y;
    const int b    = blockIdx.z;
    const int q0   = qtile * 128;
    const int kvh  = h >> 2;
    const uint32_t sbase = smem_u32(smf);

    // ---- stage Q (128x128) through stage-0 smem into A-fragment registers ----
    {
        #pragma unroll
        for (int it = 0; it < 16; ++it) {
            int li  = it * 256 + tid;
            int row = li >> 5;
            int c4  = (li & 31) << 2;
            const float* src = Qg + ((size_t)((b * S_ + q0 + row) * H_ + h)) * D_ + c4;
            CP_ASYNC16(sbase + (uint32_t)(row * FSTK + c4) * 4u, src);
        }
        CP_COMMIT(); CP_WAIT0();
        __syncthreads();
    }
    float qf[16][4];
    {
        const int r0 = warp * 16 + lr;
        #pragma unroll
        for (int j = 0; j < 16; ++j) {
            qf[j][0] = smf[r0 * FSTK + 8 * j + lc];
            qf[j][1] = smf[(r0 + 8) * FSTK + 8 * j + lc];
            qf[j][2] = smf[r0 * FSTK + 8 * j + lc + 4];
            qf[j][3] = smf[(r0 + 8) * FSTK + 8 * j + lc + 4];
        }
    }
    __syncthreads();   // all warps done reading Q before KV overwrites stage 0

    float d[16][4];
    #pragma unroll
    for (int i = 0; i < 16; ++i)
        #pragma unroll
        for (int j = 0; j < 4; ++j) d[i][j] = 0.f;
    float m0 = -1e30f, m1 = -1e30f, l0 = 0.f, l1 = 0.f;

    auto issue_kv = [&](int t) {
        const int s = t & 1;
        const uint32_t kb = sbase + (uint32_t)(s * KV_STAGE) * 4u;
        const uint32_t vb = kb + (uint32_t)(64 * FSTK) * 4u;
        const int kv0 = t * 64;
        #pragma unroll
        for (int it = 0; it < 8; ++it) {
            int li  = it * 256 + tid;
            int row = li >> 5;          // 0..63
            int c4  = (li & 31) << 2;
            size_t g = ((size_t)((b * S_ + kv0 + row) * HKV_ + kvh)) * D_ + c4;
            CP_ASYNC16(kb + (uint32_t)(row * FSTK + c4) * 4u, Kg + g);
            CP_ASYNC16(vb + (uint32_t)(row * FSTV + c4) * 4u, Vg + g);
        }
        CP_COMMIT();
    };

    const int tmax = 2 * qtile + 1;
    const int wrow_lo = q0 + warp * 16;     // warp's min global row
    const int wrow_hi = wrow_lo + 15;       // warp's max global row
    issue_kv(0);

    for (int t = 0; t <= tmax; ++t) {
        CP_WAIT0();
        __syncthreads();
        if (t < tmax) issue_kv(t + 1);

        const int kv0 = t * 64;
        if (kv0 <= wrow_hi) {
            const float* Ks = smf + (t & 1) * KV_STAGE;
            const float* Vs = Ks + 64 * FSTK;

            // ---- QK^T: S[16x64] per warp ----
            float s[8][4];
            #pragma unroll
            for (int nf = 0; nf < 8; ++nf)
                #pragma unroll
                for (int e = 0; e < 4; ++e) s[nf][e] = 0.f;
            #pragma unroll
            for (int j = 0; j < 16; ++j) {
                #pragma unroll
                for (int nf = 0; nf < 8; ++nf) {
                    float b0 = Ks[(8 * nf + lr) * FSTK + 8 * j + lc];
                    float b1 = Ks[(8 * nf + lr) * FSTK + 8 * j + lc + 4];
                    mma_tf32(s[nf], qf[j], b0, b1);
                }
            }

            // ---- causal mask (only needed near the diagonal) ----
            if (kv0 + 63 > wrow_lo) {
                const int row0 = wrow_lo + lr;
                #pragma unroll
                for (int nf = 0; nf < 8; ++nf) {
                    int c0 = kv0 + 8 * nf + 2 * lc;
                    if (c0 > row0)         s[nf][0] = -1e30f;
                    if (c0 + 1 > row0)     s[nf][1] = -1e30f;
                    if (c0 > row0 + 8)     s[nf][2] = -1e30f;
                    if (c0 + 1 > row0 + 8) s[nf][3] = -1e30f;
                }
            }

            // ---- online softmax in registers ----
            float mx0 = -1e30f, mx1 = -1e30f;
            #pragma unroll
            for (int nf = 0; nf < 8; ++nf) {
                mx0 = fmaxf(mx0, fmaxf(s[nf][0], s[nf][1]));
                mx1 = fmaxf(mx1, fmaxf(s[nf][2], s[nf][3]));
            }
            mx0 = fmaxf(mx0, __shfl_xor_sync(0xFFFFFFFFu, mx0, 1));
            mx0 = fmaxf(mx0, __shfl_xor_sync(0xFFFFFFFFu, mx0, 2));
            mx1 = fmaxf(mx1, __shfl_xor_sync(0xFFFFFFFFu, mx1, 1));
            mx1 = fmaxf(mx1, __shfl_xor_sync(0xFFFFFFFFu, mx1, 2));
            float m0n = fmaxf(m0, mx0), m1n = fmaxf(m1, mx1);
            float al0 = __expf(m0 - m0n), al1 = __expf(m1 - m1n);
            float su0 = 0.f, su1 = 0.f;
            #pragma unroll
            for (int nf = 0; nf < 8; ++nf) {
                s[nf][0] = __expf(s[nf][0] - m0n);
                s[nf][1] = __expf(s[nf][1] - m0n);
                s[nf][2] = __expf(s[nf][2] - m1n);
                s[nf][3] = __expf(s[nf][3] - m1n);
                su0 += s[nf][0] + s[nf][1];
                su1 += s[nf][2] + s[nf][3];
            }
            su0 += __shfl_xor_sync(0xFFFFFFFFu, su0, 1);
            su0 += __shfl_xor_sync(0xFFFFFFFFu, su0, 2);
            su1 += __shfl_xor_sync(0xFFFFFFFFu, su1, 1);
            su1 += __shfl_xor_sync(0xFFFFFFFFu, su1, 2);
            l0 = l0 * al0 + su0;  m0 = m0n;
            l1 = l1 * al1 + su1;  m1 = m1n;

            // rescale accumulator
            #pragma unroll
            for (int nf = 0; nf < 16; ++nf) {
                d[nf][0] *= al0; d[nf][1] *= al0;
                d[nf][2] *= al1; d[nf][3] *= al1;
            }

            // ---- PV: convert P (C-layout) -> A-layout via shfl, then mma ----
            const int srcA = (lane & ~3) | (lc >> 1);
            const int srcB = srcA + 2;
            #pragma unroll
            for (int j = 0; j < 8; ++j) {
                float pa[4];
                float v00 = __shfl_sync(0xFFFFFFFFu, s[j][0], srcA);
                float v01 = __shfl_sync(0xFFFFFFFFu, s[j][1], srcA);
                pa[0] = (lane & 1) ? v01 : v00;
                float v20 = __shfl_sync(0xFFFFFFFFu, s[j][0], srcB);
                float v21 = __shfl_sync(0xFFFFFFFFu, s[j][1], srcB);
                pa[2] = (lane & 1) ? v21 : v20;
                float v10 = __shfl_sync(0xFFFFFFFFu, s[j][2], srcA);
                float v11 = __shfl_sync(0xFFFFFFFFu, s[j][3], srcA);
                pa[1] = (lane & 1) ? v11 : v10;
                float v30 = __shfl_sync(0xFFFFFFFFu, s[j][2], srcB);
                float v31 = __shfl_sync(0xFFFFFFFFu, s[j][3], srcB);
                pa[3] = (lane & 1) ? v31 : v30;
                pa[0] = wmma::__float_to_tf32(pa[0]);
                pa[1] = wmma::__float_to_tf32(pa[1]);
                pa[2] = wmma::__float_to_tf32(pa[2]);
                pa[3] = wmma::__float_to_tf32(pa[3]);
                #pragma unroll
                for (int nf = 0; nf < 16; ++nf) {
                    float b0 = Vs[(8 * j + lc) * FSTV + 8 * nf + lr];
                    float b1 = Vs[(8 * j + lc + 4) * FSTV + 8 * nf + lr];
                    mma_tf32(d[nf], pa, b0, b1);
                }
            }
        }
    }

    // ---- finalize ----
    const float il0 = 1.f / l0, il1 = 1.f / l1;
    const int row0 = q0 + warp * 16 + lr;
    float* o0 = Og + ((size_t)((b * S_ + row0) * H_ + h)) * D_;
    float* o1 = Og + ((size_t)((b * S_ + row0 + 8) * H_ + h)) * D_;
    #pragma unroll
    for (int nf = 0; nf < 16; ++nf) {
        *reinterpret_cast<float2*>(o0 + 8 * nf + 2 * lc) =
            make_float2(d[nf][0] * il0, d[nf][1] * il0);
        *reinterpret_cast<float2*>(o1 + 8 * nf + 2 * lc) =
            make_float2(d[nf][2] * il1, d[nf][3] * il1);
    }
}

// ---------------------------------------------------------------------------
// Launcher
// ---------------------------------------------------------------------------
extern "C" void kernel_launch(void* const* d_in, const int* in_sizes, int n_in,
                              void* d_out, int out_size)
{
    const float* x  = (const float*)d_in[0];
    const float* wq = (const float*)d_in[1];
    const float* wk = (const float*)d_in[2];
    const float* wv = (const float*)d_in[3];
    const float* wo = (const float*)d_in[4];
    float* out = (float*)d_out;

    float *qp, *kp, *vp, *op, *xr, *wqr, *wkr, *wvr, *wor;
    cudaGetSymbolAddress((void**)&qp, g_q);
    cudaGetSymbolAddress((void**)&kp, g_k);
    cudaGetSymbolAddress((void**)&vp, g_v);
    cudaGetSymbolAddress((void**)&op, g_o);
    cudaGetSymbolAddress((void**)&xr, g_xr);
    cudaGetSymbolAddress((void**)&wqr, g_wqr);
    cudaGetSymbolAddress((void**)&wkr, g_wkr);
    cudaGetSymbolAddress((void**)&wvr, g_wvr);
    cudaGetSymbolAddress((void**)&wor, g_wor);

    cudaFuncSetAttribute(gemm_v3, cudaFuncAttributeMaxDynamicSharedMemorySize,
                         GEMM_SMEM_BYTES);
    cudaFuncSetAttribute(flash_k, cudaFuncAttributeMaxDynamicSharedMemorySize,
                         FLASH_SMEM_BYTES);

    const int NKV = HKV_ * D_;   // 1024

    // Pre-round inputs to tf32 bit patterns
    {
        int n4;
        n4 = (M_ * HID_) / 4;
        round_tf32_k<<<(n4 + 255) / 256, 256>>>(x, xr, n4);
        n4 = (HID_ * HID_) / 4;
        round_tf32_k<<<(n4 + 255) / 256, 256>>>(wq, wqr, n4);
        round_tf32_k<<<(n4 + 255) / 256, 256>>>(wo, wor, n4);
        n4 = (HID_ * NKV) / 4;
        round_tf32_k<<<(n4 + 255) / 256, 256>>>(wk, wkr, n4);
        round_tf32_k<<<(n4 + 255) / 256, 256>>>(wv, wvr, n4);
    }

    // QKV projections
    gemm_v3<<<dim3(HID_ / VBN, M_ / VBM), 256, GEMM_SMEM_BYTES>>>(xr, wqr, qp, M_, HID_, HID_);
    gemm_v3<<<dim3(NKV / VBN, M_ / VBM), 256, GEMM_SMEM_BYTES>>>(xr, wkr, kp, M_, NKV, HID_);
    gemm_v3<<<dim3(NKV / VBN, M_ / VBM), 256, GEMM_SMEM_BYTES>>>(xr, wvr, vp, M_, NKV, HID_);

    // RoPE (+ tf32 round; Q also pre-scaled by 1/sqrt(D)), V rounded
    {
        const float scale = 0.08838834764831845f;
        int totq = B_ * S_ * H_ * (D_ / 2);
        rope_k<<<(totq + 255) / 256, 256>>>(qp, H_, totq, scale);
        int totk = B_ * S_ * HKV_ * (D_ / 2);
        rope_k<<<(totk + 255) / 256, 256>>>(kp, HKV_, totk, 1.0f);
        int n4 = (B_ * S_ * HKV_ * D_) / 4;
        round_tf32_k<<<(n4 + 255) / 256, 256>>>(vp, vp, n4);
    }

    // Flash attention (register-resident FA2, raw mma)
    flash_k<<<dim3(S_ / 128, H_, B_), 256, FLASH_SMEM_BYTES>>>(qp, kp, vp, op);

    // Round attention output, then output projection
    {
        int n4 = (M_ * HID_) / 4;
        round_tf32_k<<<(n4 + 255) / 256, 256>>>(op, op, n4);
    }
    gemm_v3<<<dim3(HID_ / VBN, M_ / VBM), 256, GEMM_SMEM_BYTES>>>(op, wor, out, M_, HID_, HID_);
}

// round 8
// speedup vs baseline: 9.1398x; 2.8497x over previous
#include <cuda_runtime.h>
#include <cuda_fp16.h>
#include <cuda_bf16.h>
#include <mma.h>
#include <math.h>
#include <float.h>
#include <stdint.h>

using namespace nvcuda;

// Problem constants
#define B_  2
#define S_  2048
#define HID_ 4096
#define H_  32
#define HKV_ 8
#define D_  128
#define M_  (B_ * S_)   // 4096 rows of x

// Scratch (device globals; allocation in kernel_launch is forbidden)
__device__ float g_q[(size_t)B_ * S_ * H_ * D_];
__device__ float g_k[(size_t)B_ * S_ * HKV_ * D_];
__device__ float g_v[(size_t)B_ * S_ * HKV_ * D_];
__device__ float g_o[(size_t)B_ * S_ * H_ * D_];
// fp16 operands for GEMMs
__device__ __half g_xh [(size_t)M_ * HID_];
__device__ __half g_wqh[(size_t)HID_ * HID_];
__device__ __half g_wkh[(size_t)HID_ * (HKV_ * D_)];
__device__ __half g_wvh[(size_t)HID_ * (HKV_ * D_)];
__device__ __half g_woh[(size_t)HID_ * HID_];
__device__ __half g_oph[(size_t)M_ * HID_];

// ---------------------------------------------------------------------------
// helpers
// ---------------------------------------------------------------------------
__device__ __forceinline__ uint32_t smem_u32(const void* p) {
    uint32_t a;
    asm("{ .reg .u64 t; cvta.to.shared.u64 t, %1; cvt.u32.u64 %0, t; }"
        : "=r"(a) : "l"(p));
    return a;
}
#define CP_ASYNC16(dst_u32, src_ptr) \
    asm volatile("cp.async.cg.shared.global [%0], [%1], 16;" \
                 :: "r"(dst_u32), "l"(src_ptr) : "memory")
#define CP_COMMIT() asm volatile("cp.async.commit_group;" ::: "memory")
#define CP_WAIT1()  asm volatile("cp.async.wait_group 1;" ::: "memory")
#define CP_WAIT0()  asm volatile("cp.async.wait_group 0;" ::: "memory")

// m16n8k8 tf32 mma (flash)
__device__ __forceinline__ void mma_tf32(float d[4], const float a[4],
                                         float b0, float b1) {
    asm volatile(
        "mma.sync.aligned.m16n8k8.row.col.f32.tf32.tf32.f32 "
        "{%0,%1,%2,%3}, {%4,%5,%6,%7}, {%8,%9}, {%0,%1,%2,%3};"
        : "+f"(d[0]), "+f"(d[1]), "+f"(d[2]), "+f"(d[3])
        : "r"(__float_as_uint(a[0])), "r"(__float_as_uint(a[1])),
          "r"(__float_as_uint(a[2])), "r"(__float_as_uint(a[3])),
          "r"(__float_as_uint(b0)), "r"(__float_as_uint(b1)));
}

// ---------------------------------------------------------------------------
// Elementwise conversions
// ---------------------------------------------------------------------------
__global__ void round_tf32_k(const float* __restrict__ in,
                             float* __restrict__ out, int n4)
{
    int i = blockIdx.x * blockDim.x + threadIdx.x;
    if (i >= n4) return;
    float4 v = reinterpret_cast<const float4*>(in)[i];
    v.x = wmma::__float_to_tf32(v.x);
    v.y = wmma::__float_to_tf32(v.y);
    v.z = wmma::__float_to_tf32(v.z);
    v.w = wmma::__float_to_tf32(v.w);
    reinterpret_cast<float4*>(out)[i] = v;
}

__global__ void f2h_k(const float* __restrict__ in,
                      __half* __restrict__ out, int n4)
{
    int i = blockIdx.x * blockDim.x + threadIdx.x;
    if (i >= n4) return;
    float4 v = reinterpret_cast<const float4*>(in)[i];
    __half2 h0 = __floats2half2_rn(v.x, v.y);
    __half2 h1 = __floats2half2_rn(v.z, v.w);
    reinterpret_cast<__half2*>(out)[2 * i]     = h0;
    reinterpret_cast<__half2*>(out)[2 * i + 1] = h1;
}

// ---------------------------------------------------------------------------
// FP16 tensor-core GEMM: C[M,N](fp32) = A[M,K](fp16) @ B[K,N](fp16).
// 128x256 block tile, BK=64, 256 threads (8 warps, 2x4), warp tile 64x64.
// 3-stage cp.async pipeline. Requires M%128==0, N%256==0, K%64==0.
// ---------------------------------------------------------------------------
constexpr int HBM = 128, HBN = 256, HBK = 64;
constexpr int HLDA = HBK + 8;    // 72 halves (144B rows)
constexpr int HLDB = HBN + 8;    // 264 halves (528B rows)
constexpr int HA_HALVES = HBM * HLDA;   // 9216
constexpr int HB_HALVES = HBK * HLDB;   // 16896
constexpr int HSTAGE_HALVES = HA_HALVES + HB_HALVES;   // 26112
constexpr int GEMM_SMEM_BYTES = 3 * HSTAGE_HALVES * 2; // 156672

__global__ __launch_bounds__(256, 1) void gemm_h(const __half* __restrict__ A,
                                                 const __half* __restrict__ Bm,
                                                 float* __restrict__ C,
                                                 int M, int N, int K)
{
    extern __shared__ __align__(128) __half hsm[];

    const int tid  = threadIdx.x;
    const int warp = tid >> 5;
    const int wr   = warp >> 2;       // 0..1: 64-row strip
    const int wcc  = warp & 3;        // 0..3: 64-col strip

    const size_t bm0 = (size_t)blockIdx.y * HBM;
    const size_t bn0 = (size_t)blockIdx.x * HBN;

    // cp.async mappings (16B = 8 halves per chunk)
    const int aRow = tid >> 1;               // 0..127
    const int aCB  = (tid & 1) << 2;         // chunk 0..3 or 4..7
    const int bRow = tid >> 5;               // 0..7 (+8*rr)
    const int bCC  = tid & 31;               // chunk 0..31 within row

    const uint32_t smem_base = smem_u32(hsm);

    auto issue_stage = [&](int slot, int k0) {
        const uint32_t sa = smem_base + (uint32_t)(slot * HSTAGE_HALVES) * 2u;
        const uint32_t sb = sa + (uint32_t)HA_HALVES * 2u;
        // A: 128 x 64 halves = 1024 chunks; 4/thread
        #pragma unroll
        for (int j = 0; j < 4; ++j) {
            int c = aCB + j;
            const __half* src = A + (bm0 + aRow) * K + k0 + c * 8;
            CP_ASYNC16(sa + (uint32_t)(aRow * HLDA + c * 8) * 2u, src);
        }
        // B: 64 x 256 halves = 2048 chunks; 8/thread
        #pragma unroll
        for (int rr = 0; rr < 8; ++rr) {
            int row = bRow + rr * 8;
            const __half* src = Bm + (size_t)(k0 + row) * N + bn0 + bCC * 8;
            CP_ASYNC16(sb + (uint32_t)(row * HLDB + bCC * 8) * 2u, src);
        }
        CP_COMMIT();
    };

    wmma::fragment<wmma::accumulator, 16, 16, 16, float> acc[4][4];
    #pragma unroll
    for (int m = 0; m < 4; ++m)
        #pragma unroll
        for (int n = 0; n < 4; ++n)
            wmma::fill_fragment(acc[m][n], 0.0f);

    const int NIT = K / HBK;
    issue_stage(0, 0);
    issue_stage(1, HBK);

    for (int s = 0; s < NIT; ++s) {
        if (s == NIT - 1) { CP_WAIT0(); } else { CP_WAIT1(); }
        __syncthreads();

        if (s + 2 < NIT) issue_stage((s + 2) % 3, (s + 2) * HBK);

        const __half* As = hsm + (s % 3) * HSTAGE_HALVES;
        const __half* Bs = As + HA_HALVES;

        #pragma unroll
        for (int kk = 0; kk < HBK; kk += 16) {
            wmma::fragment<wmma::matrix_a, 16, 16, 16, __half,
                           wmma::row_major> af[4];
            #pragma unroll
            for (int m = 0; m < 4; ++m)
                wmma::load_matrix_sync(af[m],
                    &As[(wr * 64 + m * 16) * HLDA + kk], HLDA);
            #pragma unroll
            for (int n = 0; n < 4; ++n) {
                wmma::fragment<wmma::matrix_b, 16, 16, 16, __half,
                               wmma::row_major> bf;
                wmma::load_matrix_sync(bf,
                    &Bs[kk * HLDB + wcc * 64 + n * 16], HLDB);
                #pragma unroll
                for (int m = 0; m < 4; ++m)
                    wmma::mma_sync(acc[m][n], af[m], bf, acc[m][n]);
            }
        }
        __syncthreads();
    }

    #pragma unroll
    for (int m = 0; m < 4; ++m)
        #pragma unroll
        for (int n = 0; n < 4; ++n)
            wmma::store_matrix_sync(
                C + (bm0 + wr * 64 + m * 16) * N + bn0 + wcc * 64 + n * 16,
                acc[m][n], N, wmma::mem_row_major);
}

// ---------------------------------------------------------------------------
// RoPE in-place + scale + tf32-round on [B, S, nh, D] fp32.
// ---------------------------------------------------------------------------
__global__ void rope_k(float* __restrict__ x, int nh, int total, float mul)
{
    int idx = blockIdx.x * blockDim.x + threadIdx.x;
    if (idx >= total) return;
    const int half = D_ / 2;
    int i = idx & (half - 1);
    int rest = idx >> 6;
    int h = rest % nh;
    rest /= nh;
    int s = rest % S_;
    int b = rest / S_;

    float inv = __expf(-logf(10000.0f) * (float)i / (float)half);
    float ang = (float)s * inv;
    float sn, cs;
    sincosf(ang, &sn, &cs);

    float* base = x + ((size_t)((b * S_ + s) * nh + h)) * D_;
    float x1 = base[i];
    float x2 = base[i + half];
    base[i]        = wmma::__float_to_tf32((x1 * cs - x2 * sn) * mul);
    base[i + half] = wmma::__float_to_tf32((x2 * cs + x1 * sn) * mul);
}

// ---------------------------------------------------------------------------
// Flash attention v4 (unchanged from R7): raw m16n8k8 tf32 mma, FA2.
// ---------------------------------------------------------------------------
constexpr int FSTK = 132;
constexpr int FSTV = 136;
constexpr int KV_STAGE = 64 * FSTK + 64 * FSTV;
constexpr int FLASH_SMEM_BYTES = 2 * KV_STAGE * 4;

__global__ __launch_bounds__(256) void flash_k(const float* __restrict__ Qg,
                                               const float* __restrict__ Kg,
                                               const float* __restrict__ Vg,
                                               float* __restrict__ Og)
{
    extern __shared__ float smf[];
    const int tid  = threadIdx.x;
    const int warp = tid >> 5;
    const int lane = tid & 31;
    const int lr   = lane >> 2;
    const int lc   = lane & 3;
    const int qtile = gridDim.x - 1 - blockIdx.x;
    const int h    = blockIdx.y;
    const int b    = blockIdx.z;
    const int q0   = qtile * 128;
    const int kvh  = h >> 2;
    const uint32_t sbase = smem_u32(smf);

    {
        #pragma unroll
        for (int it = 0; it < 16; ++it) {
            int li  = it * 256 + tid;
            int row = li >> 5;
            int c4  = (li & 31) << 2;
            const float* src = Qg + ((size_t)((b * S_ + q0 + row) * H_ + h)) * D_ + c4;
            CP_ASYNC16(sbase + (uint32_t)(row * FSTK + c4) * 4u, src);
        }
        CP_COMMIT(); CP_WAIT0();
        __syncthreads();
    }
    float qf[16][4];
    {
        const int r0 = warp * 16 + lr;
        #pragma unroll
        for (int j = 0; j < 16; ++j) {
            qf[j][0] = smf[r0 * FSTK + 8 * j + lc];
            qf[j][1] = smf[(r0 + 8) * FSTK + 8 * j + lc];
            qf[j][2] = smf[r0 * FSTK + 8 * j + lc + 4];
            qf[j][3] = smf[(r0 + 8) * FSTK + 8 * j + lc + 4];
        }
    }
    __syncthreads();

    float d[16][4];
    #pragma unroll
    for (int i = 0; i < 16; ++i)
        #pragma unroll
        for (int j = 0; j < 4; ++j) d[i][j] = 0.f;
    float m0 = -1e30f, m1 = -1e30f, l0 = 0.f, l1 = 0.f;

    auto issue_kv = [&](int t) {
        const int s = t & 1;
        const uint32_t kb = sbase + (uint32_t)(s * KV_STAGE) * 4u;
        const uint32_t vb = kb + (uint32_t)(64 * FSTK) * 4u;
        const int kv0 = t * 64;
        #pragma unroll
        for (int it = 0; it < 8; ++it) {
            int li  = it * 256 + tid;
            int row = li >> 5;
            int c4  = (li & 31) << 2;
            size_t g = ((size_t)((b * S_ + kv0 + row) * HKV_ + kvh)) * D_ + c4;
            CP_ASYNC16(kb + (uint32_t)(row * FSTK + c4) * 4u, Kg + g);
            CP_ASYNC16(vb + (uint32_t)(row * FSTV + c4) * 4u, Vg + g);
        }
        CP_COMMIT();
    };

    const int tmax = 2 * qtile + 1;
    const int wrow_lo = q0 + warp * 16;
    const int wrow_hi = wrow_lo + 15;
    issue_kv(0);

    for (int t = 0; t <= tmax; ++t) {
        CP_WAIT0();
        __syncthreads();
        if (t < tmax) issue_kv(t + 1);

        const int kv0 = t * 64;
        if (kv0 <= wrow_hi) {
            const float* Ks = smf + (t & 1) * KV_STAGE;
            const float* Vs = Ks + 64 * FSTK;

            float s[8][4];
            #pragma unroll
            for (int nf = 0; nf < 8; ++nf)
                #pragma unroll
                for (int e = 0; e < 4; ++e) s[nf][e] = 0.f;
            #pragma unroll
            for (int j = 0; j < 16; ++j) {
                #pragma unroll
                for (int nf = 0; nf < 8; ++nf) {
                    float b0 = Ks[(8 * nf + lr) * FSTK + 8 * j + lc];
                    float b1 = Ks[(8 * nf + lr) * FSTK + 8 * j + lc + 4];
                    mma_tf32(s[nf], qf[j], b0, b1);
                }
            }

            if (kv0 + 63 > wrow_lo) {
                const int row0 = wrow_lo + lr;
                #pragma unroll
                for (int nf = 0; nf < 8; ++nf) {
                    int c0 = kv0 + 8 * nf + 2 * lc;
                    if (c0 > row0)         s[nf][0] = -1e30f;
                    if (c0 + 1 > row0)     s[nf][1] = -1e30f;
                    if (c0 > row0 + 8)     s[nf][2] = -1e30f;
                    if (c0 + 1 > row0 + 8) s[nf][3] = -1e30f;
                }
            }

            float mx0 = -1e30f, mx1 = -1e30f;
            #pragma unroll
            for (int nf = 0; nf < 8; ++nf) {
                mx0 = fmaxf(mx0, fmaxf(s[nf][0], s[nf][1]));
                mx1 = fmaxf(mx1, fmaxf(s[nf][2], s[nf][3]));
            }
            mx0 = fmaxf(mx0, __shfl_xor_sync(0xFFFFFFFFu, mx0, 1));
            mx0 = fmaxf(mx0, __shfl_xor_sync(0xFFFFFFFFu, mx0, 2));
            mx1 = fmaxf(mx1, __shfl_xor_sync(0xFFFFFFFFu, mx1, 1));
            mx1 = fmaxf(mx1, __shfl_xor_sync(0xFFFFFFFFu, mx1, 2));
            float m0n = fmaxf(m0, mx0), m1n = fmaxf(m1, mx1);
            float al0 = __expf(m0 - m0n), al1 = __expf(m1 - m1n);
            float su0 = 0.f, su1 = 0.f;
            #pragma unroll
            for (int nf = 0; nf < 8; ++nf) {
                s[nf][0] = __expf(s[nf][0] - m0n);
                s[nf][1] = __expf(s[nf][1] - m0n);
                s[nf][2] = __expf(s[nf][2] - m1n);
                s[nf][3] = __expf(s[nf][3] - m1n);
                su0 += s[nf][0] + s[nf][1];
                su1 += s[nf][2] + s[nf][3];
            }
            su0 += __shfl_xor_sync(0xFFFFFFFFu, su0, 1);
            su0 += __shfl_xor_sync(0xFFFFFFFFu, su0, 2);
            su1 += __shfl_xor_sync(0xFFFFFFFFu, su1, 1);
            su1 += __shfl_xor_sync(0xFFFFFFFFu, su1, 2);
            l0 = l0 * al0 + su0;  m0 = m0n;
            l1 = l1 * al1 + su1;  m1 = m1n;

            #pragma unroll
            for (int nf = 0; nf < 16; ++nf) {
                d[nf][0] *= al0; d[nf][1] *= al0;
                d[nf][2] *= al1; d[nf][3] *= al1;
            }

            const int srcA = (lane & ~3) | (lc >> 1);
            const int srcB = srcA + 2;
            #pragma unroll
            for (int j = 0; j < 8; ++j) {
                float pa[4];
                float v00 = __shfl_sync(0xFFFFFFFFu, s[j][0], srcA);
                float v01 = __shfl_sync(0xFFFFFFFFu, s[j][1], srcA);
                pa[0] = (lane & 1) ? v01 : v00;
                float v20 = __shfl_sync(0xFFFFFFFFu, s[j][0], srcB);
                float v21 = __shfl_sync(0xFFFFFFFFu, s[j][1], srcB);
                pa[2] = (lane & 1) ? v21 : v20;
                float v10 = __shfl_sync(0xFFFFFFFFu, s[j][2], srcA);
                float v11 = __shfl_sync(0xFFFFFFFFu, s[j][3], srcA);
                pa[1] = (lane & 1) ? v11 : v10;
                float v30 = __shfl_sync(0xFFFFFFFFu, s[j][2], srcB);
                float v31 = __shfl_sync(0xFFFFFFFFu, s[j][3], srcB);
                pa[3] = (lane & 1) ? v31 : v30;
                pa[0] = wmma::__float_to_tf32(pa[0]);
                pa[1] = wmma::__float_to_tf32(pa[1]);
                pa[2] = wmma::__float_to_tf32(pa[2]);
                pa[3] = wmma::__float_to_tf32(pa[3]);
                #pragma unroll
                for (int nf = 0; nf < 16; ++nf) {
                    float b0 = Vs[(8 * j + lc) * FSTV + 8 * nf + lr];
                    float b1 = Vs[(8 * j + lc + 4) * FSTV + 8 * nf + lr];
                    mma_tf32(d[nf], pa, b0, b1);
                }
            }
        }
    }

    const float il0 = 1.f / l0, il1 = 1.f / l1;
    const int row0 = q0 + warp * 16 + lr;
    float* o0 = Og + ((size_t)((b * S_ + row0) * H_ + h)) * D_;
    float* o1 = Og + ((size_t)((b * S_ + row0 + 8) * H_ + h)) * D_;
    #pragma unroll
    for (int nf = 0; nf < 16; ++nf) {
        *reinterpret_cast<float2*>(o0 + 8 * nf + 2 * lc) =
            make_float2(d[nf][0] * il0, d[nf][1] * il0);
        *reinterpret_cast<float2*>(o1 + 8 * nf + 2 * lc) =
            make_float2(d[nf][2] * il1, d[nf][3] * il1);
    }
}

// ---------------------------------------------------------------------------
// Launcher
// ---------------------------------------------------------------------------
extern "C" void kernel_launch(void* const* d_in, const int* in_sizes, int n_in,
                              void* d_out, int out_size)
{
    const float* x  = (const float*)d_in[0];
    const float* wq = (const float*)d_in[1];
    const float* wk = (const float*)d_in[2];
    const float* wv = (const float*)d_in[3];
    const float* wo = (const float*)d_in[4];
    float* out = (float*)d_out;

    float *qp, *kp, *vp, *op;
    __half *xh, *wqh, *wkh, *wvh, *woh, *oph;
    cudaGetSymbolAddress((void**)&qp, g_q);
    cudaGetSymbolAddress((void**)&kp, g_k);
    cudaGetSymbolAddress((void**)&vp, g_v);
    cudaGetSymbolAddress((void**)&op, g_o);
    cudaGetSymbolAddress((void**)&xh, g_xh);
    cudaGetSymbolAddress((void**)&wqh, g_wqh);
    cudaGetSymbolAddress((void**)&wkh, g_wkh);
    cudaGetSymbolAddress((void**)&wvh, g_wvh);
    cudaGetSymbolAddress((void**)&woh, g_woh);
    cudaGetSymbolAddress((void**)&oph, g_oph);

    cudaFuncSetAttribute(gemm_h, cudaFuncAttributeMaxDynamicSharedMemorySize,
                         GEMM_SMEM_BYTES);
    cudaFuncSetAttribute(flash_k, cudaFuncAttributeMaxDynamicSharedMemorySize,
                         FLASH_SMEM_BYTES);

    const int NKV = HKV_ * D_;   // 1024

    // Convert inputs to fp16
    {
        int n4;
        n4 = (M_ * HID_) / 4;
        f2h_k<<<(n4 + 255) / 256, 256>>>(x, xh, n4);
        n4 = (HID_ * HID_) / 4;
        f2h_k<<<(n4 + 255) / 256, 256>>>(wq, wqh, n4);
        f2h_k<<<(n4 + 255) / 256, 256>>>(wo, woh, n4);
        n4 = (HID_ * NKV) / 4;
        f2h_k<<<(n4 + 255) / 256, 256>>>(wk, wkh, n4);
        f2h_k<<<(n4 + 255) / 256, 256>>>(wv, wvh, n4);
    }

    // QKV projections (fp16 tensor cores, fp32 out)
    gemm_h<<<dim3(HID_ / HBN, M_ / HBM), 256, GEMM_SMEM_BYTES>>>(xh, wqh, qp, M_, HID_, HID_);
    gemm_h<<<dim3(NKV / HBN, M_ / HBM), 256, GEMM_SMEM_BYTES>>>(xh, wkh, kp, M_, NKV, HID_);
    gemm_h<<<dim3(NKV / HBN, M_ / HBM), 256, GEMM_SMEM_BYTES>>>(xh, wvh, vp, M_, NKV, HID_);

    // RoPE (+ tf32 round; Q pre-scaled), V rounded for flash
    {
        const float scale = 0.08838834764831845f;
        int totq = B_ * S_ * H_ * (D_ / 2);
        rope_k<<<(totq + 255) / 256, 256>>>(qp, H_, totq, scale);
        int totk = B_ * S_ * HKV_ * (D_ / 2);
        rope_k<<<(totk + 255) / 256, 256>>>(kp, HKV_, totk, 1.0f);
        int n4 = (B_ * S_ * HKV_ * D_) / 4;
        round_tf32_k<<<(n4 + 255) / 256, 256>>>(vp, vp, n4);
    }

    // Flash attention (tf32 FA2)
    flash_k<<<dim3(S_ / 128, H_, B_), 256, FLASH_SMEM_BYTES>>>(qp, kp, vp, op);

    // Convert attention output to fp16, then output projection
    {
        int n4 = (M_ * HID_) / 4;
        f2h_k<<<(n4 + 255) / 256, 256>>>(op, oph, n4);
    }
    gemm_h<<<dim3(HID_ / HBN, M_ / HBM), 256, GEMM_SMEM_BYTES>>>(oph, woh, out, M_, HID_, HID_);
}

// round 9
// speedup vs baseline: 10.0654x; 1.1013x over previous
#include <cuda_runtime.h>
#include <cuda_fp16.h>
#include <cuda_bf16.h>
#include <mma.h>
#include <math.h>
#include <float.h>
#include <stdint.h>

using namespace nvcuda;

// Problem constants
#define B_  2
#define S_  2048
#define HID_ 4096
#define H_  32
#define HKV_ 8
#define D_  128
#define M_  (B_ * S_)   // 4096 rows of x

// Scratch (device globals)
__device__ float g_q[(size_t)B_ * S_ * H_ * D_];
__device__ float g_k[(size_t)B_ * S_ * HKV_ * D_];
__device__ float g_v[(size_t)B_ * S_ * HKV_ * D_];
// fp16 operands
__device__ __half g_xh [(size_t)M_ * HID_];
__device__ __half g_wqh[(size_t)HID_ * HID_];
__device__ __half g_wkh[(size_t)HID_ * (HKV_ * D_)];
__device__ __half g_wvh[(size_t)HID_ * (HKV_ * D_)];
__device__ __half g_woh[(size_t)HID_ * HID_];
__device__ __half g_oph[(size_t)M_ * HID_];
__device__ __half g_qh [(size_t)B_ * S_ * H_ * D_];       // rope'd+scaled Q
__device__ __half g_kh [(size_t)B_ * S_ * HKV_ * D_];     // rope'd K
__device__ __half g_vth[(size_t)B_ * HKV_ * D_ * S_];     // V transposed [b][kvh][d][s]

// ---------------------------------------------------------------------------
// helpers
// ---------------------------------------------------------------------------
__device__ __forceinline__ uint32_t smem_u32(const void* p) {
    uint32_t a;
    asm("{ .reg .u64 t; cvta.to.shared.u64 t, %1; cvt.u32.u64 %0, t; }"
        : "=r"(a) : "l"(p));
    return a;
}
#define CP_ASYNC16(dst_u32, src_ptr) \
    asm volatile("cp.async.cg.shared.global [%0], [%1], 16;" \
                 :: "r"(dst_u32), "l"(src_ptr) : "memory")
#define CP_COMMIT() asm volatile("cp.async.commit_group;" ::: "memory")
#define CP_WAIT1()  asm volatile("cp.async.wait_group 1;" ::: "memory")
#define CP_WAIT0()  asm volatile("cp.async.wait_group 0;" ::: "memory")

// fp16 m16n8k16 mma, fp32 accumulate
__device__ __forceinline__ void mma_f16(float d[4], uint32_t a0, uint32_t a1,
                                        uint32_t a2, uint32_t a3,
                                        uint32_t b0, uint32_t b1) {
    asm volatile(
        "mma.sync.aligned.m16n8k16.row.col.f32.f16.f16.f32 "
        "{%0,%1,%2,%3}, {%4,%5,%6,%7}, {%8,%9}, {%0,%1,%2,%3};"
        : "+f"(d[0]), "+f"(d[1]), "+f"(d[2]), "+f"(d[3])
        : "r"(a0), "r"(a1), "r"(a2), "r"(a3), "r"(b0), "r"(b1));
}
__device__ __forceinline__ uint32_t pack_h2(float x, float y) {
    __half2 h = __floats2half2_rn(x, y);
    return *reinterpret_cast<uint32_t*>(&h);
}

// ---------------------------------------------------------------------------
// Elementwise fp32 -> fp16
// ---------------------------------------------------------------------------
__global__ void f2h_k(const float* __restrict__ in,
                      __half* __restrict__ out, int n4)
{
    int i = blockIdx.x * blockDim.x + threadIdx.x;
    if (i >= n4) return;
    float4 v = reinterpret_cast<const float4*>(in)[i];
    reinterpret_cast<__half2*>(out)[2 * i]     = __floats2half2_rn(v.x, v.y);
    reinterpret_cast<__half2*>(out)[2 * i + 1] = __floats2half2_rn(v.z, v.w);
}

// ---------------------------------------------------------------------------
// FP16 tensor-core GEMM (unchanged from R8)
// ---------------------------------------------------------------------------
constexpr int HBM = 128, HBN = 256, HBK = 64;
constexpr int HLDA = HBK + 8;
constexpr int HLDB = HBN + 8;
constexpr int HA_HALVES = HBM * HLDA;
constexpr int HB_HALVES = HBK * HLDB;
constexpr int HSTAGE_HALVES = HA_HALVES + HB_HALVES;
constexpr int GEMM_SMEM_BYTES = 3 * HSTAGE_HALVES * 2;

__global__ __launch_bounds__(256, 1) void gemm_h(const __half* __restrict__ A,
                                                 const __half* __restrict__ Bm,
                                                 float* __restrict__ C,
                                                 int M, int N, int K)
{
    extern __shared__ __align__(128) __half hsm[];

    const int tid  = threadIdx.x;
    const int warp = tid >> 5;
    const int wr   = warp >> 2;
    const int wcc  = warp & 3;

    const size_t bm0 = (size_t)blockIdx.y * HBM;
    const size_t bn0 = (size_t)blockIdx.x * HBN;

    const int aRow = tid >> 1;
    const int aCB  = (tid & 1) << 2;
    const int bRow = tid >> 5;
    const int bCC  = tid & 31;

    const uint32_t smem_base = smem_u32(hsm);

    auto issue_stage = [&](int slot, int k0) {
        const uint32_t sa = smem_base + (uint32_t)(slot * HSTAGE_HALVES) * 2u;
        const uint32_t sb = sa + (uint32_t)HA_HALVES * 2u;
        #pragma unroll
        for (int j = 0; j < 4; ++j) {
            int c = aCB + j;
            const __half* src = A + (bm0 + aRow) * K + k0 + c * 8;
            CP_ASYNC16(sa + (uint32_t)(aRow * HLDA + c * 8) * 2u, src);
        }
        #pragma unroll
        for (int rr = 0; rr < 8; ++rr) {
            int row = bRow + rr * 8;
            const __half* src = Bm + (size_t)(k0 + row) * N + bn0 + bCC * 8;
            CP_ASYNC16(sb + (uint32_t)(row * HLDB + bCC * 8) * 2u, src);
        }
        CP_COMMIT();
    };

    wmma::fragment<wmma::accumulator, 16, 16, 16, float> acc[4][4];
    #pragma unroll
    for (int m = 0; m < 4; ++m)
        #pragma unroll
        for (int n = 0; n < 4; ++n)
            wmma::fill_fragment(acc[m][n], 0.0f);

    const int NIT = K / HBK;
    issue_stage(0, 0);
    issue_stage(1, HBK);

    for (int s = 0; s < NIT; ++s) {
        if (s == NIT - 1) { CP_WAIT0(); } else { CP_WAIT1(); }
        __syncthreads();

        if (s + 2 < NIT) issue_stage((s + 2) % 3, (s + 2) * HBK);

        const __half* As = hsm + (s % 3) * HSTAGE_HALVES;
        const __half* Bs = As + HA_HALVES;

        #pragma unroll
        for (int kk = 0; kk < HBK; kk += 16) {
            wmma::fragment<wmma::matrix_a, 16, 16, 16, __half,
                           wmma::row_major> af[4];
            #pragma unroll
            for (int m = 0; m < 4; ++m)
                wmma::load_matrix_sync(af[m],
                    &As[(wr * 64 + m * 16) * HLDA + kk], HLDA);
            #pragma unroll
            for (int n = 0; n < 4; ++n) {
                wmma::fragment<wmma::matrix_b, 16, 16, 16, __half,
                               wmma::row_major> bf;
                wmma::load_matrix_sync(bf,
                    &Bs[kk * HLDB + wcc * 64 + n * 16], HLDB);
                #pragma unroll
                for (int m = 0; m < 4; ++m)
                    wmma::mma_sync(acc[m][n], af[m], bf, acc[m][n]);
            }
        }
        __syncthreads();
    }

    #pragma unroll
    for (int m = 0; m < 4; ++m)
        #pragma unroll
        for (int n = 0; n < 4; ++n)
            wmma::store_matrix_sync(
                C + (bm0 + wr * 64 + m * 16) * N + bn0 + wcc * 64 + n * 16,
                acc[m][n], N, wmma::mem_row_major);
}

// ---------------------------------------------------------------------------
// RoPE: read fp32, write scaled fp16 to separate buffer.
// ---------------------------------------------------------------------------
__global__ void rope_h_k(const float* __restrict__ in, __half* __restrict__ out,
                         int nh, int total, float mul)
{
    int idx = blockIdx.x * blockDim.x + threadIdx.x;
    if (idx >= total) return;
    const int half = D_ / 2;
    int i = idx & (half - 1);
    int rest = idx >> 6;
    int h = rest % nh;
    rest /= nh;
    int s = rest % S_;
    int b = rest / S_;

    float inv = __expf(-logf(10000.0f) * (float)i / (float)half);
    float ang = (float)s * inv;
    float sn, cs;
    sincosf(ang, &sn, &cs);

    size_t base = ((size_t)((b * S_ + s) * nh + h)) * D_;
    float x1 = in[base + i];
    float x2 = in[base + i + half];
    out[base + i]        = __float2half_rn((x1 * cs - x2 * sn) * mul);
    out[base + i + half] = __float2half_rn((x2 * cs + x1 * sn) * mul);
}

// ---------------------------------------------------------------------------
// V transpose + fp16: in fp32 [b][s][kvh][d] -> out fp16 [b][kvh][d][s]
// Grid (S/32, D/32, B*HKV), block 256 (32x8).
// ---------------------------------------------------------------------------
__global__ __launch_bounds__(256) void vt_k(const float* __restrict__ in,
                                            __half* __restrict__ out)
{
    __shared__ __half t[32][34];
    const int tx = threadIdx.x & 31;
    const int ty = threadIdx.x >> 5;
    const int s0 = blockIdx.x * 32;
    const int d0 = blockIdx.y * 32;
    const int bk = blockIdx.z;          // b*HKV + kvh
    const int b  = bk >> 3;
    const int kvh = bk & 7;

    #pragma unroll
    for (int j = 0; j < 32; j += 8) {
        float v = in[((size_t)((b * S_ + s0 + ty + j) * HKV_ + kvh)) * D_ + d0 + tx];
        t[ty + j][tx] = __float2half_rn(v);
    }
    __syncthreads();
    #pragma unroll
    for (int j = 0; j < 32; j += 8)
        out[((size_t)(bk * D_ + d0 + ty + j)) * S_ + s0 + tx] = t[tx][ty + j];
}

// ---------------------------------------------------------------------------
// Flash attention v5: fp16 m16n8k16 FA2, register-resident, zero shuffles.
// Grid (S/128, H, B), 256 threads (8 warps x 16 Q rows).
// Q fp16 [b,s,h,d] (pre-scaled), K fp16 [b,s,kvh,d], V fp16 transposed [b,kvh,d,s].
// Output fp16 [b,s,h,d].
// ---------------------------------------------------------------------------
constexpr int KST = 136;  // K/Q smem stride in halves (272B; 68 u32 % 32 = 4)
constexpr int VST = 72;   // Vt smem stride in halves (144B; 36 u32 % 32 = 4)
constexpr int KV_STG = 64 * KST + 128 * VST;   // halves: 8704 + 9216 = 17920
constexpr int FLASH_SMEM_BYTES = 2 * KV_STG * 2;   // 71680 B

__global__ __launch_bounds__(256) void flash_h(const __half* __restrict__ Qg,
                                               const __half* __restrict__ Kg,
                                               const __half* __restrict__ Vtg,
                                               __half* __restrict__ Og)
{
    extern __shared__ __half smh[];
    uint32_t* smw = reinterpret_cast<uint32_t*>(smh);
    const int tid  = threadIdx.x;
    const int warp = tid >> 5;
    const int lane = tid & 31;
    const int lr   = lane >> 2;   // groupID
    const int lc   = lane & 3;    // threadID in group
    const int qtile = gridDim.x - 1 - blockIdx.x;   // heavy first
    const int h    = blockIdx.y;
    const int b    = blockIdx.z;
    const int q0   = qtile * 128;
    const int kvh  = h >> 2;
    const uint32_t sbase = smem_u32(smh);

    // ---- stage Q (128 x 128 halves) through stage-0 smem into A-frags ----
    {
        #pragma unroll
        for (int it = 0; it < 8; ++it) {
            int li  = it * 256 + tid;
            int row = li >> 4;          // 0..127
            int c   = li & 15;          // 16B chunk (8 halves)
            const __half* src = Qg + ((size_t)((b * S_ + q0 + row) * H_ + h)) * D_ + c * 8;
            CP_ASYNC16(sbase + (uint32_t)(row * KST + c * 8) * 2u, src);
        }
        CP_COMMIT(); CP_WAIT0();
        __syncthreads();
    }
    uint32_t qf[8][4];
    {
        const int r0 = warp * 16 + lr;
        #pragma unroll
        for (int j = 0; j < 8; ++j) {
            int base = r0 * 68 + 8 * j + lc;   // u32 index
            qf[j][0] = smw[base];
            qf[j][1] = smw[base + 8 * 68];
            qf[j][2] = smw[base + 4];
            qf[j][3] = smw[base + 8 * 68 + 4];
        }
    }
    __syncthreads();

    float d[16][4];
    #pragma unroll
    for (int i = 0; i < 16; ++i)
        #pragma unroll
        for (int j = 0; j < 4; ++j) d[i][j] = 0.f;
    float m0 = -1e30f, m1 = -1e30f, l0 = 0.f, l1 = 0.f;

    auto issue_kv = [&](int t) {
        const int s = t & 1;
        const uint32_t kb = sbase + (uint32_t)(s * KV_STG) * 2u;
        const uint32_t vb = kb + (uint32_t)(64 * KST) * 2u;
        const int kv0 = t * 64;
        // K: 64 rows x 16 chunks
        #pragma unroll
        for (int it = 0; it < 4; ++it) {
            int li  = it * 256 + tid;
            int row = li >> 4;
            int c   = li & 15;
            const __half* src = Kg + ((size_t)((b * S_ + kv0 + row) * HKV_ + kvh)) * D_ + c * 8;
            CP_ASYNC16(kb + (uint32_t)(row * KST + c * 8) * 2u, src);
        }
        // Vt: 128 rows (d) x 8 chunks (64 kv halves)
        #pragma unroll
        for (int it = 0; it < 4; ++it) {
            int li  = it * 256 + tid;
            int row = li >> 3;          // 0..127
            int c   = li & 7;
            const __half* src = Vtg + ((size_t)((b * HKV_ + kvh) * D_ + row)) * S_ + kv0 + c * 8;
            CP_ASYNC16(vb + (uint32_t)(row * VST + c * 8) * 2u, src);
        }
        CP_COMMIT();
    };

    const int tmax = 2 * qtile + 1;
    const int wrow_lo = q0 + warp * 16;
    const int wrow_hi = wrow_lo + 15;
    issue_kv(0);

    for (int t = 0; t <= tmax; ++t) {
        CP_WAIT0();
        __syncthreads();
        if (t < tmax) issue_kv(t + 1);

        const int kv0 = t * 64;
        if (kv0 <= wrow_hi) {
            const uint32_t* Kw = smw + (t & 1) * (KV_STG / 2);
            const uint32_t* Vw = Kw + (64 * KST) / 2;

            // ---- QK^T: S[16x64] per warp, 8 k-steps x 8 n-frags ----
            float s[8][4];
            #pragma unroll
            for (int nf = 0; nf < 8; ++nf)
                #pragma unroll
                for (int e = 0; e < 4; ++e) s[nf][e] = 0.f;
            #pragma unroll
            for (int j = 0; j < 8; ++j) {
                #pragma unroll
                for (int nf = 0; nf < 8; ++nf) {
                    int bidx = (8 * nf + lr) * 68 + 8 * j + lc;
                    mma_f16(s[nf], qf[j][0], qf[j][1], qf[j][2], qf[j][3],
                            Kw[bidx], Kw[bidx + 4]);
                }
            }

            // ---- causal mask ----
            if (kv0 + 63 > wrow_lo) {
                const int row0 = wrow_lo + lr;
                #pragma unroll
                for (int nf = 0; nf < 8; ++nf) {
                    int c0 = kv0 + 8 * nf + 2 * lc;
                    if (c0 > row0)         s[nf][0] = -1e30f;
                    if (c0 + 1 > row0)     s[nf][1] = -1e30f;
                    if (c0 > row0 + 8)     s[nf][2] = -1e30f;
                    if (c0 + 1 > row0 + 8) s[nf][3] = -1e30f;
                }
            }

            // ---- online softmax in registers ----
            float mx0 = -1e30f, mx1 = -1e30f;
            #pragma unroll
            for (int nf = 0; nf < 8; ++nf) {
                mx0 = fmaxf(mx0, fmaxf(s[nf][0], s[nf][1]));
                mx1 = fmaxf(mx1, fmaxf(s[nf][2], s[nf][3]));
            }
            mx0 = fmaxf(mx0, __shfl_xor_sync(0xFFFFFFFFu, mx0, 1));
            mx0 = fmaxf(mx0, __shfl_xor_sync(0xFFFFFFFFu, mx0, 2));
            mx1 = fmaxf(mx1, __shfl_xor_sync(0xFFFFFFFFu, mx1, 1));
            mx1 = fmaxf(mx1, __shfl_xor_sync(0xFFFFFFFFu, mx1, 2));
            float m0n = fmaxf(m0, mx0), m1n = fmaxf(m1, mx1);
            float al0 = __expf(m0 - m0n), al1 = __expf(m1 - m1n);
            float su0 = 0.f, su1 = 0.f;
            #pragma unroll
            for (int nf = 0; nf < 8; ++nf) {
                s[nf][0] = __expf(s[nf][0] - m0n);
                s[nf][1] = __expf(s[nf][1] - m0n);
                s[nf][2] = __expf(s[nf][2] - m1n);
                s[nf][3] = __expf(s[nf][3] - m1n);
                su0 += s[nf][0] + s[nf][1];
                su1 += s[nf][2] + s[nf][3];
            }
            su0 += __shfl_xor_sync(0xFFFFFFFFu, su0, 1);
            su0 += __shfl_xor_sync(0xFFFFFFFFu, su0, 2);
            su1 += __shfl_xor_sync(0xFFFFFFFFu, su1, 1);
            su1 += __shfl_xor_sync(0xFFFFFFFFu, su1, 2);
            l0 = l0 * al0 + su0;  m0 = m0n;
            l1 = l1 * al1 + su1;  m1 = m1n;

            #pragma unroll
            for (int nf = 0; nf < 16; ++nf) {
                d[nf][0] *= al0; d[nf][1] *= al0;
                d[nf][2] *= al1; d[nf][3] *= al1;
            }

            // ---- PV: P A-frags straight from score C-frags (no shuffles) ----
            #pragma unroll
            for (int j = 0; j < 4; ++j) {        // kv 16-blocks
                uint32_t pa0 = pack_h2(s[2*j][0],   s[2*j][1]);
                uint32_t pa1 = pack_h2(s[2*j][2],   s[2*j][3]);
                uint32_t pa2 = pack_h2(s[2*j+1][0], s[2*j+1][1]);
                uint32_t pa3 = pack_h2(s[2*j+1][2], s[2*j+1][3]);
                #pragma unroll
                for (int nf = 0; nf < 16; ++nf) {  // d 8-blocks
                    int bidx = (8 * nf + lr) * 36 + 8 * j + lc;
                    mma_f16(d[nf], pa0, pa1, pa2, pa3,
                            Vw[bidx], Vw[bidx + 4]);
                }
            }
        }
    }

    // ---- finalize: write fp16 output ----
    const float il0 = 1.f / l0, il1 = 1.f / l1;
    const int row0 = q0 + warp * 16 + lr;
    __half* o0 = Og + ((size_t)((b * S_ + row0) * H_ + h)) * D_;
    __half* o1 = Og + ((size_t)((b * S_ + row0 + 8) * H_ + h)) * D_;
    #pragma unroll
    for (int nf = 0; nf < 16; ++nf) {
        *reinterpret_cast<uint32_t*>(o0 + 8 * nf + 2 * lc) =
            pack_h2(d[nf][0] * il0, d[nf][1] * il0);
        *reinterpret_cast<uint32_t*>(o1 + 8 * nf + 2 * lc) =
            pack_h2(d[nf][2] * il1, d[nf][3] * il1);
    }
}

// ---------------------------------------------------------------------------
// Launcher
// ---------------------------------------------------------------------------
extern "C" void kernel_launch(void* const* d_in, const int* in_sizes, int n_in,
                              void* d_out, int out_size)
{
    const float* x  = (const float*)d_in[0];
    const float* wq = (const float*)d_in[1];
    const float* wk = (const float*)d_in[2];
    const float* wv = (const float*)d_in[3];
    const float* wo = (const float*)d_in[4];
    float* out = (float*)d_out;

    float *qp, *kp, *vp;
    __half *xh, *wqh, *wkh, *wvh, *woh, *oph, *qh, *kh, *vth;
    cudaGetSymbolAddress((void**)&qp, g_q);
    cudaGetSymbolAddress((void**)&kp, g_k);
    cudaGetSymbolAddress((void**)&vp, g_v);
    cudaGetSymbolAddress((void**)&xh, g_xh);
    cudaGetSymbolAddress((void**)&wqh, g_wqh);
    cudaGetSymbolAddress((void**)&wkh, g_wkh);
    cudaGetSymbolAddress((void**)&wvh, g_wvh);
    cudaGetSymbolAddress((void**)&woh, g_woh);
    cudaGetSymbolAddress((void**)&oph, g_oph);
    cudaGetSymbolAddress((void**)&qh, g_qh);
    cudaGetSymbolAddress((void**)&kh, g_kh);
    cudaGetSymbolAddress((void**)&vth, g_vth);

    cudaFuncSetAttribute(gemm_h, cudaFuncAttributeMaxDynamicSharedMemorySize,
                         GEMM_SMEM_BYTES);
    cudaFuncSetAttribute(flash_h, cudaFuncAttributeMaxDynamicSharedMemorySize,
                         FLASH_SMEM_BYTES);

    const int NKV = HKV_ * D_;   // 1024

    // Convert inputs to fp16
    {
        int n4;
        n4 = (M_ * HID_) / 4;
        f2h_k<<<(n4 + 255) / 256, 256>>>(x, xh, n4);
        n4 = (HID_ * HID_) / 4;
        f2h_k<<<(n4 + 255) / 256, 256>>>(wq, wqh, n4);
        f2h_k<<<(n4 + 255) / 256, 256>>>(wo, woh, n4);
        n4 = (HID_ * NKV) / 4;
        f2h_k<<<(n4 + 255) / 256, 256>>>(wk, wkh, n4);
        f2h_k<<<(n4 + 255) / 256, 256>>>(wv, wvh, n4);
    }

    // QKV projections (fp16 tensor cores, fp32 out)
    gemm_h<<<dim3(HID_ / HBN, M_ / HBM), 256, GEMM_SMEM_BYTES>>>(xh, wqh, qp, M_, HID_, HID_);
    gemm_h<<<dim3(NKV / HBN, M_ / HBM), 256, GEMM_SMEM_BYTES>>>(xh, wkh, kp, M_, NKV, HID_);
    gemm_h<<<dim3(NKV / HBN, M_ / HBM), 256, GEMM_SMEM_BYTES>>>(xh, wvh, vp, M_, NKV, HID_);

    // RoPE -> fp16 (Q pre-scaled); V transpose -> fp16
    {
        const float scale = 0.08838834764831845f;
        int totq = B_ * S_ * H_ * (D_ / 2);
        rope_h_k<<<(totq + 255) / 256, 256>>>(qp, qh, H_, totq, scale);
        int totk = B_ * S_ * HKV_ * (D_ / 2);
        rope_h_k<<<(totk + 255) / 256, 256>>>(kp, kh, HKV_, totk, 1.0f);
        vt_k<<<dim3(S_ / 32, D_ / 32, B_ * HKV_), 256>>>(vp, vth);
    }

    // Flash attention (fp16 FA2) -> fp16 output
    flash_h<<<dim3(S_ / 128, H_, B_), 256, FLASH_SMEM_BYTES>>>(qh, kh, vth, oph);

    // Output projection
    gemm_h<<<dim3(HID_ / HBN, M_ / HBM), 256, GEMM_SMEM_BYTES>>>(oph, woh, out, M_, HID_, HID_);
}

// round 10
// speedup vs baseline: 10.1947x; 1.0129x over previous
#include <cuda_runtime.h>
#include <cuda_fp16.h>
#include <cuda_bf16.h>
#include <mma.h>
#include <math.h>
#include <float.h>
#include <stdint.h>

using namespace nvcuda;

// Problem constants
#define B_  2
#define S_  2048
#define HID_ 4096
#define H_  32
#define HKV_ 8
#define D_  128
#define M_  (B_ * S_)   // 4096 rows of x

// Scratch (device globals)
__device__ float g_q[(size_t)B_ * S_ * H_ * D_];
__device__ float g_k[(size_t)B_ * S_ * HKV_ * D_];
__device__ float g_v[(size_t)B_ * S_ * HKV_ * D_];
// fp16 operands
__device__ __half g_xh [(size_t)M_ * HID_];
__device__ __half g_wqh[(size_t)HID_ * HID_];
__device__ __half g_wkh[(size_t)HID_ * (HKV_ * D_)];
__device__ __half g_wvh[(size_t)HID_ * (HKV_ * D_)];
__device__ __half g_woh[(size_t)HID_ * HID_];
__device__ __half g_oph[(size_t)M_ * HID_];
__device__ __half g_qh [(size_t)B_ * S_ * H_ * D_];       // rope'd+scaled Q (log2e folded)
__device__ __half g_kh [(size_t)B_ * S_ * HKV_ * D_];     // rope'd K
__device__ __half g_vth[(size_t)B_ * HKV_ * D_ * S_];     // V transposed [b][kvh][d][s]

// ---------------------------------------------------------------------------
// helpers
// ---------------------------------------------------------------------------
__device__ __forceinline__ uint32_t smem_u32(const void* p) {
    uint32_t a;
    asm("{ .reg .u64 t; cvta.to.shared.u64 t, %1; cvt.u32.u64 %0, t; }"
        : "=r"(a) : "l"(p));
    return a;
}
#define CP_ASYNC16(dst_u32, src_ptr) \
    asm volatile("cp.async.cg.shared.global [%0], [%1], 16;" \
                 :: "r"(dst_u32), "l"(src_ptr) : "memory")
#define CP_COMMIT() asm volatile("cp.async.commit_group;" ::: "memory")
#define CP_WAIT1()  asm volatile("cp.async.wait_group 1;" ::: "memory")
#define CP_WAIT0()  asm volatile("cp.async.wait_group 0;" ::: "memory")

// fp16 m16n8k16 mma, fp32 accumulate
__device__ __forceinline__ void mma_f16(float d[4], uint32_t a0, uint32_t a1,
                                        uint32_t a2, uint32_t a3,
                                        uint32_t b0, uint32_t b1) {
    asm volatile(
        "mma.sync.aligned.m16n8k16.row.col.f32.f16.f16.f32 "
        "{%0,%1,%2,%3}, {%4,%5,%6,%7}, {%8,%9}, {%0,%1,%2,%3};"
        : "+f"(d[0]), "+f"(d[1]), "+f"(d[2]), "+f"(d[3])
        : "r"(a0), "r"(a1), "r"(a2), "r"(a3), "r"(b0), "r"(b1));
}
__device__ __forceinline__ uint32_t pack_h2(float x, float y) {
    __half2 h = __floats2half2_rn(x, y);
    return *reinterpret_cast<uint32_t*>(&h);
}

// ---------------------------------------------------------------------------
// Elementwise fp32 -> fp16
// ---------------------------------------------------------------------------
__global__ void f2h_k(const float* __restrict__ in,
                      __half* __restrict__ out, int n4)
{
    int i = blockIdx.x * blockDim.x + threadIdx.x;
    if (i >= n4) return;
    float4 v = reinterpret_cast<const float4*>(in)[i];
    reinterpret_cast<__half2*>(out)[2 * i]     = __floats2half2_rn(v.x, v.y);
    reinterpret_cast<__half2*>(out)[2 * i + 1] = __floats2half2_rn(v.z, v.w);
}

// ---------------------------------------------------------------------------
// FP16 tensor-core GEMM (unchanged from R8)
// ---------------------------------------------------------------------------
constexpr int HBM = 128, HBN = 256, HBK = 64;
constexpr int HLDA = HBK + 8;
constexpr int HLDB = HBN + 8;
constexpr int HA_HALVES = HBM * HLDA;
constexpr int HB_HALVES = HBK * HLDB;
constexpr int HSTAGE_HALVES = HA_HALVES + HB_HALVES;
constexpr int GEMM_SMEM_BYTES = 3 * HSTAGE_HALVES * 2;

__global__ __launch_bounds__(256, 1) void gemm_h(const __half* __restrict__ A,
                                                 const __half* __restrict__ Bm,
                                                 float* __restrict__ C,
                                                 int M, int N, int K)
{
    extern __shared__ __align__(128) __half hsm[];

    const int tid  = threadIdx.x;
    const int warp = tid >> 5;
    const int wr   = warp >> 2;
    const int wcc  = warp & 3;

    const size_t bm0 = (size_t)blockIdx.y * HBM;
    const size_t bn0 = (size_t)blockIdx.x * HBN;

    const int aRow = tid >> 1;
    const int aCB  = (tid & 1) << 2;
    const int bRow = tid >> 5;
    const int bCC  = tid & 31;

    const uint32_t smem_base = smem_u32(hsm);

    auto issue_stage = [&](int slot, int k0) {
        const uint32_t sa = smem_base + (uint32_t)(slot * HSTAGE_HALVES) * 2u;
        const uint32_t sb = sa + (uint32_t)HA_HALVES * 2u;
        #pragma unroll
        for (int j = 0; j < 4; ++j) {
            int c = aCB + j;
            const __half* src = A + (bm0 + aRow) * K + k0 + c * 8;
            CP_ASYNC16(sa + (uint32_t)(aRow * HLDA + c * 8) * 2u, src);
        }
        #pragma unroll
        for (int rr = 0; rr < 8; ++rr) {
            int row = bRow + rr * 8;
            const __half* src = Bm + (size_t)(k0 + row) * N + bn0 + bCC * 8;
            CP_ASYNC16(sb + (uint32_t)(row * HLDB + bCC * 8) * 2u, src);
        }
        CP_COMMIT();
    };

    wmma::fragment<wmma::accumulator, 16, 16, 16, float> acc[4][4];
    #pragma unroll
    for (int m = 0; m < 4; ++m)
        #pragma unroll
        for (int n = 0; n < 4; ++n)
            wmma::fill_fragment(acc[m][n], 0.0f);

    const int NIT = K / HBK;
    issue_stage(0, 0);
    issue_stage(1, HBK);

    for (int s = 0; s < NIT; ++s) {
        if (s == NIT - 1) { CP_WAIT0(); } else { CP_WAIT1(); }
        __syncthreads();

        if (s + 2 < NIT) issue_stage((s + 2) % 3, (s + 2) * HBK);

        const __half* As = hsm + (s % 3) * HSTAGE_HALVES;
        const __half* Bs = As + HA_HALVES;

        #pragma unroll
        for (int kk = 0; kk < HBK; kk += 16) {
            wmma::fragment<wmma::matrix_a, 16, 16, 16, __half,
                           wmma::row_major> af[4];
            #pragma unroll
            for (int m = 0; m < 4; ++m)
                wmma::load_matrix_sync(af[m],
                    &As[(wr * 64 + m * 16) * HLDA + kk], HLDA);
            #pragma unroll
            for (int n = 0; n < 4; ++n) {
                wmma::fragment<wmma::matrix_b, 16, 16, 16, __half,
                               wmma::row_major> bf;
                wmma::load_matrix_sync(bf,
                    &Bs[kk * HLDB + wcc * 64 + n * 16], HLDB);
                #pragma unroll
                for (int m = 0; m < 4; ++m)
                    wmma::mma_sync(acc[m][n], af[m], bf, acc[m][n]);
            }
        }
        __syncthreads();
    }

    #pragma unroll
    for (int m = 0; m < 4; ++m)
        #pragma unroll
        for (int n = 0; n < 4; ++n)
            wmma::store_matrix_sync(
                C + (bm0 + wr * 64 + m * 16) * N + bn0 + wcc * 64 + n * 16,
                acc[m][n], N, wmma::mem_row_major);
}

// ---------------------------------------------------------------------------
// RoPE: read fp32, write scaled fp16 to separate buffer.
// ---------------------------------------------------------------------------
__global__ void rope_h_k(const float* __restrict__ in, __half* __restrict__ out,
                         int nh, int total, float mul)
{
    int idx = blockIdx.x * blockDim.x + threadIdx.x;
    if (idx >= total) return;
    const int half = D_ / 2;
    int i = idx & (half - 1);
    int rest = idx >> 6;
    int h = rest % nh;
    rest /= nh;
    int s = rest % S_;
    int b = rest / S_;

    float inv = __expf(-logf(10000.0f) * (float)i / (float)half);
    float ang = (float)s * inv;
    float sn, cs;
    sincosf(ang, &sn, &cs);

    size_t base = ((size_t)((b * S_ + s) * nh + h)) * D_;
    float x1 = in[base + i];
    float x2 = in[base + i + half];
    out[base + i]        = __float2half_rn((x1 * cs - x2 * sn) * mul);
    out[base + i + half] = __float2half_rn((x2 * cs + x1 * sn) * mul);
}

// ---------------------------------------------------------------------------
// V transpose + fp16: [b][s][kvh][d] fp32 -> [b][kvh][d][s] fp16
// ---------------------------------------------------------------------------
__global__ __launch_bounds__(256) void vt_k(const float* __restrict__ in,
                                            __half* __restrict__ out)
{
    __shared__ __half t[32][34];
    const int tx = threadIdx.x & 31;
    const int ty = threadIdx.x >> 5;
    const int s0 = blockIdx.x * 32;
    const int d0 = blockIdx.y * 32;
    const int bk = blockIdx.z;
    const int b  = bk >> 3;
    const int kvh = bk & 7;

    #pragma unroll
    for (int j = 0; j < 32; j += 8) {
        float v = in[((size_t)((b * S_ + s0 + ty + j) * HKV_ + kvh)) * D_ + d0 + tx];
        t[ty + j][tx] = __float2half_rn(v);
    }
    __syncthreads();
    #pragma unroll
    for (int j = 0; j < 32; j += 8)
        out[((size_t)(bk * D_ + d0 + ty + j)) * S_ + s0 + tx] = t[tx][ty + j];
}

// ---------------------------------------------------------------------------
// Flash attention v6: fp16 m16n8k16 FA2; Q resident in SMEM (regs freed),
// 2 CTAs/SM via __launch_bounds__(256,2); exp2-domain softmax
// (Q pre-scaled by 1/sqrt(D)*log2(e) in rope).
// Grid (S/128, H, B), 256 threads (8 warps x 16 Q rows).
// ---------------------------------------------------------------------------
constexpr int KST = 136;  // K/Q smem stride halves (68 u32; %32==4 -> conflict-free)
constexpr int VST = 72;   // Vt smem stride halves (36 u32; %32==4 -> conflict-free)
constexpr int QSM_HALVES = 128 * KST;                 // 17408
constexpr int KV_STG = 64 * KST + 128 * VST;          // 17920 halves
constexpr int FLASH_SMEM_BYTES = (QSM_HALVES + 2 * KV_STG) * 2;  // 106496 B

__global__ __launch_bounds__(256, 2) void flash_h(const __half* __restrict__ Qg,
                                                  const __half* __restrict__ Kg,
                                                  const __half* __restrict__ Vtg,
                                                  __half* __restrict__ Og)
{
    extern __shared__ __half smh[];
    uint32_t* smw = reinterpret_cast<uint32_t*>(smh);
    const int tid  = threadIdx.x;
    const int warp = tid >> 5;
    const int lane = tid & 31;
    const int lr   = lane >> 2;
    const int lc   = lane & 3;
    const int qtile = gridDim.x - 1 - blockIdx.x;   // heavy first
    const int h    = blockIdx.y;
    const int b    = blockIdx.z;
    const int q0   = qtile * 128;
    const int kvh  = h >> 2;
    const uint32_t sbase = smem_u32(smh);

    // ---- stage Q (128 x 128 halves) into persistent smem region ----
    #pragma unroll
    for (int it = 0; it < 8; ++it) {
        int li  = it * 256 + tid;
        int row = li >> 4;
        int c   = li & 15;
        const __half* src = Qg + ((size_t)((b * S_ + q0 + row) * H_ + h)) * D_ + c * 8;
        CP_ASYNC16(sbase + (uint32_t)(row * KST + c * 8) * 2u, src);
    }
    CP_COMMIT();

    float d[16][4];
    #pragma unroll
    for (int i = 0; i < 16; ++i)
        #pragma unroll
        for (int j = 0; j < 4; ++j) d[i][j] = 0.f;
    float m0 = -1e30f, m1 = -1e30f, l0 = 0.f, l1 = 0.f;

    auto issue_kv = [&](int t) {
        const int s = t & 1;
        const uint32_t kb = sbase + (uint32_t)(QSM_HALVES + s * KV_STG) * 2u;
        const uint32_t vb = kb + (uint32_t)(64 * KST) * 2u;
        const int kv0 = t * 64;
        #pragma unroll
        for (int it = 0; it < 4; ++it) {
            int li  = it * 256 + tid;
            int row = li >> 4;
            int c   = li & 15;
            const __half* src = Kg + ((size_t)((b * S_ + kv0 + row) * HKV_ + kvh)) * D_ + c * 8;
            CP_ASYNC16(kb + (uint32_t)(row * KST + c * 8) * 2u, src);
        }
        #pragma unroll
        for (int it = 0; it < 4; ++it) {
            int li  = it * 256 + tid;
            int row = li >> 3;
            int c   = li & 7;
            const __half* src = Vtg + ((size_t)((b * HKV_ + kvh) * D_ + row)) * S_ + kv0 + c * 8;
            CP_ASYNC16(vb + (uint32_t)(row * VST + c * 8) * 2u, src);
        }
        CP_COMMIT();
    };

    const int tmax = 2 * qtile + 1;
    const int wrow_lo = q0 + warp * 16;
    const int wrow_hi = wrow_lo + 15;
    const int r068 = (warp * 16 + lr) * 68;   // Q u32 row base
    issue_kv(0);

    for (int t = 0; t <= tmax; ++t) {
        CP_WAIT0();
        __syncthreads();
        if (t < tmax) issue_kv(t + 1);

        const int kv0 = t * 64;
        if (kv0 <= wrow_hi) {
            const uint32_t* Kw = smw + QSM_HALVES / 2 + (t & 1) * (KV_STG / 2);
            const uint32_t* Vw = Kw + (64 * KST) / 2;

            // ---- QK^T: S[16x64] per warp ----
            float s[8][4];
            #pragma unroll
            for (int nf = 0; nf < 8; ++nf)
                #pragma unroll
                for (int e = 0; e < 4; ++e) s[nf][e] = 0.f;
            #pragma unroll
            for (int j = 0; j < 8; ++j) {
                int qb = r068 + 8 * j + lc;
                uint32_t qa0 = smw[qb];
                uint32_t qa1 = smw[qb + 544];    // +8 rows
                uint32_t qa2 = smw[qb + 4];
                uint32_t qa3 = smw[qb + 548];
                #pragma unroll
                for (int nf = 0; nf < 8; ++nf) {
                    int bidx = (8 * nf + lr) * 68 + 8 * j + lc;
                    mma_f16(s[nf], qa0, qa1, qa2, qa3, Kw[bidx], Kw[bidx + 4]);
                }
            }

            // ---- causal mask ----
            if (kv0 + 63 > wrow_lo) {
                const int row0 = wrow_lo + lr;
                #pragma unroll
                for (int nf = 0; nf < 8; ++nf) {
                    int c0 = kv0 + 8 * nf + 2 * lc;
                    if (c0 > row0)         s[nf][0] = -1e30f;
                    if (c0 + 1 > row0)     s[nf][1] = -1e30f;
                    if (c0 > row0 + 8)     s[nf][2] = -1e30f;
                    if (c0 + 1 > row0 + 8) s[nf][3] = -1e30f;
                }
            }

            // ---- online softmax (log2 domain; Q pre-scaled by log2e/sqrt(D)) ----
            float mx0 = -1e30f, mx1 = -1e30f;
            #pragma unroll
            for (int nf = 0; nf < 8; ++nf) {
                mx0 = fmaxf(mx0, fmaxf(s[nf][0], s[nf][1]));
                mx1 = fmaxf(mx1, fmaxf(s[nf][2], s[nf][3]));
            }
            mx0 = fmaxf(mx0, __shfl_xor_sync(0xFFFFFFFFu, mx0, 1));
            mx0 = fmaxf(mx0, __shfl_xor_sync(0xFFFFFFFFu, mx0, 2));
            mx1 = fmaxf(mx1, __shfl_xor_sync(0xFFFFFFFFu, mx1, 1));
            mx1 = fmaxf(mx1, __shfl_xor_sync(0xFFFFFFFFu, mx1, 2));
            float m0n = fmaxf(m0, mx0), m1n = fmaxf(m1, mx1);
            float al0 = exp2f(m0 - m0n), al1 = exp2f(m1 - m1n);
            float su0 = 0.f, su1 = 0.f;
            #pragma unroll
            for (int nf = 0; nf < 8; ++nf) {
                s[nf][0] = exp2f(s[nf][0] - m0n);
                s[nf][1] = exp2f(s[nf][1] - m0n);
                s[nf][2] = exp2f(s[nf][2] - m1n);
                s[nf][3] = exp2f(s[nf][3] - m1n);
                su0 += s[nf][0] + s[nf][1];
                su1 += s[nf][2] + s[nf][3];
            }
            su0 += __shfl_xor_sync(0xFFFFFFFFu, su0, 1);
            su0 += __shfl_xor_sync(0xFFFFFFFFu, su0, 2);
            su1 += __shfl_xor_sync(0xFFFFFFFFu, su1, 1);
            su1 += __shfl_xor_sync(0xFFFFFFFFu, su1, 2);
            l0 = l0 * al0 + su0;  m0 = m0n;
            l1 = l1 * al1 + su1;  m1 = m1n;

            #pragma unroll
            for (int nf = 0; nf < 16; ++nf) {
                d[nf][0] *= al0; d[nf][1] *= al0;
                d[nf][2] *= al1; d[nf][3] *= al1;
            }

            // ---- PV: P A-frags straight from score C-frags ----
            #pragma unroll
            for (int j = 0; j < 4; ++j) {
                uint32_t pa0 = pack_h2(s[2*j][0],   s[2*j][1]);
                uint32_t pa1 = pack_h2(s[2*j][2],   s[2*j][3]);
                uint32_t pa2 = pack_h2(s[2*j+1][0], s[2*j+1][1]);
                uint32_t pa3 = pack_h2(s[2*j+1][2], s[2*j+1][3]);
                #pragma unroll
                for (int nf = 0; nf < 16; ++nf) {
                    int bidx = (8 * nf + lr) * 36 + 8 * j + lc;
                    mma_f16(d[nf], pa0, pa1, pa2, pa3,
                            Vw[bidx], Vw[bidx + 4]);
                }
            }
        }
    }

    // ---- finalize: write fp16 output ----
    const float il0 = 1.f / l0, il1 = 1.f / l1;
    const int row0 = q0 + warp * 16 + lr;
    __half* o0 = Og + ((size_t)((b * S_ + row0) * H_ + h)) * D_;
    __half* o1 = Og + ((size_t)((b * S_ + row0 + 8) * H_ + h)) * D_;
    #pragma unroll
    for (int nf = 0; nf < 16; ++nf) {
        *reinterpret_cast<uint32_t*>(o0 + 8 * nf + 2 * lc) =
            pack_h2(d[nf][0] * il0, d[nf][1] * il0);
        *reinterpret_cast<uint32_t*>(o1 + 8 * nf + 2 * lc) =
            pack_h2(d[nf][2] * il1, d[nf][3] * il1);
    }
}

// ---------------------------------------------------------------------------
// Launcher
// ---------------------------------------------------------------------------
extern "C" void kernel_launch(void* const* d_in, const int* in_sizes, int n_in,
                              void* d_out, int out_size)
{
    const float* x  = (const float*)d_in[0];
    const float* wq = (const float*)d_in[1];
    const float* wk = (const float*)d_in[2];
    const float* wv = (const float*)d_in[3];
    const float* wo = (const float*)d_in[4];
    float* out = (float*)d_out;

    float *qp, *kp, *vp;
    __half *xh, *wqh, *wkh, *wvh, *woh, *oph, *qh, *kh, *vth;
    cudaGetSymbolAddress((void**)&qp, g_q);
    cudaGetSymbolAddress((void**)&kp, g_k);
    cudaGetSymbolAddress((void**)&vp, g_v);
    cudaGetSymbolAddress((void**)&xh, g_xh);
    cudaGetSymbolAddress((void**)&wqh, g_wqh);
    cudaGetSymbolAddress((void**)&wkh, g_wkh);
    cudaGetSymbolAddress((void**)&wvh, g_wvh);
    cudaGetSymbolAddress((void**)&woh, g_woh);
    cudaGetSymbolAddress((void**)&oph, g_oph);
    cudaGetSymbolAddress((void**)&qh, g_qh);
    cudaGetSymbolAddress((void**)&kh, g_kh);
    cudaGetSymbolAddress((void**)&vth, g_vth);

    cudaFuncSetAttribute(gemm_h, cudaFuncAttributeMaxDynamicSharedMemorySize,
                         GEMM_SMEM_BYTES);
    cudaFuncSetAttribute(flash_h, cudaFuncAttributeMaxDynamicSharedMemorySize,
                         FLASH_SMEM_BYTES);

    const int NKV = HKV_ * D_;   // 1024

    // Convert inputs to fp16
    {
        int n4;
        n4 = (M_ * HID_) / 4;
        f2h_k<<<(n4 + 255) / 256, 256>>>(x, xh, n4);
        n4 = (HID_ * HID_) / 4;
        f2h_k<<<(n4 + 255) / 256, 256>>>(wq, wqh, n4);
        f2h_k<<<(n4 + 255) / 256, 256>>>(wo, woh, n4);
        n4 = (HID_ * NKV) / 4;
        f2h_k<<<(n4 + 255) / 256, 256>>>(wk, wkh, n4);
        f2h_k<<<(n4 + 255) / 256, 256>>>(wv, wvh, n4);
    }

    // QKV projections (fp16 tensor cores, fp32 out)
    gemm_h<<<dim3(HID_ / HBN, M_ / HBM), 256, GEMM_SMEM_BYTES>>>(xh, wqh, qp, M_, HID_, HID_);
    gemm_h<<<dim3(NKV / HBN, M_ / HBM), 256, GEMM_SMEM_BYTES>>>(xh, wkh, kp, M_, NKV, HID_);
    gemm_h<<<dim3(NKV / HBN, M_ / HBM), 256, GEMM_SMEM_BYTES>>>(xh, wvh, vp, M_, NKV, HID_);

    // RoPE -> fp16 (Q pre-scaled by 1/sqrt(D)*log2e for exp2 softmax); V transpose
    {
        const float qmul = 0.08838834764831845f * 1.4426950408889634f;
        int totq = B_ * S_ * H_ * (D_ / 2);
        rope_h_k<<<(totq + 255) / 256, 256>>>(qp, qh, H_, totq, qmul);
        int totk = B_ * S_ * HKV_ * (D_ / 2);
        rope_h_k<<<(totk + 255) / 256, 256>>>(kp, kh, HKV_, totk, 1.0f);
        vt_k<<<dim3(S_ / 32, D_ / 32, B_ * HKV_), 256>>>(vp, vth);
    }

    // Flash attention (fp16 FA2, 2 CTAs/SM) -> fp16 output
    flash_h<<<dim3(S_ / 128, H_, B_), 256, FLASH_SMEM_BYTES>>>(qh, kh, vth, oph);

    // Output projection
    gemm_h<<<dim3(HID_ / HBN, M_ / HBM), 256, GEMM_SMEM_BYTES>>>(oph, woh, out, M_, HID_, HID_);
}

// round 11
// speedup vs baseline: 10.4072x; 1.0208x over previous
#include <cuda_runtime.h>
#include <cuda_fp16.h>
#include <cuda_bf16.h>
#include <mma.h>
#include <math.h>
#include <float.h>
#include <stdint.h>

using namespace nvcuda;

// Problem constants
#define B_  2
#define S_  2048
#define HID_ 4096
#define H_  32
#define HKV_ 8
#define D_  128
#define M_  (B_ * S_)   // 4096 rows of x

// Scratch (device globals)
__device__ float g_q[(size_t)B_ * S_ * H_ * D_];
__device__ float g_k[(size_t)B_ * S_ * HKV_ * D_];
__device__ float g_v[(size_t)B_ * S_ * HKV_ * D_];
// fp16 operands
__device__ __half g_xh [(size_t)M_ * HID_];
__device__ __half g_wqh[(size_t)HID_ * HID_];
__device__ __half g_wkh[(size_t)HID_ * (HKV_ * D_)];
__device__ __half g_wvh[(size_t)HID_ * (HKV_ * D_)];
__device__ __half g_woh[(size_t)HID_ * HID_];
__device__ __half g_oph[(size_t)M_ * HID_];
__device__ __half g_qh [(size_t)B_ * S_ * H_ * D_];       // rope'd+scaled Q (log2e folded)
__device__ __half g_kh [(size_t)B_ * S_ * HKV_ * D_];     // rope'd K
__device__ __half g_vth[(size_t)B_ * HKV_ * D_ * S_];     // V transposed [b][kvh][d][s]

// ---------------------------------------------------------------------------
// helpers
// ---------------------------------------------------------------------------
__device__ __forceinline__ uint32_t smem_u32(const void* p) {
    uint32_t a;
    asm("{ .reg .u64 t; cvta.to.shared.u64 t, %1; cvt.u32.u64 %0, t; }"
        : "=r"(a) : "l"(p));
    return a;
}
#define CP_ASYNC16(dst_u32, src_ptr) \
    asm volatile("cp.async.cg.shared.global [%0], [%1], 16;" \
                 :: "r"(dst_u32), "l"(src_ptr) : "memory")
#define CP_COMMIT() asm volatile("cp.async.commit_group;" ::: "memory")
#define CP_WAIT1()  asm volatile("cp.async.wait_group 1;" ::: "memory")
#define CP_WAIT0()  asm volatile("cp.async.wait_group 0;" ::: "memory")

// fp16 m16n8k16 mma, fp32 accumulate
__device__ __forceinline__ void mma_f16(float d[4], uint32_t a0, uint32_t a1,
                                        uint32_t a2, uint32_t a3,
                                        uint32_t b0, uint32_t b1) {
    asm volatile(
        "mma.sync.aligned.m16n8k16.row.col.f32.f16.f16.f32 "
        "{%0,%1,%2,%3}, {%4,%5,%6,%7}, {%8,%9}, {%0,%1,%2,%3};"
        : "+f"(d[0]), "+f"(d[1]), "+f"(d[2]), "+f"(d[3])
        : "r"(a0), "r"(a1), "r"(a2), "r"(a3), "r"(b0), "r"(b1));
}
__device__ __forceinline__ uint32_t pack_h2(float x, float y) {
    __half2 h = __floats2half2_rn(x, y);
    return *reinterpret_cast<uint32_t*>(&h);
}
// ldmatrix: 4 x (8x8 b16) tiles, non-transposed
__device__ __forceinline__ void ldsm_x4(uint32_t& r0, uint32_t& r1,
                                        uint32_t& r2, uint32_t& r3,
                                        uint32_t addr) {
    asm volatile("ldmatrix.sync.aligned.m8n8.x4.shared.b16 {%0,%1,%2,%3}, [%4];"
                 : "=r"(r0), "=r"(r1), "=r"(r2), "=r"(r3) : "r"(addr));
}

// ---------------------------------------------------------------------------
// Elementwise fp32 -> fp16
// ---------------------------------------------------------------------------
__global__ void f2h_k(const float* __restrict__ in,
                      __half* __restrict__ out, int n4)
{
    int i = blockIdx.x * blockDim.x + threadIdx.x;
    if (i >= n4) return;
    float4 v = reinterpret_cast<const float4*>(in)[i];
    reinterpret_cast<__half2*>(out)[2 * i]     = __floats2half2_rn(v.x, v.y);
    reinterpret_cast<__half2*>(out)[2 * i + 1] = __floats2half2_rn(v.z, v.w);
}

// ---------------------------------------------------------------------------
// FP16 tensor-core GEMM (unchanged)
// ---------------------------------------------------------------------------
constexpr int HBM = 128, HBN = 256, HBK = 64;
constexpr int HLDA = HBK + 8;
constexpr int HLDB = HBN + 8;
constexpr int HA_HALVES = HBM * HLDA;
constexpr int HB_HALVES = HBK * HLDB;
constexpr int HSTAGE_HALVES = HA_HALVES + HB_HALVES;
constexpr int GEMM_SMEM_BYTES = 3 * HSTAGE_HALVES * 2;

__global__ __launch_bounds__(256, 1) void gemm_h(const __half* __restrict__ A,
                                                 const __half* __restrict__ Bm,
                                                 float* __restrict__ C,
                                                 int M, int N, int K)
{
    extern __shared__ __align__(128) __half hsm[];

    const int tid  = threadIdx.x;
    const int warp = tid >> 5;
    const int wr   = warp >> 2;
    const int wcc  = warp & 3;

    const size_t bm0 = (size_t)blockIdx.y * HBM;
    const size_t bn0 = (size_t)blockIdx.x * HBN;

    const int aRow = tid >> 1;
    const int aCB  = (tid & 1) << 2;
    const int bRow = tid >> 5;
    const int bCC  = tid & 31;

    const uint32_t smem_base = smem_u32(hsm);

    auto issue_stage = [&](int slot, int k0) {
        const uint32_t sa = smem_base + (uint32_t)(slot * HSTAGE_HALVES) * 2u;
        const uint32_t sb = sa + (uint32_t)HA_HALVES * 2u;
        #pragma unroll
        for (int j = 0; j < 4; ++j) {
            int c = aCB + j;
            const __half* src = A + (bm0 + aRow) * K + k0 + c * 8;
            CP_ASYNC16(sa + (uint32_t)(aRow * HLDA + c * 8) * 2u, src);
        }
        #pragma unroll
        for (int rr = 0; rr < 8; ++rr) {
            int row = bRow + rr * 8;
            const __half* src = Bm + (size_t)(k0 + row) * N + bn0 + bCC * 8;
            CP_ASYNC16(sb + (uint32_t)(row * HLDB + bCC * 8) * 2u, src);
        }
        CP_COMMIT();
    };

    wmma::fragment<wmma::accumulator, 16, 16, 16, float> acc[4][4];
    #pragma unroll
    for (int m = 0; m < 4; ++m)
        #pragma unroll
        for (int n = 0; n < 4; ++n)
            wmma::fill_fragment(acc[m][n], 0.0f);

    const int NIT = K / HBK;
    issue_stage(0, 0);
    issue_stage(1, HBK);

    for (int s = 0; s < NIT; ++s) {
        if (s == NIT - 1) { CP_WAIT0(); } else { CP_WAIT1(); }
        __syncthreads();

        if (s + 2 < NIT) issue_stage((s + 2) % 3, (s + 2) * HBK);

        const __half* As = hsm + (s % 3) * HSTAGE_HALVES;
        const __half* Bs = As + HA_HALVES;

        #pragma unroll
        for (int kk = 0; kk < HBK; kk += 16) {
            wmma::fragment<wmma::matrix_a, 16, 16, 16, __half,
                           wmma::row_major> af[4];
            #pragma unroll
            for (int m = 0; m < 4; ++m)
                wmma::load_matrix_sync(af[m],
                    &As[(wr * 64 + m * 16) * HLDA + kk], HLDA);
            #pragma unroll
            for (int n = 0; n < 4; ++n) {
                wmma::fragment<wmma::matrix_b, 16, 16, 16, __half,
                               wmma::row_major> bf;
                wmma::load_matrix_sync(bf,
                    &Bs[kk * HLDB + wcc * 64 + n * 16], HLDB);
                #pragma unroll
                for (int m = 0; m < 4; ++m)
                    wmma::mma_sync(acc[m][n], af[m], bf, acc[m][n]);
            }
        }
        __syncthreads();
    }

    #pragma unroll
    for (int m = 0; m < 4; ++m)
        #pragma unroll
        for (int n = 0; n < 4; ++n)
            wmma::store_matrix_sync(
                C + (bm0 + wr * 64 + m * 16) * N + bn0 + wcc * 64 + n * 16,
                acc[m][n], N, wmma::mem_row_major);
}

// ---------------------------------------------------------------------------
// RoPE: read fp32, write scaled fp16 to separate buffer.
// ---------------------------------------------------------------------------
__global__ void rope_h_k(const float* __restrict__ in, __half* __restrict__ out,
                         int nh, int total, float mul)
{
    int idx = blockIdx.x * blockDim.x + threadIdx.x;
    if (idx >= total) return;
    const int half = D_ / 2;
    int i = idx & (half - 1);
    int rest = idx >> 6;
    int h = rest % nh;
    rest /= nh;
    int s = rest % S_;
    int b = rest / S_;

    float inv = __expf(-logf(10000.0f) * (float)i / (float)half);
    float ang = (float)s * inv;
    float sn, cs;
    sincosf(ang, &sn, &cs);

    size_t base = ((size_t)((b * S_ + s) * nh + h)) * D_;
    float x1 = in[base + i];
    float x2 = in[base + i + half];
    out[base + i]        = __float2half_rn((x1 * cs - x2 * sn) * mul);
    out[base + i + half] = __float2half_rn((x2 * cs + x1 * sn) * mul);
}

// ---------------------------------------------------------------------------
// V transpose + fp16: [b][s][kvh][d] fp32 -> [b][kvh][d][s] fp16
// ---------------------------------------------------------------------------
__global__ __launch_bounds__(256) void vt_k(const float* __restrict__ in,
                                            __half* __restrict__ out)
{
    __shared__ __half t[32][34];
    const int tx = threadIdx.x & 31;
    const int ty = threadIdx.x >> 5;
    const int s0 = blockIdx.x * 32;
    const int d0 = blockIdx.y * 32;
    const int bk = blockIdx.z;
    const int b  = bk >> 3;
    const int kvh = bk & 7;

    #pragma unroll
    for (int j = 0; j < 32; j += 8) {
        float v = in[((size_t)((b * S_ + s0 + ty + j) * HKV_ + kvh)) * D_ + d0 + tx];
        t[ty + j][tx] = __float2half_rn(v);
    }
    __syncthreads();
    #pragma unroll
    for (int j = 0; j < 32; j += 8)
        out[((size_t)(bk * D_ + d0 + ty + j)) * S_ + s0 + tx] = t[tx][ty + j];
}

// ---------------------------------------------------------------------------
// Flash attention v7: fp16 m16n8k16 FA2, ALL operand loads via ldmatrix.x4.
// Q resident in SMEM; 2 CTAs/SM; exp2-domain softmax (scale folded into Q).
// Grid (S/128, H, B), 256 threads (8 warps x 16 Q rows).
// ---------------------------------------------------------------------------
constexpr int KST = 136;  // K/Q smem stride halves (272B rows -> conflict-free LDSM)
constexpr int VST = 72;   // Vt smem stride halves (144B rows -> conflict-free LDSM)
constexpr int QSM_HALVES = 128 * KST;                 // 17408
constexpr int KV_STG = 64 * KST + 128 * VST;          // 17920 halves
constexpr int FLASH_SMEM_BYTES = (QSM_HALVES + 2 * KV_STG) * 2;  // 106496 B

__global__ __launch_bounds__(256, 2) void flash_h(const __half* __restrict__ Qg,
                                                  const __half* __restrict__ Kg,
                                                  const __half* __restrict__ Vtg,
                                                  __half* __restrict__ Og)
{
    extern __shared__ __half smh[];
    const int tid  = threadIdx.x;
    const int warp = tid >> 5;
    const int lane = tid & 31;
    const int lr   = lane >> 2;
    const int lc   = lane & 3;
    const int g    = lane >> 3;   // ldmatrix address group 0..3
    const int li   = lane & 7;    // row within group
    const int qtile = gridDim.x - 1 - blockIdx.x;   // heavy first
    const int h    = blockIdx.y;
    const int b    = blockIdx.z;
    const int q0   = qtile * 128;
    const int kvh  = h >> 2;
    const uint32_t sbase = smem_u32(smh);

    // ---- stage Q (128 x 128 halves) into persistent smem region ----
    #pragma unroll
    for (int it = 0; it < 8; ++it) {
        int li2  = it * 256 + tid;
        int row = li2 >> 4;
        int c   = li2 & 15;
        const __half* src = Qg + ((size_t)((b * S_ + q0 + row) * H_ + h)) * D_ + c * 8;
        CP_ASYNC16(sbase + (uint32_t)(row * KST + c * 8) * 2u, src);
    }
    CP_COMMIT();

    float d[16][4];
    #pragma unroll
    for (int i = 0; i < 16; ++i)
        #pragma unroll
        for (int j = 0; j < 4; ++j) d[i][j] = 0.f;
    float m0 = -1e30f, m1 = -1e30f, l0 = 0.f, l1 = 0.f;

    auto issue_kv = [&](int t) {
        const int s = t & 1;
        const uint32_t kb = sbase + (uint32_t)(QSM_HALVES + s * KV_STG) * 2u;
        const uint32_t vb = kb + (uint32_t)(64 * KST) * 2u;
        const int kv0 = t * 64;
        #pragma unroll
        for (int it = 0; it < 4; ++it) {
            int li2  = it * 256 + tid;
            int row = li2 >> 4;
            int c   = li2 & 15;
            const __half* src = Kg + ((size_t)((b * S_ + kv0 + row) * HKV_ + kvh)) * D_ + c * 8;
            CP_ASYNC16(kb + (uint32_t)(row * KST + c * 8) * 2u, src);
        }
        #pragma unroll
        for (int it = 0; it < 4; ++it) {
            int li2  = it * 256 + tid;
            int row = li2 >> 3;
            int c   = li2 & 7;
            const __half* src = Vtg + ((size_t)((b * HKV_ + kvh) * D_ + row)) * S_ + kv0 + c * 8;
            CP_ASYNC16(vb + (uint32_t)(row * VST + c * 8) * 2u, src);
        }
        CP_COMMIT();
    };

    const int tmax = 2 * qtile + 1;
    const int wrow_lo = q0 + warp * 16;
    const int wrow_hi = wrow_lo + 15;
    // Q ldmatrix per-thread address: groups -> (a0: r0-8/k0, a1: r8-16/k0,
    //                                           a2: r0-8/k8, a3: r8-16/k8)
    const uint32_t qaddr = sbase +
        (uint32_t)(((warp * 16 + (g & 1) * 8 + li) * KST + (g >> 1) * 8) * 2);
    issue_kv(0);

    for (int t = 0; t <= tmax; ++t) {
        CP_WAIT0();
        __syncthreads();
        if (t < tmax) issue_kv(t + 1);

        const int kv0 = t * 64;
        if (kv0 <= wrow_hi) {
            const uint32_t kwb = sbase +
                (uint32_t)((QSM_HALVES + (t & 1) * KV_STG) * 2);
            // K ldmatrix: groups -> (b0 nf even, b1 nf even, b0 nf odd, b1 nf odd)
            const uint32_t kaddr = kwb +
                (uint32_t)((((g >> 1) * 8 + li) * KST + (g & 1) * 8) * 2);
            const uint32_t vaddr = kwb + (uint32_t)(64 * KST * 2) +
                (uint32_t)((((g >> 1) * 8 + li) * VST + (g & 1) * 8) * 2);

            // ---- QK^T: S[16x64] per warp ----
            float s[8][4];
            #pragma unroll
            for (int nf = 0; nf < 8; ++nf)
                #pragma unroll
                for (int e = 0; e < 4; ++e) s[nf][e] = 0.f;
            #pragma unroll
            for (int j = 0; j < 8; ++j) {
                uint32_t qa0, qa1, qa2, qa3;
                ldsm_x4(qa0, qa1, qa2, qa3, qaddr + j * 32);
                #pragma unroll
                for (int nfp = 0; nfp < 4; ++nfp) {
                    uint32_t kb0, kb1, kb2, kb3;
                    ldsm_x4(kb0, kb1, kb2, kb3,
                            kaddr + nfp * (16 * KST * 2) + j * 32);
                    mma_f16(s[2 * nfp],     qa0, qa1, qa2, qa3, kb0, kb1);
                    mma_f16(s[2 * nfp + 1], qa0, qa1, qa2, qa3, kb2, kb3);
                }
            }

            // ---- causal mask ----
            if (kv0 + 63 > wrow_lo) {
                const int row0 = wrow_lo + lr;
                #pragma unroll
                for (int nf = 0; nf < 8; ++nf) {
                    int c0 = kv0 + 8 * nf + 2 * lc;
                    if (c0 > row0)         s[nf][0] = -1e30f;
                    if (c0 + 1 > row0)     s[nf][1] = -1e30f;
                    if (c0 > row0 + 8)     s[nf][2] = -1e30f;
                    if (c0 + 1 > row0 + 8) s[nf][3] = -1e30f;
                }
            }

            // ---- online softmax (log2 domain) ----
            float mx0 = -1e30f, mx1 = -1e30f;
            #pragma unroll
            for (int nf = 0; nf < 8; ++nf) {
                mx0 = fmaxf(mx0, fmaxf(s[nf][0], s[nf][1]));
                mx1 = fmaxf(mx1, fmaxf(s[nf][2], s[nf][3]));
            }
            mx0 = fmaxf(mx0, __shfl_xor_sync(0xFFFFFFFFu, mx0, 1));
            mx0 = fmaxf(mx0, __shfl_xor_sync(0xFFFFFFFFu, mx0, 2));
            mx1 = fmaxf(mx1, __shfl_xor_sync(0xFFFFFFFFu, mx1, 1));
            mx1 = fmaxf(mx1, __shfl_xor_sync(0xFFFFFFFFu, mx1, 2));
            float m0n = fmaxf(m0, mx0), m1n = fmaxf(m1, mx1);
            float al0 = exp2f(m0 - m0n), al1 = exp2f(m1 - m1n);
            float su0 = 0.f, su1 = 0.f;
            #pragma unroll
            for (int nf = 0; nf < 8; ++nf) {
                s[nf][0] = exp2f(s[nf][0] - m0n);
                s[nf][1] = exp2f(s[nf][1] - m0n);
                s[nf][2] = exp2f(s[nf][2] - m1n);
                s[nf][3] = exp2f(s[nf][3] - m1n);
                su0 += s[nf][0] + s[nf][1];
                su1 += s[nf][2] + s[nf][3];
            }
            su0 += __shfl_xor_sync(0xFFFFFFFFu, su0, 1);
            su0 += __shfl_xor_sync(0xFFFFFFFFu, su0, 2);
            su1 += __shfl_xor_sync(0xFFFFFFFFu, su1, 1);
            su1 += __shfl_xor_sync(0xFFFFFFFFu, su1, 2);
            l0 = l0 * al0 + su0;  m0 = m0n;
            l1 = l1 * al1 + su1;  m1 = m1n;

            #pragma unroll
            for (int nf = 0; nf < 16; ++nf) {
                d[nf][0] *= al0; d[nf][1] *= al0;
                d[nf][2] *= al1; d[nf][3] *= al1;
            }

            // ---- PV: P A-frags from score C-frags; V B-frags via ldmatrix ----
            #pragma unroll
            for (int j = 0; j < 4; ++j) {
                uint32_t pa0 = pack_h2(s[2*j][0],   s[2*j][1]);
                uint32_t pa1 = pack_h2(s[2*j][2],   s[2*j][3]);
                uint32_t pa2 = pack_h2(s[2*j+1][0], s[2*j+1][1]);
                uint32_t pa3 = pack_h2(s[2*j+1][2], s[2*j+1][3]);
                #pragma unroll
                for (int nfp = 0; nfp < 8; ++nfp) {
                    uint32_t vb0, vb1, vb2, vb3;
                    ldsm_x4(vb0, vb1, vb2, vb3,
                            vaddr + nfp * (16 * VST * 2) + j * 32);
                    mma_f16(d[2 * nfp],     pa0, pa1, pa2, pa3, vb0, vb1);
                    mma_f16(d[2 * nfp + 1], pa0, pa1, pa2, pa3, vb2, vb3);
                }
            }
        }
    }

    // ---- finalize: write fp16 output ----
    const float il0 = 1.f / l0, il1 = 1.f / l1;
    const int row0 = q0 + warp * 16 + lr;
    __half* o0 = Og + ((size_t)((b * S_ + row0) * H_ + h)) * D_;
    __half* o1 = Og + ((size_t)((b * S_ + row0 + 8) * H_ + h)) * D_;
    #pragma unroll
    for (int nf = 0; nf < 16; ++nf) {
        *reinterpret_cast<uint32_t*>(o0 + 8 * nf + 2 * lc) =
            pack_h2(d[nf][0] * il0, d[nf][1] * il0);
        *reinterpret_cast<uint32_t*>(o1 + 8 * nf + 2 * lc) =
            pack_h2(d[nf][2] * il1, d[nf][3] * il1);
    }
}

// ---------------------------------------------------------------------------
// Launcher
// ---------------------------------------------------------------------------
extern "C" void kernel_launch(void* const* d_in, const int* in_sizes, int n_in,
                              void* d_out, int out_size)
{
    const float* x  = (const float*)d_in[0];
    const float* wq = (const float*)d_in[1];
    const float* wk = (const float*)d_in[2];
    const float* wv = (const float*)d_in[3];
    const float* wo = (const float*)d_in[4];
    float* out = (float*)d_out;

    float *qp, *kp, *vp;
    __half *xh, *wqh, *wkh, *wvh, *woh, *oph, *qh, *kh, *vth;
    cudaGetSymbolAddress((void**)&qp, g_q);
    cudaGetSymbolAddress((void**)&kp, g_k);
    cudaGetSymbolAddress((void**)&vp, g_v);
    cudaGetSymbolAddress((void**)&xh, g_xh);
    cudaGetSymbolAddress((void**)&wqh, g_wqh);
    cudaGetSymbolAddress((void**)&wkh, g_wkh);
    cudaGetSymbolAddress((void**)&wvh, g_wvh);
    cudaGetSymbolAddress((void**)&woh, g_woh);
    cudaGetSymbolAddress((void**)&oph, g_oph);
    cudaGetSymbolAddress((void**)&qh, g_qh);
    cudaGetSymbolAddress((void**)&kh, g_kh);
    cudaGetSymbolAddress((void**)&vth, g_vth);

    cudaFuncSetAttribute(gemm_h, cudaFuncAttributeMaxDynamicSharedMemorySize,
                         GEMM_SMEM_BYTES);
    cudaFuncSetAttribute(flash_h, cudaFuncAttributeMaxDynamicSharedMemorySize,
                         FLASH_SMEM_BYTES);

    const int NKV = HKV_ * D_;   // 1024

    // Convert inputs to fp16
    {
        int n4;
        n4 = (M_ * HID_) / 4;
        f2h_k<<<(n4 + 255) / 256, 256>>>(x, xh, n4);
        n4 = (HID_ * HID_) / 4;
        f2h_k<<<(n4 + 255) / 256, 256>>>(wq, wqh, n4);
        f2h_k<<<(n4 + 255) / 256, 256>>>(wo, woh, n4);
        n4 = (HID_ * NKV) / 4;
        f2h_k<<<(n4 + 255) / 256, 256>>>(wk, wkh, n4);
        f2h_k<<<(n4 + 255) / 256, 256>>>(wv, wvh, n4);
    }

    // QKV projections (fp16 tensor cores, fp32 out)
    gemm_h<<<dim3(HID_ / HBN, M_ / HBM), 256, GEMM_SMEM_BYTES>>>(xh, wqh, qp, M_, HID_, HID_);
    gemm_h<<<dim3(NKV / HBN, M_ / HBM), 256, GEMM_SMEM_BYTES>>>(xh, wkh, kp, M_, NKV, HID_);
    gemm_h<<<dim3(NKV / HBN, M_ / HBM), 256, GEMM_SMEM_BYTES>>>(xh, wvh, vp, M_, NKV, HID_);

    // RoPE -> fp16 (Q pre-scaled by 1/sqrt(D)*log2e for exp2 softmax); V transpose
    {
        const float qmul = 0.08838834764831845f * 1.4426950408889634f;
        int totq = B_ * S_ * H_ * (D_ / 2);
        rope_h_k<<<(totq + 255) / 256, 256>>>(qp, qh, H_, totq, qmul);
        int totk = B_ * S_ * HKV_ * (D_ / 2);
        rope_h_k<<<(totk + 255) / 256, 256>>>(kp, kh, HKV_, totk, 1.0f);
        vt_k<<<dim3(S_ / 32, D_ / 32, B_ * HKV_), 256>>>(vp, vth);
    }

    // Flash attention (fp16 FA2 + ldmatrix) -> fp16 output
    flash_h<<<dim3(S_ / 128, H_, B_), 256, FLASH_SMEM_BYTES>>>(qh, kh, vth, oph);

    // Output projection
    gemm_h<<<dim3(HID_ / HBN, M_ / HBM), 256, GEMM_SMEM_BYTES>>>(oph, woh, out, M_, HID_, HID_);
}

// round 12
// speedup vs baseline: 11.9920x; 1.1523x over previous
#include <cuda_runtime.h>
#include <cuda_fp16.h>
#include <cuda_bf16.h>
#include <mma.h>
#include <math.h>
#include <float.h>
#include <stdint.h>

using namespace nvcuda;

// Problem constants
#define B_  2
#define S_  2048
#define HID_ 4096
#define H_  32
#define HKV_ 8
#define D_  128
#define M_  (B_ * S_)   // 4096 rows of x

// Scratch (device globals)
__device__ float g_q[(size_t)B_ * S_ * H_ * D_];
__device__ float g_k[(size_t)B_ * S_ * HKV_ * D_];
__device__ float g_v[(size_t)B_ * S_ * HKV_ * D_];
// fp16 operands (weights stored TRANSPOSED [N][K])
__device__ __half g_xh [(size_t)M_ * HID_];
__device__ __half g_wqh[(size_t)HID_ * HID_];
__device__ __half g_wkh[(size_t)HID_ * (HKV_ * D_)];
__device__ __half g_wvh[(size_t)HID_ * (HKV_ * D_)];
__device__ __half g_woh[(size_t)HID_ * HID_];
__device__ __half g_oph[(size_t)M_ * HID_];
__device__ __half g_qh [(size_t)B_ * S_ * H_ * D_];
__device__ __half g_kh [(size_t)B_ * S_ * HKV_ * D_];
__device__ __half g_vth[(size_t)B_ * HKV_ * D_ * S_];

// ---------------------------------------------------------------------------
// helpers
// ---------------------------------------------------------------------------
__device__ __forceinline__ uint32_t smem_u32(const void* p) {
    uint32_t a;
    asm("{ .reg .u64 t; cvta.to.shared.u64 t, %1; cvt.u32.u64 %0, t; }"
        : "=r"(a) : "l"(p));
    return a;
}
#define CP_ASYNC16(dst_u32, src_ptr) \
    asm volatile("cp.async.cg.shared.global [%0], [%1], 16;" \
                 :: "r"(dst_u32), "l"(src_ptr) : "memory")
#define CP_COMMIT() asm volatile("cp.async.commit_group;" ::: "memory")
#define CP_WAIT1()  asm volatile("cp.async.wait_group 1;" ::: "memory")
#define CP_WAIT0()  asm volatile("cp.async.wait_group 0;" ::: "memory")

__device__ __forceinline__ void mma_f16(float d[4], uint32_t a0, uint32_t a1,
                                        uint32_t a2, uint32_t a3,
                                        uint32_t b0, uint32_t b1) {
    asm volatile(
        "mma.sync.aligned.m16n8k16.row.col.f32.f16.f16.f32 "
        "{%0,%1,%2,%3}, {%4,%5,%6,%7}, {%8,%9}, {%0,%1,%2,%3};"
        : "+f"(d[0]), "+f"(d[1]), "+f"(d[2]), "+f"(d[3])
        : "r"(a0), "r"(a1), "r"(a2), "r"(a3), "r"(b0), "r"(b1));
}
__device__ __forceinline__ uint32_t pack_h2(float x, float y) {
    __half2 h = __floats2half2_rn(x, y);
    return *reinterpret_cast<uint32_t*>(&h);
}
__device__ __forceinline__ void ldsm_x4(uint32_t& r0, uint32_t& r1,
                                        uint32_t& r2, uint32_t& r3,
                                        uint32_t addr) {
    asm volatile("ldmatrix.sync.aligned.m8n8.x4.shared.b16 {%0,%1,%2,%3}, [%4];"
                 : "=r"(r0), "=r"(r1), "=r"(r2), "=r"(r3) : "r"(addr));
}

// ---------------------------------------------------------------------------
// Conversions
// ---------------------------------------------------------------------------
__global__ void f2h_k(const float* __restrict__ in,
                      __half* __restrict__ out, int n4)
{
    int i = blockIdx.x * blockDim.x + threadIdx.x;
    if (i >= n4) return;
    float4 v = reinterpret_cast<const float4*>(in)[i];
    reinterpret_cast<__half2*>(out)[2 * i]     = __floats2half2_rn(v.x, v.y);
    reinterpret_cast<__half2*>(out)[2 * i + 1] = __floats2half2_rn(v.z, v.w);
}

// Transpose + convert: in fp32 [R][C] -> out fp16 [C][R]
__global__ __launch_bounds__(256) void f2hT_k(const float* __restrict__ in,
                                              __half* __restrict__ out,
                                              int R, int C)
{
    __shared__ float t[32][33];
    const int tx = threadIdx.x & 31;
    const int ty = threadIdx.x >> 5;
    const int c0 = blockIdx.x * 32;
    const int r0 = blockIdx.y * 32;
    #pragma unroll
    for (int j = 0; j < 32; j += 8)
        t[ty + j][tx] = in[(size_t)(r0 + ty + j) * C + c0 + tx];
    __syncthreads();
    #pragma unroll
    for (int j = 0; j < 32; j += 8)
        out[(size_t)(c0 + ty + j) * R + r0 + tx] = __float2half_rn(t[tx][ty + j]);
}

// ---------------------------------------------------------------------------
// FP16 GEMM v2: C[M,N](fp32) = A[M,K](fp16, row-major) @ BT[N,K](fp16)^T.
// Raw mma.m16n8k16 + ldmatrix.x4, 144B-stride conflict-free smem.
// 128x256 block, BK=64, 256 threads (8 warps 2x4), warp tile 64x64.
// 3-stage cp.async, wait_group 1.
// ---------------------------------------------------------------------------
constexpr int G2ST = 72;                        // smem stride (halves) for A and B
constexpr int G2A_H = 128 * G2ST;               // 9216
constexpr int G2B_H = 256 * G2ST;               // 18432
constexpr int G2STG_H = G2A_H + G2B_H;          // 27648 halves / stage
constexpr int GEMM_SMEM_BYTES = 3 * G2STG_H * 2; // 165888 B

__global__ __launch_bounds__(256, 1) void gemm_h2(const __half* __restrict__ A,
                                                  const __half* __restrict__ BT,
                                                  float* __restrict__ C,
                                                  int M, int N, int K)
{
    extern __shared__ __half hsm[];
    const int tid  = threadIdx.x;
    const int warp = tid >> 5;
    const int lane = tid & 31;
    const int lr   = lane >> 2;
    const int lc   = lane & 3;
    const int g    = lane >> 3;
    const int li   = lane & 7;
    const int wr   = warp >> 2;       // 0..1: 64-row strip
    const int wcc  = warp & 3;        // 0..3: 64-col strip

    const size_t bm0 = (size_t)blockIdx.y * 128;
    const size_t bn0 = (size_t)blockIdx.x * 256;
    const uint32_t sbase = smem_u32(hsm);

    auto issue_stage = [&](int slot, int k0) {
        const uint32_t sa = sbase + (uint32_t)(slot * G2STG_H) * 2u;
        const uint32_t sb = sa + (uint32_t)G2A_H * 2u;
        // A: 128 rows x 8 chunks (64 halves) = 1024 chunks, 4/thread
        #pragma unroll
        for (int j = 0; j < 4; ++j) {
            int li2 = j * 256 + tid;
            int row = li2 >> 3;
            int c   = li2 & 7;
            const __half* src = A + (bm0 + row) * K + k0 + c * 8;
            CP_ASYNC16(sa + (uint32_t)(row * G2ST + c * 8) * 2u, src);
        }
        // B: 256 rows (n) x 8 chunks = 2048 chunks, 8/thread
        #pragma unroll
        for (int j = 0; j < 8; ++j) {
            int li2 = j * 256 + tid;
            int row = li2 >> 3;
            int c   = li2 & 7;
            const __half* src = BT + (bn0 + row) * K + k0 + c * 8;
            CP_ASYNC16(sb + (uint32_t)(row * G2ST + c * 8) * 2u, src);
        }
        CP_COMMIT();
    };

    float acc[4][8][4];
    #pragma unroll
    for (int mi = 0; mi < 4; ++mi)
        #pragma unroll
        for (int nf = 0; nf < 8; ++nf)
            #pragma unroll
            for (int e = 0; e < 4; ++e) acc[mi][nf][e] = 0.f;

    const int NIT = K >> 6;
    issue_stage(0, 0);
    issue_stage(1, 64);

    // ldmatrix per-thread base offsets (within a stage)
    // A (m16k16 frags): rows (g&1)*8+li, col (g>>1)*8  -> a0..a3
    const uint32_t aoff = (uint32_t)((((g & 1) * 8 + li) * G2ST + (g >> 1) * 8) * 2);
    // B (k16n8 frag pairs): rows (g>>1)*8+li, col (g&1)*8 -> (r0,r1),(r2,r3)
    const uint32_t boff = (uint32_t)((((g >> 1) * 8 + li) * G2ST + (g & 1) * 8) * 2);

    for (int s = 0; s < NIT; ++s) {
        if (s >= NIT - 2) { CP_WAIT0(); } else { CP_WAIT1(); }
        __syncthreads();
        if (s + 2 < NIT) issue_stage((s + 2) % 3, (s + 2) * 64);

        const uint32_t abase = sbase + (uint32_t)((s % 3) * G2STG_H) * 2u +
                               (uint32_t)(wr * 64 * G2ST) * 2u + aoff;
        const uint32_t bbase = sbase + (uint32_t)((s % 3) * G2STG_H + G2A_H) * 2u +
                               (uint32_t)(wcc * 64 * G2ST) * 2u + boff;

        #pragma unroll
        for (int ks = 0; ks < 4; ++ks) {
            uint32_t af[4][4];
            #pragma unroll
            for (int mi = 0; mi < 4; ++mi)
                ldsm_x4(af[mi][0], af[mi][1], af[mi][2], af[mi][3],
                        abase + (uint32_t)(mi * 16 * G2ST + ks * 16) * 2u);
            #pragma unroll
            for (int p = 0; p < 4; ++p) {
                uint32_t b0, b1, b2, b3;
                ldsm_x4(b0, b1, b2, b3,
                        bbase + (uint32_t)(p * 16 * G2ST + ks * 16) * 2u);
                #pragma unroll
                for (int mi = 0; mi < 4; ++mi) {
                    mma_f16(acc[mi][2 * p],     af[mi][0], af[mi][1],
                            af[mi][2], af[mi][3], b0, b1);
                    mma_f16(acc[mi][2 * p + 1], af[mi][0], af[mi][1],
                            af[mi][2], af[mi][3], b2, b3);
                }
            }
        }
        __syncthreads();
    }

    // Epilogue: direct STG of accumulators
    #pragma unroll
    for (int mi = 0; mi < 4; ++mi) {
        const size_t r0 = bm0 + wr * 64 + mi * 16 + lr;
        #pragma unroll
        for (int nf = 0; nf < 8; ++nf) {
            const size_t col = bn0 + wcc * 64 + nf * 8 + 2 * lc;
            *reinterpret_cast<float2*>(C + r0 * N + col) =
                make_float2(acc[mi][nf][0], acc[mi][nf][1]);
            *reinterpret_cast<float2*>(C + (r0 + 8) * N + col) =
                make_float2(acc[mi][nf][2], acc[mi][nf][3]);
        }
    }
}

// ---------------------------------------------------------------------------
// RoPE: read fp32, write scaled fp16.
// ---------------------------------------------------------------------------
__global__ void rope_h_k(const float* __restrict__ in, __half* __restrict__ out,
                         int nh, int total, float mul)
{
    int idx = blockIdx.x * blockDim.x + threadIdx.x;
    if (idx >= total) return;
    const int half = D_ / 2;
    int i = idx & (half - 1);
    int rest = idx >> 6;
    int h = rest % nh;
    rest /= nh;
    int s = rest % S_;
    int b = rest / S_;

    float inv = __expf(-logf(10000.0f) * (float)i / (float)half);
    float ang = (float)s * inv;
    float sn, cs;
    sincosf(ang, &sn, &cs);

    size_t base = ((size_t)((b * S_ + s) * nh + h)) * D_;
    float x1 = in[base + i];
    float x2 = in[base + i + half];
    out[base + i]        = __float2half_rn((x1 * cs - x2 * sn) * mul);
    out[base + i + half] = __float2half_rn((x2 * cs + x1 * sn) * mul);
}

// ---------------------------------------------------------------------------
// V transpose + fp16: [b][s][kvh][d] fp32 -> [b][kvh][d][s] fp16
// ---------------------------------------------------------------------------
__global__ __launch_bounds__(256) void vt_k(const float* __restrict__ in,
                                            __half* __restrict__ out)
{
    __shared__ __half t[32][34];
    const int tx = threadIdx.x & 31;
    const int ty = threadIdx.x >> 5;
    const int s0 = blockIdx.x * 32;
    const int d0 = blockIdx.y * 32;
    const int bk = blockIdx.z;
    const int b  = bk >> 3;
    const int kvh = bk & 7;

    #pragma unroll
    for (int j = 0; j < 32; j += 8) {
        float v = in[((size_t)((b * S_ + s0 + ty + j) * HKV_ + kvh)) * D_ + d0 + tx];
        t[ty + j][tx] = __float2half_rn(v);
    }
    __syncthreads();
    #pragma unroll
    for (int j = 0; j < 32; j += 8)
        out[((size_t)(bk * D_ + d0 + ty + j)) * S_ + s0 + tx] = t[tx][ty + j];
}

// ---------------------------------------------------------------------------
// Flash attention v7 (unchanged from R11): fp16 mma + ldmatrix, FA2.
// ---------------------------------------------------------------------------
constexpr int KST = 136;
constexpr int VST = 72;
constexpr int QSM_HALVES = 128 * KST;
constexpr int KV_STG = 64 * KST + 128 * VST;
constexpr int FLASH_SMEM_BYTES = (QSM_HALVES + 2 * KV_STG) * 2;

__global__ __launch_bounds__(256, 2) void flash_h(const __half* __restrict__ Qg,
                                                  const __half* __restrict__ Kg,
                                                  const __half* __restrict__ Vtg,
                                                  __half* __restrict__ Og)
{
    extern __shared__ __half smh[];
    const int tid  = threadIdx.x;
    const int warp = tid >> 5;
    const int lane = tid & 31;
    const int lr   = lane >> 2;
    const int lc   = lane & 3;
    const int g    = lane >> 3;
    const int li   = lane & 7;
    const int qtile = gridDim.x - 1 - blockIdx.x;
    const int h    = blockIdx.y;
    const int b    = blockIdx.z;
    const int q0   = qtile * 128;
    const int kvh  = h >> 2;
    const uint32_t sbase = smem_u32(smh);

    #pragma unroll
    for (int it = 0; it < 8; ++it) {
        int li2  = it * 256 + tid;
        int row = li2 >> 4;
        int c   = li2 & 15;
        const __half* src = Qg + ((size_t)((b * S_ + q0 + row) * H_ + h)) * D_ + c * 8;
        CP_ASYNC16(sbase + (uint32_t)(row * KST + c * 8) * 2u, src);
    }
    CP_COMMIT();

    float d[16][4];
    #pragma unroll
    for (int i = 0; i < 16; ++i)
        #pragma unroll
        for (int j = 0; j < 4; ++j) d[i][j] = 0.f;
    float m0 = -1e30f, m1 = -1e30f, l0 = 0.f, l1 = 0.f;

    auto issue_kv = [&](int t) {
        const int s = t & 1;
        const uint32_t kb = sbase + (uint32_t)(QSM_HALVES + s * KV_STG) * 2u;
        const uint32_t vb = kb + (uint32_t)(64 * KST) * 2u;
        const int kv0 = t * 64;
        #pragma unroll
        for (int it = 0; it < 4; ++it) {
            int li2  = it * 256 + tid;
            int row = li2 >> 4;
            int c   = li2 & 15;
            const __half* src = Kg + ((size_t)((b * S_ + kv0 + row) * HKV_ + kvh)) * D_ + c * 8;
            CP_ASYNC16(kb + (uint32_t)(row * KST + c * 8) * 2u, src);
        }
        #pragma unroll
        for (int it = 0; it < 4; ++it) {
            int li2  = it * 256 + tid;
            int row = li2 >> 3;
            int c   = li2 & 7;
            const __half* src = Vtg + ((size_t)((b * HKV_ + kvh) * D_ + row)) * S_ + kv0 + c * 8;
            CP_ASYNC16(vb + (uint32_t)(row * VST + c * 8) * 2u, src);
        }
        CP_COMMIT();
    };

    const int tmax = 2 * qtile + 1;
    const int wrow_lo = q0 + warp * 16;
    const int wrow_hi = wrow_lo + 15;
    const uint32_t qaddr = sbase +
        (uint32_t)(((warp * 16 + (g & 1) * 8 + li) * KST + (g >> 1) * 8) * 2);
    issue_kv(0);

    for (int t = 0; t <= tmax; ++t) {
        CP_WAIT0();
        __syncthreads();
        if (t < tmax) issue_kv(t + 1);

        const int kv0 = t * 64;
        if (kv0 <= wrow_hi) {
            const uint32_t kwb = sbase +
                (uint32_t)((QSM_HALVES + (t & 1) * KV_STG) * 2);
            const uint32_t kaddr = kwb +
                (uint32_t)((((g >> 1) * 8 + li) * KST + (g & 1) * 8) * 2);
            const uint32_t vaddr = kwb + (uint32_t)(64 * KST * 2) +
                (uint32_t)((((g >> 1) * 8 + li) * VST + (g & 1) * 8) * 2);

            float s[8][4];
            #pragma unroll
            for (int nf = 0; nf < 8; ++nf)
                #pragma unroll
                for (int e = 0; e < 4; ++e) s[nf][e] = 0.f;
            #pragma unroll
            for (int j = 0; j < 8; ++j) {
                uint32_t qa0, qa1, qa2, qa3;
                ldsm_x4(qa0, qa1, qa2, qa3, qaddr + j * 32);
                #pragma unroll
                for (int nfp = 0; nfp < 4; ++nfp) {
                    uint32_t kb0, kb1, kb2, kb3;
                    ldsm_x4(kb0, kb1, kb2, kb3,
                            kaddr + nfp * (16 * KST * 2) + j * 32);
                    mma_f16(s[2 * nfp],     qa0, qa1, qa2, qa3, kb0, kb1);
                    mma_f16(s[2 * nfp + 1], qa0, qa1, qa2, qa3, kb2, kb3);
                }
            }

            if (kv0 + 63 > wrow_lo) {
                const int row0 = wrow_lo + lr;
                #pragma unroll
                for (int nf = 0; nf < 8; ++nf) {
                    int c0 = kv0 + 8 * nf + 2 * lc;
                    if (c0 > row0)         s[nf][0] = -1e30f;
                    if (c0 + 1 > row0)     s[nf][1] = -1e30f;
                    if (c0 > row0 + 8)     s[nf][2] = -1e30f;
                    if (c0 + 1 > row0 + 8) s[nf][3] = -1e30f;
                }
            }

            float mx0 = -1e30f, mx1 = -1e30f;
            #pragma unroll
            for (int nf = 0; nf < 8; ++nf) {
                mx0 = fmaxf(mx0, fmaxf(s[nf][0], s[nf][1]));
                mx1 = fmaxf(mx1, fmaxf(s[nf][2], s[nf][3]));
            }
            mx0 = fmaxf(mx0, __shfl_xor_sync(0xFFFFFFFFu, mx0, 1));
            mx0 = fmaxf(mx0, __shfl_xor_sync(0xFFFFFFFFu, mx0, 2));
            mx1 = fmaxf(mx1, __shfl_xor_sync(0xFFFFFFFFu, mx1, 1));
            mx1 = fmaxf(mx1, __shfl_xor_sync(0xFFFFFFFFu, mx1, 2));
            float m0n = fmaxf(m0, mx0), m1n = fmaxf(m1, mx1);
            float al0 = exp2f(m0 - m0n), al1 = exp2f(m1 - m1n);
            float su0 = 0.f, su1 = 0.f;
            #pragma unroll
            for (int nf = 0; nf < 8; ++nf) {
                s[nf][0] = exp2f(s[nf][0] - m0n);
                s[nf][1] = exp2f(s[nf][1] - m0n);
                s[nf][2] = exp2f(s[nf][2] - m1n);
                s[nf][3] = exp2f(s[nf][3] - m1n);
                su0 += s[nf][0] + s[nf][1];
                su1 += s[nf][2] + s[nf][3];
            }
            su0 += __shfl_xor_sync(0xFFFFFFFFu, su0, 1);
            su0 += __shfl_xor_sync(0xFFFFFFFFu, su0, 2);
            su1 += __shfl_xor_sync(0xFFFFFFFFu, su1, 1);
            su1 += __shfl_xor_sync(0xFFFFFFFFu, su1, 2);
            l0 = l0 * al0 + su0;  m0 = m0n;
            l1 = l1 * al1 + su1;  m1 = m1n;

            #pragma unroll
            for (int nf = 0; nf < 16; ++nf) {
                d[nf][0] *= al0; d[nf][1] *= al0;
                d[nf][2] *= al1; d[nf][3] *= al1;
            }

            #pragma unroll
            for (int j = 0; j < 4; ++j) {
                uint32_t pa0 = pack_h2(s[2*j][0],   s[2*j][1]);
                uint32_t pa1 = pack_h2(s[2*j][2],   s[2*j][3]);
                uint32_t pa2 = pack_h2(s[2*j+1][0], s[2*j+1][1]);
                uint32_t pa3 = pack_h2(s[2*j+1][2], s[2*j+1][3]);
                #pragma unroll
                for (int nfp = 0; nfp < 8; ++nfp) {
                    uint32_t vb0, vb1, vb2, vb3;
                    ldsm_x4(vb0, vb1, vb2, vb3,
                            vaddr + nfp * (16 * VST * 2) + j * 32);
                    mma_f16(d[2 * nfp],     pa0, pa1, pa2, pa3, vb0, vb1);
                    mma_f16(d[2 * nfp + 1], pa0, pa1, pa2, pa3, vb2, vb3);
                }
            }
        }
    }

    const float il0 = 1.f / l0, il1 = 1.f / l1;
    const int row0 = q0 + warp * 16 + lr;
    __half* o0 = Og + ((size_t)((b * S_ + row0) * H_ + h)) * D_;
    __half* o1 = Og + ((size_t)((b * S_ + row0 + 8) * H_ + h)) * D_;
    #pragma unroll
    for (int nf = 0; nf < 16; ++nf) {
        *reinterpret_cast<uint32_t*>(o0 + 8 * nf + 2 * lc) =
            pack_h2(d[nf][0] * il0, d[nf][1] * il0);
        *reinterpret_cast<uint32_t*>(o1 + 8 * nf + 2 * lc) =
            pack_h2(d[nf][2] * il1, d[nf][3] * il1);
    }
}

// ---------------------------------------------------------------------------
// Launcher
// ---------------------------------------------------------------------------
extern "C" void kernel_launch(void* const* d_in, const int* in_sizes, int n_in,
                              void* d_out, int out_size)
{
    const float* x  = (const float*)d_in[0];
    const float* wq = (const float*)d_in[1];
    const float* wk = (const float*)d_in[2];
    const float* wv = (const float*)d_in[3];
    const float* wo = (const float*)d_in[4];
    float* out = (float*)d_out;

    float *qp, *kp, *vp;
    __half *xh, *wqh, *wkh, *wvh, *woh, *oph, *qh, *kh, *vth;
    cudaGetSymbolAddress((void**)&qp, g_q);
    cudaGetSymbolAddress((void**)&kp, g_k);
    cudaGetSymbolAddress((void**)&vp, g_v);
    cudaGetSymbolAddress((void**)&xh, g_xh);
    cudaGetSymbolAddress((void**)&wqh, g_wqh);
    cudaGetSymbolAddress((void**)&wkh, g_wkh);
    cudaGetSymbolAddress((void**)&wvh, g_wvh);
    cudaGetSymbolAddress((void**)&woh, g_woh);
    cudaGetSymbolAddress((void**)&oph, g_oph);
    cudaGetSymbolAddress((void**)&qh, g_qh);
    cudaGetSymbolAddress((void**)&kh, g_kh);
    cudaGetSymbolAddress((void**)&vth, g_vth);

    cudaFuncSetAttribute(gemm_h2, cudaFuncAttributeMaxDynamicSharedMemorySize,
                         GEMM_SMEM_BYTES);
    cudaFuncSetAttribute(flash_h, cudaFuncAttributeMaxDynamicSharedMemorySize,
                         FLASH_SMEM_BYTES);

    const int NKV = HKV_ * D_;   // 1024

    // Convert inputs: x -> fp16 row-major; weights -> fp16 TRANSPOSED [N][K]
    {
        int n4 = (M_ * HID_) / 4;
        f2h_k<<<(n4 + 255) / 256, 256>>>(x, xh, n4);
        f2hT_k<<<dim3(HID_ / 32, HID_ / 32), 256>>>(wq, wqh, HID_, HID_);
        f2hT_k<<<dim3(HID_ / 32, HID_ / 32), 256>>>(wo, woh, HID_, HID_);
        f2hT_k<<<dim3(NKV / 32, HID_ / 32), 256>>>(wk, wkh, HID_, NKV);
        f2hT_k<<<dim3(NKV / 32, HID_ / 32), 256>>>(wv, wvh, HID_, NKV);
    }

    // QKV projections (raw-mma fp16 GEMM, fp32 out)
    gemm_h2<<<dim3(HID_ / 256, M_ / 128), 256, GEMM_SMEM_BYTES>>>(xh, wqh, qp, M_, HID_, HID_);
    gemm_h2<<<dim3(NKV / 256, M_ / 128), 256, GEMM_SMEM_BYTES>>>(xh, wkh, kp, M_, NKV, HID_);
    gemm_h2<<<dim3(NKV / 256, M_ / 128), 256, GEMM_SMEM_BYTES>>>(xh, wvh, vp, M_, NKV, HID_);

    // RoPE -> fp16 (Q pre-scaled by 1/sqrt(D)*log2e); V transpose
    {
        const float qmul = 0.08838834764831845f * 1.4426950408889634f;
        int totq = B_ * S_ * H_ * (D_ / 2);
        rope_h_k<<<(totq + 255) / 256, 256>>>(qp, qh, H_, totq, qmul);
        int totk = B_ * S_ * HKV_ * (D_ / 2);
        rope_h_k<<<(totk + 255) / 256, 256>>>(kp, kh, HKV_, totk, 1.0f);
        vt_k<<<dim3(S_ / 32, D_ / 32, B_ * HKV_), 256>>>(vp, vth);
    }

    // Flash attention -> fp16 output
    flash_h<<<dim3(S_ / 128, H_, B_), 256, FLASH_SMEM_BYTES>>>(qh, kh, vth, oph);

    // Output projection
    gemm_h2<<<dim3(HID_ / 256, M_ / 128), 256, GEMM_SMEM_BYTES>>>(oph, woh, out, M_, HID_, HID_);
}

// round 13
// speedup vs baseline: 12.0565x; 1.0054x over previous
#include <cuda_runtime.h>
#include <cuda_fp16.h>
#include <cuda_bf16.h>
#include <mma.h>
#include <math.h>
#include <float.h>
#include <stdint.h>

using namespace nvcuda;

// Problem constants
#define B_  2
#define S_  2048
#define HID_ 4096
#define H_  32
#define HKV_ 8
#define D_  128
#define M_  (B_ * S_)   // 4096 rows of x

// Scratch (device globals)
__device__ float g_q[(size_t)B_ * S_ * H_ * D_];
__device__ float g_k[(size_t)B_ * S_ * HKV_ * D_];
// fp16 operands (weights stored TRANSPOSED [N][K])
__device__ __half g_xh [(size_t)M_ * HID_];
__device__ __half g_wqh[(size_t)HID_ * HID_];
__device__ __half g_wkh[(size_t)HID_ * (HKV_ * D_)];
__device__ __half g_wvh[(size_t)HID_ * (HKV_ * D_)];
__device__ __half g_woh[(size_t)HID_ * HID_];
__device__ __half g_oph[(size_t)M_ * HID_];   // first: V fp16; later: attn out fp16
__device__ __half g_qh [(size_t)B_ * S_ * H_ * D_];
__device__ __half g_kh [(size_t)B_ * S_ * HKV_ * D_];
__device__ __half g_vth[(size_t)B_ * HKV_ * D_ * S_];

// ---------------------------------------------------------------------------
// helpers
// ---------------------------------------------------------------------------
__device__ __forceinline__ uint32_t smem_u32(const void* p) {
    uint32_t a;
    asm("{ .reg .u64 t; cvta.to.shared.u64 t, %1; cvt.u32.u64 %0, t; }"
        : "=r"(a) : "l"(p));
    return a;
}
#define CP_ASYNC16(dst_u32, src_ptr) \
    asm volatile("cp.async.cg.shared.global [%0], [%1], 16;" \
                 :: "r"(dst_u32), "l"(src_ptr) : "memory")
#define CP_COMMIT() asm volatile("cp.async.commit_group;" ::: "memory")
#define CP_WAIT1()  asm volatile("cp.async.wait_group 1;" ::: "memory")
#define CP_WAIT0()  asm volatile("cp.async.wait_group 0;" ::: "memory")

__device__ __forceinline__ void mma_f16(float d[4], uint32_t a0, uint32_t a1,
                                        uint32_t a2, uint32_t a3,
                                        uint32_t b0, uint32_t b1) {
    asm volatile(
        "mma.sync.aligned.m16n8k16.row.col.f32.f16.f16.f32 "
        "{%0,%1,%2,%3}, {%4,%5,%6,%7}, {%8,%9}, {%0,%1,%2,%3};"
        : "+f"(d[0]), "+f"(d[1]), "+f"(d[2]), "+f"(d[3])
        : "r"(a0), "r"(a1), "r"(a2), "r"(a3), "r"(b0), "r"(b1));
}
__device__ __forceinline__ uint32_t pack_h2(float x, float y) {
    __half2 h = __floats2half2_rn(x, y);
    return *reinterpret_cast<uint32_t*>(&h);
}
__device__ __forceinline__ void ldsm_x4(uint32_t& r0, uint32_t& r1,
                                        uint32_t& r2, uint32_t& r3,
                                        uint32_t addr) {
    asm volatile("ldmatrix.sync.aligned.m8n8.x4.shared.b16 {%0,%1,%2,%3}, [%4];"
                 : "=r"(r0), "=r"(r1), "=r"(r2), "=r"(r3) : "r"(addr));
}

// ---------------------------------------------------------------------------
// Conversions
// ---------------------------------------------------------------------------
__global__ void f2h_k(const float* __restrict__ in,
                      __half* __restrict__ out, int n4)
{
    int i = blockIdx.x * blockDim.x + threadIdx.x;
    if (i >= n4) return;
    float4 v = reinterpret_cast<const float4*>(in)[i];
    reinterpret_cast<__half2*>(out)[2 * i]     = __floats2half2_rn(v.x, v.y);
    reinterpret_cast<__half2*>(out)[2 * i + 1] = __floats2half2_rn(v.z, v.w);
}

// Transpose + convert: in fp32 [R][C] -> out fp16 [C][R]
__global__ __launch_bounds__(256) void f2hT_k(const float* __restrict__ in,
                                              __half* __restrict__ out,
                                              int R, int C)
{
    __shared__ float t[32][33];
    const int tx = threadIdx.x & 31;
    const int ty = threadIdx.x >> 5;
    const int c0 = blockIdx.x * 32;
    const int r0 = blockIdx.y * 32;
    #pragma unroll
    for (int j = 0; j < 32; j += 8)
        t[ty + j][tx] = in[(size_t)(r0 + ty + j) * C + c0 + tx];
    __syncthreads();
    #pragma unroll
    for (int j = 0; j < 32; j += 8)
        out[(size_t)(c0 + ty + j) * R + r0 + tx] = __float2half_rn(t[tx][ty + j]);
}

// ---------------------------------------------------------------------------
// FP16 GEMM: C[M,N] = A[M,K](fp16) @ BT[N,K](fp16)^T, templated output type.
// Raw mma.m16n8k16 + ldmatrix.x4; 128x256 block, BK=64, 8 warps (64x64);
// 3-stage cp.async; ONE barrier per K-iteration.
// ---------------------------------------------------------------------------
constexpr int G2ST = 72;
constexpr int G2A_H = 128 * G2ST;
constexpr int G2B_H = 256 * G2ST;
constexpr int G2STG_H = G2A_H + G2B_H;
constexpr int GEMM_SMEM_BYTES = 3 * G2STG_H * 2;

template <bool HALF_OUT>
__global__ __launch_bounds__(256, 1) void gemm_h2(const __half* __restrict__ A,
                                                  const __half* __restrict__ BT,
                                                  void* __restrict__ Cv,
                                                  int M, int N, int K)
{
    extern __shared__ __half hsm[];
    const int tid  = threadIdx.x;
    const int warp = tid >> 5;
    const int lane = tid & 31;
    const int lr   = lane >> 2;
    const int lc   = lane & 3;
    const int g    = lane >> 3;
    const int li   = lane & 7;
    const int wr   = warp >> 2;
    const int wcc  = warp & 3;

    const size_t bm0 = (size_t)blockIdx.y * 128;
    const size_t bn0 = (size_t)blockIdx.x * 256;
    const uint32_t sbase = smem_u32(hsm);

    auto issue_stage = [&](int slot, int k0) {
        const uint32_t sa = sbase + (uint32_t)(slot * G2STG_H) * 2u;
        const uint32_t sb = sa + (uint32_t)G2A_H * 2u;
        #pragma unroll
        for (int j = 0; j < 4; ++j) {
            int li2 = j * 256 + tid;
            int row = li2 >> 3;
            int c   = li2 & 7;
            const __half* src = A + (bm0 + row) * K + k0 + c * 8;
            CP_ASYNC16(sa + (uint32_t)(row * G2ST + c * 8) * 2u, src);
        }
        #pragma unroll
        for (int j = 0; j < 8; ++j) {
            int li2 = j * 256 + tid;
            int row = li2 >> 3;
            int c   = li2 & 7;
            const __half* src = BT + (bn0 + row) * K + k0 + c * 8;
            CP_ASYNC16(sb + (uint32_t)(row * G2ST + c * 8) * 2u, src);
        }
        CP_COMMIT();
    };

    float acc[4][8][4];
    #pragma unroll
    for (int mi = 0; mi < 4; ++mi)
        #pragma unroll
        for (int nf = 0; nf < 8; ++nf)
            #pragma unroll
            for (int e = 0; e < 4; ++e) acc[mi][nf][e] = 0.f;

    const int NIT = K >> 6;
    issue_stage(0, 0);
    issue_stage(1, 64);

    const uint32_t aoff = (uint32_t)((((g & 1) * 8 + li) * G2ST + (g >> 1) * 8) * 2);
    const uint32_t boff = (uint32_t)((((g >> 1) * 8 + li) * G2ST + (g & 1) * 8) * 2);

    for (int s = 0; s < NIT; ++s) {
        if (s >= NIT - 2) { CP_WAIT0(); } else { CP_WAIT1(); }
        __syncthreads();   // single barrier: separates iter s-1 reads of slot
                           // (s+2)%3 from this iter's cp.async writes into it,
                           // and makes the just-waited stage visible to all.
        if (s + 2 < NIT) issue_stage((s + 2) % 3, (s + 2) * 64);

        const uint32_t abase = sbase + (uint32_t)((s % 3) * G2STG_H) * 2u +
                               (uint32_t)(wr * 64 * G2ST) * 2u + aoff;
        const uint32_t bbase = sbase + (uint32_t)((s % 3) * G2STG_H + G2A_H) * 2u +
                               (uint32_t)(wcc * 64 * G2ST) * 2u + boff;

        #pragma unroll
        for (int ks = 0; ks < 4; ++ks) {
            uint32_t af[4][4];
            #pragma unroll
            for (int mi = 0; mi < 4; ++mi)
                ldsm_x4(af[mi][0], af[mi][1], af[mi][2], af[mi][3],
                        abase + (uint32_t)(mi * 16 * G2ST + ks * 16) * 2u);
            #pragma unroll
            for (int p = 0; p < 4; ++p) {
                uint32_t b0, b1, b2, b3;
                ldsm_x4(b0, b1, b2, b3,
                        bbase + (uint32_t)(p * 16 * G2ST + ks * 16) * 2u);
                #pragma unroll
                for (int mi = 0; mi < 4; ++mi) {
                    mma_f16(acc[mi][2 * p],     af[mi][0], af[mi][1],
                            af[mi][2], af[mi][3], b0, b1);
                    mma_f16(acc[mi][2 * p + 1], af[mi][0], af[mi][1],
                            af[mi][2], af[mi][3], b2, b3);
                }
            }
        }
        // no bottom barrier: next iter's top barrier provides the ordering
    }

    // Epilogue
    #pragma unroll
    for (int mi = 0; mi < 4; ++mi) {
        const size_t r0 = bm0 + wr * 64 + mi * 16 + lr;
        #pragma unroll
        for (int nf = 0; nf < 8; ++nf) {
            const size_t col = bn0 + wcc * 64 + nf * 8 + 2 * lc;
            if (HALF_OUT) {
                __half* C = (__half*)Cv;
                *reinterpret_cast<uint32_t*>(C + r0 * N + col) =
                    pack_h2(acc[mi][nf][0], acc[mi][nf][1]);
                *reinterpret_cast<uint32_t*>(C + (r0 + 8) * N + col) =
                    pack_h2(acc[mi][nf][2], acc[mi][nf][3]);
            } else {
                float* C = (float*)Cv;
                *reinterpret_cast<float2*>(C + r0 * N + col) =
                    make_float2(acc[mi][nf][0], acc[mi][nf][1]);
                *reinterpret_cast<float2*>(C + (r0 + 8) * N + col) =
                    make_float2(acc[mi][nf][2], acc[mi][nf][3]);
            }
        }
    }
}

// ---------------------------------------------------------------------------
// RoPE: read fp32, write scaled fp16.
// ---------------------------------------------------------------------------
__global__ void rope_h_k(const float* __restrict__ in, __half* __restrict__ out,
                         int nh, int total, float mul)
{
    int idx = blockIdx.x * blockDim.x + threadIdx.x;
    if (idx >= total) return;
    const int half = D_ / 2;
    int i = idx & (half - 1);
    int rest = idx >> 6;
    int h = rest % nh;
    rest /= nh;
    int s = rest % S_;
    int b = rest / S_;

    float inv = __expf(-logf(10000.0f) * (float)i / (float)half);
    float ang = (float)s * inv;
    float sn, cs;
    sincosf(ang, &sn, &cs);

    size_t base = ((size_t)((b * S_ + s) * nh + h)) * D_;
    float x1 = in[base + i];
    float x2 = in[base + i + half];
    out[base + i]        = __float2half_rn((x1 * cs - x2 * sn) * mul);
    out[base + i + half] = __float2half_rn((x2 * cs + x1 * sn) * mul);
}

// ---------------------------------------------------------------------------
// V transpose (fp16 in): [b][s][kvh][d] -> [b][kvh][d][s]
// ---------------------------------------------------------------------------
__global__ __launch_bounds__(256) void vt_k(const __half* __restrict__ in,
                                            __half* __restrict__ out)
{
    __shared__ __half t[32][34];
    const int tx = threadIdx.x & 31;
    const int ty = threadIdx.x >> 5;
    const int s0 = blockIdx.x * 32;
    const int d0 = blockIdx.y * 32;
    const int bk = blockIdx.z;
    const int b  = bk >> 3;
    const int kvh = bk & 7;

    #pragma unroll
    for (int j = 0; j < 32; j += 8)
        t[ty + j][tx] = in[((size_t)((b * S_ + s0 + ty + j) * HKV_ + kvh)) * D_ + d0 + tx];
    __syncthreads();
    #pragma unroll
    for (int j = 0; j < 32; j += 8)
        out[((size_t)(bk * D_ + d0 + ty + j)) * S_ + s0 + tx] = t[tx][ty + j];
}

// ---------------------------------------------------------------------------
// Flash attention (unchanged): fp16 mma + ldmatrix, FA2.
// ---------------------------------------------------------------------------
constexpr int KST = 136;
constexpr int VST = 72;
constexpr int QSM_HALVES = 128 * KST;
constexpr int KV_STG = 64 * KST + 128 * VST;
constexpr int FLASH_SMEM_BYTES = (QSM_HALVES + 2 * KV_STG) * 2;

__global__ __launch_bounds__(256, 2) void flash_h(const __half* __restrict__ Qg,
                                                  const __half* __restrict__ Kg,
                                                  const __half* __restrict__ Vtg,
                                                  __half* __restrict__ Og)
{
    extern __shared__ __half smh[];
    const int tid  = threadIdx.x;
    const int warp = tid >> 5;
    const int lane = tid & 31;
    const int lr   = lane >> 2;
    const int lc   = lane & 3;
    const int g    = lane >> 3;
    const int li   = lane & 7;
    const int qtile = gridDim.x - 1 - blockIdx.x;
    const int h    = blockIdx.y;
    const int b    = blockIdx.z;
    const int q0   = qtile * 128;
    const int kvh  = h >> 2;
    const uint32_t sbase = smem_u32(smh);

    #pragma unroll
    for (int it = 0; it < 8; ++it) {
        int li2  = it * 256 + tid;
        int row = li2 >> 4;
        int c   = li2 & 15;
        const __half* src = Qg + ((size_t)((b * S_ + q0 + row) * H_ + h)) * D_ + c * 8;
        CP_ASYNC16(sbase + (uint32_t)(row * KST + c * 8) * 2u, src);
    }
    CP_COMMIT();

    float d[16][4];
    #pragma unroll
    for (int i = 0; i < 16; ++i)
        #pragma unroll
        for (int j = 0; j < 4; ++j) d[i][j] = 0.f;
    float m0 = -1e30f, m1 = -1e30f, l0 = 0.f, l1 = 0.f;

    auto issue_kv = [&](int t) {
        const int s = t & 1;
        const uint32_t kb = sbase + (uint32_t)(QSM_HALVES + s * KV_STG) * 2u;
        const uint32_t vb = kb + (uint32_t)(64 * KST) * 2u;
        const int kv0 = t * 64;
        #pragma unroll
        for (int it = 0; it < 4; ++it) {
            int li2  = it * 256 + tid;
            int row = li2 >> 4;
            int c   = li2 & 15;
            const __half* src = Kg + ((size_t)((b * S_ + kv0 + row) * HKV_ + kvh)) * D_ + c * 8;
            CP_ASYNC16(kb + (uint32_t)(row * KST + c * 8) * 2u, src);
        }
        #pragma unroll
        for (int it = 0; it < 4; ++it) {
            int li2  = it * 256 + tid;
            int row = li2 >> 3;
            int c   = li2 & 7;
            const __half* src = Vtg + ((size_t)((b * HKV_ + kvh) * D_ + row)) * S_ + kv0 + c * 8;
            CP_ASYNC16(vb + (uint32_t)(row * VST + c * 8) * 2u, src);
        }
        CP_COMMIT();
    };

    const int tmax = 2 * qtile + 1;
    const int wrow_lo = q0 + warp * 16;
    const int wrow_hi = wrow_lo + 15;
    const uint32_t qaddr = sbase +
        (uint32_t)(((warp * 16 + (g & 1) * 8 + li) * KST + (g >> 1) * 8) * 2);
    issue_kv(0);

    for (int t = 0; t <= tmax; ++t) {
        CP_WAIT0();
        __syncthreads();
        if (t < tmax) issue_kv(t + 1);

        const int kv0 = t * 64;
        if (kv0 <= wrow_hi) {
            const uint32_t kwb = sbase +
                (uint32_t)((QSM_HALVES + (t & 1) * KV_STG) * 2);
            const uint32_t kaddr = kwb +
                (uint32_t)((((g >> 1) * 8 + li) * KST + (g & 1) * 8) * 2);
            const uint32_t vaddr = kwb + (uint32_t)(64 * KST * 2) +
                (uint32_t)((((g >> 1) * 8 + li) * VST + (g & 1) * 8) * 2);

            float s[8][4];
            #pragma unroll
            for (int nf = 0; nf < 8; ++nf)
                #pragma unroll
                for (int e = 0; e < 4; ++e) s[nf][e] = 0.f;
            #pragma unroll
            for (int j = 0; j < 8; ++j) {
                uint32_t qa0, qa1, qa2, qa3;
                ldsm_x4(qa0, qa1, qa2, qa3, qaddr + j * 32);
                #pragma unroll
                for (int nfp = 0; nfp < 4; ++nfp) {
                    uint32_t kb0, kb1, kb2, kb3;
                    ldsm_x4(kb0, kb1, kb2, kb3,
                            kaddr + nfp * (16 * KST * 2) + j * 32);
                    mma_f16(s[2 * nfp],     qa0, qa1, qa2, qa3, kb0, kb1);
                    mma_f16(s[2 * nfp + 1], qa0, qa1, qa2, qa3, kb2, kb3);
                }
            }

            if (kv0 + 63 > wrow_lo) {
                const int row0 = wrow_lo + lr;
                #pragma unroll
                for (int nf = 0; nf < 8; ++nf) {
                    int c0 = kv0 + 8 * nf + 2 * lc;
                    if (c0 > row0)         s[nf][0] = -1e30f;
                    if (c0 + 1 > row0)     s[nf][1] = -1e30f;
                    if (c0 > row0 + 8)     s[nf][2] = -1e30f;
                    if (c0 + 1 > row0 + 8) s[nf][3] = -1e30f;
                }
            }

            float mx0 = -1e30f, mx1 = -1e30f;
            #pragma unroll
            for (int nf = 0; nf < 8; ++nf) {
                mx0 = fmaxf(mx0, fmaxf(s[nf][0], s[nf][1]));
                mx1 = fmaxf(mx1, fmaxf(s[nf][2], s[nf][3]));
            }
            mx0 = fmaxf(mx0, __shfl_xor_sync(0xFFFFFFFFu, mx0, 1));
            mx0 = fmaxf(mx0, __shfl_xor_sync(0xFFFFFFFFu, mx0, 2));
            mx1 = fmaxf(mx1, __shfl_xor_sync(0xFFFFFFFFu, mx1, 1));
            mx1 = fmaxf(mx1, __shfl_xor_sync(0xFFFFFFFFu, mx1, 2));
            float m0n = fmaxf(m0, mx0), m1n = fmaxf(m1, mx1);
            float al0 = exp2f(m0 - m0n), al1 = exp2f(m1 - m1n);
            float su0 = 0.f, su1 = 0.f;
            #pragma unroll
            for (int nf = 0; nf < 8; ++nf) {
                s[nf][0] = exp2f(s[nf][0] - m0n);
                s[nf][1] = exp2f(s[nf][1] - m0n);
                s[nf][2] = exp2f(s[nf][2] - m1n);
                s[nf][3] = exp2f(s[nf][3] - m1n);
                su0 += s[nf][0] + s[nf][1];
                su1 += s[nf][2] + s[nf][3];
            }
            su0 += __shfl_xor_sync(0xFFFFFFFFu, su0, 1);
            su0 += __shfl_xor_sync(0xFFFFFFFFu, su0, 2);
            su1 += __shfl_xor_sync(0xFFFFFFFFu, su1, 1);
            su1 += __shfl_xor_sync(0xFFFFFFFFu, su1, 2);
            l0 = l0 * al0 + su0;  m0 = m0n;
            l1 = l1 * al1 + su1;  m1 = m1n;

            #pragma unroll
            for (int nf = 0; nf < 16; ++nf) {
                d[nf][0] *= al0; d[nf][1] *= al0;
                d[nf][2] *= al1; d[nf][3] *= al1;
            }

            #pragma unroll
            for (int j = 0; j < 4; ++j) {
                uint32_t pa0 = pack_h2(s[2*j][0],   s[2*j][1]);
                uint32_t pa1 = pack_h2(s[2*j][2],   s[2*j][3]);
                uint32_t pa2 = pack_h2(s[2*j+1][0], s[2*j+1][1]);
                uint32_t pa3 = pack_h2(s[2*j+1][2], s[2*j+1][3]);
                #pragma unroll
                for (int nfp = 0; nfp < 8; ++nfp) {
                    uint32_t vb0, vb1, vb2, vb3;
                    ldsm_x4(vb0, vb1, vb2, vb3,
                            vaddr + nfp * (16 * VST * 2) + j * 32);
                    mma_f16(d[2 * nfp],     pa0, pa1, pa2, pa3, vb0, vb1);
                    mma_f16(d[2 * nfp + 1], pa0, pa1, pa2, pa3, vb2, vb3);
                }
            }
        }
    }

    const float il0 = 1.f / l0, il1 = 1.f / l1;
    const int row0 = q0 + warp * 16 + lr;
    __half* o0 = Og + ((size_t)((b * S_ + row0) * H_ + h)) * D_;
    __half* o1 = Og + ((size_t)((b * S_ + row0 + 8) * H_ + h)) * D_;
    #pragma unroll
    for (int nf = 0; nf < 16; ++nf) {
        *reinterpret_cast<uint32_t*>(o0 + 8 * nf + 2 * lc) =
            pack_h2(d[nf][0] * il0, d[nf][1] * il0);
        *reinterpret_cast<uint32_t*>(o1 + 8 * nf + 2 * lc) =
            pack_h2(d[nf][2] * il1, d[nf][3] * il1);
    }
}

// ---------------------------------------------------------------------------
// Launcher
// ---------------------------------------------------------------------------
extern "C" void kernel_launch(void* const* d_in, const int* in_sizes, int n_in,
                              void* d_out, int out_size)
{
    const float* x  = (const float*)d_in[0];
    const float* wq = (const float*)d_in[1];
    const float* wk = (const float*)d_in[2];
    const float* wv = (const float*)d_in[3];
    const float* wo = (const float*)d_in[4];
    float* out = (float*)d_out;

    float *qp, *kp;
    __half *xh, *wqh, *wkh, *wvh, *woh, *oph, *qh, *kh, *vth;
    cudaGetSymbolAddress((void**)&qp, g_q);
    cudaGetSymbolAddress((void**)&kp, g_k);
    cudaGetSymbolAddress((void**)&xh, g_xh);
    cudaGetSymbolAddress((void**)&wqh, g_wqh);
    cudaGetSymbolAddress((void**)&wkh, g_wkh);
    cudaGetSymbolAddress((void**)&wvh, g_wvh);
    cudaGetSymbolAddress((void**)&woh, g_woh);
    cudaGetSymbolAddress((void**)&oph, g_oph);
    cudaGetSymbolAddress((void**)&qh, g_qh);
    cudaGetSymbolAddress((void**)&kh, g_kh);
    cudaGetSymbolAddress((void**)&vth, g_vth);

    cudaFuncSetAttribute(gemm_h2<false>, cudaFuncAttributeMaxDynamicSharedMemorySize,
                         GEMM_SMEM_BYTES);
    cudaFuncSetAttribute(gemm_h2<true>, cudaFuncAttributeMaxDynamicSharedMemorySize,
                         GEMM_SMEM_BYTES);
    cudaFuncSetAttribute(flash_h, cudaFuncAttributeMaxDynamicSharedMemorySize,
                         FLASH_SMEM_BYTES);

    const int NKV = HKV_ * D_;   // 1024

    // Convert inputs: x -> fp16 row-major; weights -> fp16 TRANSPOSED [N][K]
    {
        int n4 = (M_ * HID_) / 4;
        f2h_k<<<(n4 + 255) / 256, 256>>>(x, xh, n4);
        f2hT_k<<<dim3(HID_ / 32, HID_ / 32), 256>>>(wq, wqh, HID_, HID_);
        f2hT_k<<<dim3(HID_ / 32, HID_ / 32), 256>>>(wo, woh, HID_, HID_);
        f2hT_k<<<dim3(NKV / 32, HID_ / 32), 256>>>(wk, wkh, HID_, NKV);
        f2hT_k<<<dim3(NKV / 32, HID_ / 32), 256>>>(wv, wvh, HID_, NKV);
    }

    // QKV projections: Q,K fp32 out (RoPE precision), V fp16 out (direct)
    gemm_h2<false><<<dim3(HID_ / 256, M_ / 128), 256, GEMM_SMEM_BYTES>>>(xh, wqh, qp, M_, HID_, HID_);
    gemm_h2<false><<<dim3(NKV / 256, M_ / 128), 256, GEMM_SMEM_BYTES>>>(xh, wkh, kp, M_, NKV, HID_);
    gemm_h2<true ><<<dim3(NKV / 256, M_ / 128), 256, GEMM_SMEM_BYTES>>>(xh, wvh, oph, M_, NKV, HID_);

    // RoPE -> fp16 (Q pre-scaled by 1/sqrt(D)*log2e); V transpose (fp16 in)
    {
        const float qmul = 0.08838834764831845f * 1.4426950408889634f;
        int totq = B_ * S_ * H_ * (D_ / 2);
        rope_h_k<<<(totq + 255) / 256, 256>>>(qp, qh, H_, totq, qmul);
        int totk = B_ * S_ * HKV_ * (D_ / 2);
        rope_h_k<<<(totk + 255) / 256, 256>>>(kp, kh, HKV_, totk, 1.0f);
        vt_k<<<dim3(S_ / 32, D_ / 32, B_ * HKV_), 256>>>(oph, vth);
    }

    // Flash attention -> fp16 output (overwrites oph after vt consumed V)
    flash_h<<<dim3(S_ / 128, H_, B_), 256, FLASH_SMEM_BYTES>>>(qh, kh, vth, oph);

    // Output projection (fp32 out)
    gemm_h2<false><<<dim3(HID_ / 256, M_ / 128), 256, GEMM_SMEM_BYTES>>>(oph, woh, out, M_, HID_, HID_);
}

// round 14
// speedup vs baseline: 12.1058x; 1.0041x over previous
#include <cuda_runtime.h>
#include <cuda_fp16.h>
#include <cuda_bf16.h>
#include <mma.h>
#include <math.h>
#include <float.h>
#include <stdint.h>

using namespace nvcuda;

// Problem constants
#define B_  2
#define S_  2048
#define HID_ 4096
#define H_  32
#define HKV_ 8
#define D_  128
#define M_  (B_ * S_)   // 4096 rows of x

// Scratch (device globals)
__device__ float g_q[(size_t)B_ * S_ * H_ * D_];
__device__ float g_k[(size_t)B_ * S_ * HKV_ * D_];
// fp16 operands (weights stored TRANSPOSED [N][K])
__device__ __half g_xh [(size_t)M_ * HID_];
__device__ __half g_wqh[(size_t)HID_ * HID_];
__device__ __half g_wkh[(size_t)HID_ * (HKV_ * D_)];
__device__ __half g_wvh[(size_t)HID_ * (HKV_ * D_)];
__device__ __half g_woh[(size_t)HID_ * HID_];
__device__ __half g_oph[(size_t)M_ * HID_];   // first: V fp16; later: attn out fp16
__device__ __half g_qh [(size_t)B_ * S_ * H_ * D_];
__device__ __half g_kh [(size_t)B_ * S_ * HKV_ * D_];
__device__ __half g_vth[(size_t)B_ * HKV_ * D_ * S_];

// ---------------------------------------------------------------------------
// helpers
// ---------------------------------------------------------------------------
__device__ __forceinline__ uint32_t smem_u32(const void* p) {
    uint32_t a;
    asm("{ .reg .u64 t; cvta.to.shared.u64 t, %1; cvt.u32.u64 %0, t; }"
        : "=r"(a) : "l"(p));
    return a;
}
#define CP_ASYNC16(dst_u32, src_ptr) \
    asm volatile("cp.async.cg.shared.global [%0], [%1], 16;" \
                 :: "r"(dst_u32), "l"(src_ptr) : "memory")
#define CP_COMMIT() asm volatile("cp.async.commit_group;" ::: "memory")
#define CP_WAIT1()  asm volatile("cp.async.wait_group 1;" ::: "memory")
#define CP_WAIT0()  asm volatile("cp.async.wait_group 0;" ::: "memory")

__device__ __forceinline__ void mma_f16(float d[4], uint32_t a0, uint32_t a1,
                                        uint32_t a2, uint32_t a3,
                                        uint32_t b0, uint32_t b1) {
    asm volatile(
        "mma.sync.aligned.m16n8k16.row.col.f32.f16.f16.f32 "
        "{%0,%1,%2,%3}, {%4,%5,%6,%7}, {%8,%9}, {%0,%1,%2,%3};"
        : "+f"(d[0]), "+f"(d[1]), "+f"(d[2]), "+f"(d[3])
        : "r"(a0), "r"(a1), "r"(a2), "r"(a3), "r"(b0), "r"(b1));
}
__device__ __forceinline__ uint32_t pack_h2(float x, float y) {
    __half2 h = __floats2half2_rn(x, y);
    return *reinterpret_cast<uint32_t*>(&h);
}
__device__ __forceinline__ void ldsm_x4(uint32_t& r0, uint32_t& r1,
                                        uint32_t& r2, uint32_t& r3,
                                        uint32_t addr) {
    asm volatile("ldmatrix.sync.aligned.m8n8.x4.shared.b16 {%0,%1,%2,%3}, [%4];"
                 : "=r"(r0), "=r"(r1), "=r"(r2), "=r"(r3) : "r"(addr));
}

// ---------------------------------------------------------------------------
// Conversions
// ---------------------------------------------------------------------------
__global__ void f2h_k(const float* __restrict__ in,
                      __half* __restrict__ out, int n4)
{
    int i = blockIdx.x * blockDim.x + threadIdx.x;
    if (i >= n4) return;
    float4 v = reinterpret_cast<const float4*>(in)[i];
    reinterpret_cast<__half2*>(out)[2 * i]     = __floats2half2_rn(v.x, v.y);
    reinterpret_cast<__half2*>(out)[2 * i + 1] = __floats2half2_rn(v.z, v.w);
}

// Transpose + convert: in fp32 [R][C] -> out fp16 [C][R]
__global__ __launch_bounds__(256) void f2hT_k(const float* __restrict__ in,
                                              __half* __restrict__ out,
                                              int R, int C)
{
    __shared__ float t[32][33];
    const int tx = threadIdx.x & 31;
    const int ty = threadIdx.x >> 5;
    const int c0 = blockIdx.x * 32;
    const int r0 = blockIdx.y * 32;
    #pragma unroll
    for (int j = 0; j < 32; j += 8)
        t[ty + j][tx] = in[(size_t)(r0 + ty + j) * C + c0 + tx];
    __syncthreads();
    #pragma unroll
    for (int j = 0; j < 32; j += 8)
        out[(size_t)(c0 + ty + j) * R + r0 + tx] = __float2half_rn(t[tx][ty + j]);
}

// ---------------------------------------------------------------------------
// FP16 GEMM: C[M,N] = A[M,K](fp16) @ BT[N,K](fp16)^T, templated output type.
// Raw mma.m16n8k16 + ldmatrix.x4; 128x256 block, BK=64, 8 warps (64x64);
// 3-stage cp.async; software-pipelined (double-buffered) register fragments.
// ---------------------------------------------------------------------------
constexpr int G2ST = 72;
constexpr int G2A_H = 128 * G2ST;
constexpr int G2B_H = 256 * G2ST;
constexpr int G2STG_H = G2A_H + G2B_H;
constexpr int GEMM_SMEM_BYTES = 3 * G2STG_H * 2;

template <bool HALF_OUT>
__global__ __launch_bounds__(256, 1) void gemm_h2(const __half* __restrict__ A,
                                                  const __half* __restrict__ BT,
                                                  void* __restrict__ Cv,
                                                  int M, int N, int K)
{
    extern __shared__ __half hsm[];
    const int tid  = threadIdx.x;
    const int warp = tid >> 5;
    const int lane = tid & 31;
    const int lr   = lane >> 2;
    const int lc   = lane & 3;
    const int g    = lane >> 3;
    const int li   = lane & 7;
    const int wr   = warp >> 2;
    const int wcc  = warp & 3;

    const size_t bm0 = (size_t)blockIdx.y * 128;
    const size_t bn0 = (size_t)blockIdx.x * 256;
    const uint32_t sbase = smem_u32(hsm);

    auto issue_stage = [&](int slot, int k0) {
        const uint32_t sa = sbase + (uint32_t)(slot * G2STG_H) * 2u;
        const uint32_t sb = sa + (uint32_t)G2A_H * 2u;
        #pragma unroll
        for (int j = 0; j < 4; ++j) {
            int li2 = j * 256 + tid;
            int row = li2 >> 3;
            int c   = li2 & 7;
            const __half* src = A + (bm0 + row) * K + k0 + c * 8;
            CP_ASYNC16(sa + (uint32_t)(row * G2ST + c * 8) * 2u, src);
        }
        #pragma unroll
        for (int j = 0; j < 8; ++j) {
            int li2 = j * 256 + tid;
            int row = li2 >> 3;
            int c   = li2 & 7;
            const __half* src = BT + (bn0 + row) * K + k0 + c * 8;
            CP_ASYNC16(sb + (uint32_t)(row * G2ST + c * 8) * 2u, src);
        }
        CP_COMMIT();
    };

    float acc[4][8][4];
    #pragma unroll
    for (int mi = 0; mi < 4; ++mi)
        #pragma unroll
        for (int nf = 0; nf < 8; ++nf)
            #pragma unroll
            for (int e = 0; e < 4; ++e) acc[mi][nf][e] = 0.f;

    const int NIT = K >> 6;
    issue_stage(0, 0);
    issue_stage(1, 64);

    const uint32_t aoff = (uint32_t)((((g & 1) * 8 + li) * G2ST + (g >> 1) * 8) * 2);
    const uint32_t boff = (uint32_t)((((g >> 1) * 8 + li) * G2ST + (g & 1) * 8) * 2);

    // Double-buffered register fragments
    uint32_t af[2][4][4];
    uint32_t bf[2][4][4];

    for (int s = 0; s < NIT; ++s) {
        if (s >= NIT - 2) { CP_WAIT0(); } else { CP_WAIT1(); }
        __syncthreads();
        if (s + 2 < NIT) issue_stage((s + 2) % 3, (s + 2) * 64);

        const uint32_t abase = sbase + (uint32_t)((s % 3) * G2STG_H) * 2u +
                               (uint32_t)(wr * 64 * G2ST) * 2u + aoff;
        const uint32_t bbase = sbase + (uint32_t)((s % 3) * G2STG_H + G2A_H) * 2u +
                               (uint32_t)(wcc * 64 * G2ST) * 2u + boff;

        // Prologue: stage ks=0 fragments
        #pragma unroll
        for (int mi = 0; mi < 4; ++mi)
            ldsm_x4(af[0][mi][0], af[0][mi][1], af[0][mi][2], af[0][mi][3],
                    abase + (uint32_t)(mi * 16 * G2ST) * 2u);
        #pragma unroll
        for (int p = 0; p < 4; ++p)
            ldsm_x4(bf[0][p][0], bf[0][p][1], bf[0][p][2], bf[0][p][3],
                    bbase + (uint32_t)(p * 16 * G2ST) * 2u);

        #pragma unroll
        for (int ks = 0; ks < 4; ++ks) {
            const int cur = ks & 1;
            const int nxt = cur ^ 1;
            // Prefetch ks+1 fragments BEFORE consuming ks (hides LDSM latency)
            if (ks < 3) {
                #pragma unroll
                for (int mi = 0; mi < 4; ++mi)
                    ldsm_x4(af[nxt][mi][0], af[nxt][mi][1],
                            af[nxt][mi][2], af[nxt][mi][3],
                            abase + (uint32_t)(mi * 16 * G2ST + (ks + 1) * 16) * 2u);
                #pragma unroll
                for (int p = 0; p < 4; ++p)
                    ldsm_x4(bf[nxt][p][0], bf[nxt][p][1],
                            bf[nxt][p][2], bf[nxt][p][3],
                            bbase + (uint32_t)(p * 16 * G2ST + (ks + 1) * 16) * 2u);
            }
            #pragma unroll
            for (int p = 0; p < 4; ++p) {
                #pragma unroll
                for (int mi = 0; mi < 4; ++mi) {
                    mma_f16(acc[mi][2 * p],     af[cur][mi][0], af[cur][mi][1],
                            af[cur][mi][2], af[cur][mi][3],
                            bf[cur][p][0], bf[cur][p][1]);
                    mma_f16(acc[mi][2 * p + 1], af[cur][mi][0], af[cur][mi][1],
                            af[cur][mi][2], af[cur][mi][3],
                            bf[cur][p][2], bf[cur][p][3]);
                }
            }
        }
    }

    // Epilogue
    #pragma unroll
    for (int mi = 0; mi < 4; ++mi) {
        const size_t r0 = bm0 + wr * 64 + mi * 16 + lr;
        #pragma unroll
        for (int nf = 0; nf < 8; ++nf) {
            const size_t col = bn0 + wcc * 64 + nf * 8 + 2 * lc;
            if (HALF_OUT) {
                __half* C = (__half*)Cv;
                *reinterpret_cast<uint32_t*>(C + r0 * N + col) =
                    pack_h2(acc[mi][nf][0], acc[mi][nf][1]);
                *reinterpret_cast<uint32_t*>(C + (r0 + 8) * N + col) =
                    pack_h2(acc[mi][nf][2], acc[mi][nf][3]);
            } else {
                float* C = (float*)Cv;
                *reinterpret_cast<float2*>(C + r0 * N + col) =
                    make_float2(acc[mi][nf][0], acc[mi][nf][1]);
                *reinterpret_cast<float2*>(C + (r0 + 8) * N + col) =
                    make_float2(acc[mi][nf][2], acc[mi][nf][3]);
            }
        }
    }
}

// ---------------------------------------------------------------------------
// RoPE: read fp32, write scaled fp16.
// ---------------------------------------------------------------------------
__global__ void rope_h_k(const float* __restrict__ in, __half* __restrict__ out,
                         int nh, int total, float mul)
{
    int idx = blockIdx.x * blockDim.x + threadIdx.x;
    if (idx >= total) return;
    const int half = D_ / 2;
    int i = idx & (half - 1);
    int rest = idx >> 6;
    int h = rest % nh;
    rest /= nh;
    int s = rest % S_;
    int b = rest / S_;

    float inv = __expf(-logf(10000.0f) * (float)i / (float)half);
    float ang = (float)s * inv;
    float sn, cs;
    sincosf(ang, &sn, &cs);

    size_t base = ((size_t)((b * S_ + s) * nh + h)) * D_;
    float x1 = in[base + i];
    float x2 = in[base + i + half];
    out[base + i]        = __float2half_rn((x1 * cs - x2 * sn) * mul);
    out[base + i + half] = __float2half_rn((x2 * cs + x1 * sn) * mul);
}

// ---------------------------------------------------------------------------
// V transpose (fp16 in): [b][s][kvh][d] -> [b][kvh][d][s]
// ---------------------------------------------------------------------------
__global__ __launch_bounds__(256) void vt_k(const __half* __restrict__ in,
                                            __half* __restrict__ out)
{
    __shared__ __half t[32][34];
    const int tx = threadIdx.x & 31;
    const int ty = threadIdx.x >> 5;
    const int s0 = blockIdx.x * 32;
    const int d0 = blockIdx.y * 32;
    const int bk = blockIdx.z;
    const int b  = bk >> 3;
    const int kvh = bk & 7;

    #pragma unroll
    for (int j = 0; j < 32; j += 8)
        t[ty + j][tx] = in[((size_t)((b * S_ + s0 + ty + j) * HKV_ + kvh)) * D_ + d0 + tx];
    __syncthreads();
    #pragma unroll
    for (int j = 0; j < 32; j += 8)
        out[((size_t)(bk * D_ + d0 + ty + j)) * S_ + s0 + tx] = t[tx][ty + j];
}

// ---------------------------------------------------------------------------
// Flash attention (unchanged): fp16 mma + ldmatrix, FA2.
// ---------------------------------------------------------------------------
constexpr int KST = 136;
constexpr int VST = 72;
constexpr int QSM_HALVES = 128 * KST;
constexpr int KV_STG = 64 * KST + 128 * VST;
constexpr int FLASH_SMEM_BYTES = (QSM_HALVES + 2 * KV_STG) * 2;

__global__ __launch_bounds__(256, 2) void flash_h(const __half* __restrict__ Qg,
                                                  const __half* __restrict__ Kg,
                                                  const __half* __restrict__ Vtg,
                                                  __half* __restrict__ Og)
{
    extern __shared__ __half smh[];
    const int tid  = threadIdx.x;
    const int warp = tid >> 5;
    const int lane = tid & 31;
    const int lr   = lane >> 2;
    const int lc   = lane & 3;
    const int g    = lane >> 3;
    const int li   = lane & 7;
    const int qtile = gridDim.x - 1 - blockIdx.x;
    const int h    = blockIdx.y;
    const int b    = blockIdx.z;
    const int q0   = qtile * 128;
    const int kvh  = h >> 2;
    const uint32_t sbase = smem_u32(smh);

    #pragma unroll
    for (int it = 0; it < 8; ++it) {
        int li2  = it * 256 + tid;
        int row = li2 >> 4;
        int c   = li2 & 15;
        const __half* src = Qg + ((size_t)((b * S_ + q0 + row) * H_ + h)) * D_ + c * 8;
        CP_ASYNC16(sbase + (uint32_t)(row * KST + c * 8) * 2u, src);
    }
    CP_COMMIT();

    float d[16][4];
    #pragma unroll
    for (int i = 0; i < 16; ++i)
        #pragma unroll
        for (int j = 0; j < 4; ++j) d[i][j] = 0.f;
    float m0 = -1e30f, m1 = -1e30f, l0 = 0.f, l1 = 0.f;

    auto issue_kv = [&](int t) {
        const int s = t & 1;
        const uint32_t kb = sbase + (uint32_t)(QSM_HALVES + s * KV_STG) * 2u;
        const uint32_t vb = kb + (uint32_t)(64 * KST) * 2u;
        const int kv0 = t * 64;
        #pragma unroll
        for (int it = 0; it < 4; ++it) {
            int li2  = it * 256 + tid;
            int row = li2 >> 4;
            int c   = li2 & 15;
            const __half* src = Kg + ((size_t)((b * S_ + kv0 + row) * HKV_ + kvh)) * D_ + c * 8;
            CP_ASYNC16(kb + (uint32_t)(row * KST + c * 8) * 2u, src);
        }
        #pragma unroll
        for (int it = 0; it < 4; ++it) {
            int li2  = it * 256 + tid;
            int row = li2 >> 3;
            int c   = li2 & 7;
            const __half* src = Vtg + ((size_t)((b * HKV_ + kvh) * D_ + row)) * S_ + kv0 + c * 8;
            CP_ASYNC16(vb + (uint32_t)(row * VST + c * 8) * 2u, src);
        }
        CP_COMMIT();
    };

    const int tmax = 2 * qtile + 1;
    const int wrow_lo = q0 + warp * 16;
    const int wrow_hi = wrow_lo + 15;
    const uint32_t qaddr = sbase +
        (uint32_t)(((warp * 16 + (g & 1) * 8 + li) * KST + (g >> 1) * 8) * 2);
    issue_kv(0);

    for (int t = 0; t <= tmax; ++t) {
        CP_WAIT0();
        __syncthreads();
        if (t < tmax) issue_kv(t + 1);

        const int kv0 = t * 64;
        if (kv0 <= wrow_hi) {
            const uint32_t kwb = sbase +
                (uint32_t)((QSM_HALVES + (t & 1) * KV_STG) * 2);
            const uint32_t kaddr = kwb +
                (uint32_t)((((g >> 1) * 8 + li) * KST + (g & 1) * 8) * 2);
            const uint32_t vaddr = kwb + (uint32_t)(64 * KST * 2) +
                (uint32_t)((((g >> 1) * 8 + li) * VST + (g & 1) * 8) * 2);

            float s[8][4];
            #pragma unroll
            for (int nf = 0; nf < 8; ++nf)
                #pragma unroll
                for (int e = 0; e < 4; ++e) s[nf][e] = 0.f;
            #pragma unroll
            for (int j = 0; j < 8; ++j) {
                uint32_t qa0, qa1, qa2, qa3;
                ldsm_x4(qa0, qa1, qa2, qa3, qaddr + j * 32);
                #pragma unroll
                for (int nfp = 0; nfp < 4; ++nfp) {
                    uint32_t kb0, kb1, kb2, kb3;
                    ldsm_x4(kb0, kb1, kb2, kb3,
                            kaddr + nfp * (16 * KST * 2) + j * 32);
                    mma_f16(s[2 * nfp],     qa0, qa1, qa2, qa3, kb0, kb1);
                    mma_f16(s[2 * nfp + 1], qa0, qa1, qa2, qa3, kb2, kb3);
                }
            }

            if (kv0 + 63 > wrow_lo) {
                const int row0 = wrow_lo + lr;
                #pragma unroll
                for (int nf = 0; nf < 8; ++nf) {
                    int c0 = kv0 + 8 * nf + 2 * lc;
                    if (c0 > row0)         s[nf][0] = -1e30f;
                    if (c0 + 1 > row0)     s[nf][1] = -1e30f;
                    if (c0 > row0 + 8)     s[nf][2] = -1e30f;
                    if (c0 + 1 > row0 + 8) s[nf][3] = -1e30f;
                }
            }

            float mx0 = -1e30f, mx1 = -1e30f;
            #pragma unroll
            for (int nf = 0; nf < 8; ++nf) {
                mx0 = fmaxf(mx0, fmaxf(s[nf][0], s[nf][1]));
                mx1 = fmaxf(mx1, fmaxf(s[nf][2], s[nf][3]));
            }
            mx0 = fmaxf(mx0, __shfl_xor_sync(0xFFFFFFFFu, mx0, 1));
            mx0 = fmaxf(mx0, __shfl_xor_sync(0xFFFFFFFFu, mx0, 2));
            mx1 = fmaxf(mx1, __shfl_xor_sync(0xFFFFFFFFu, mx1, 1));
            mx1 = fmaxf(mx1, __shfl_xor_sync(0xFFFFFFFFu, mx1, 2));
            float m0n = fmaxf(m0, mx0), m1n = fmaxf(m1, mx1);
            float al0 = exp2f(m0 - m0n), al1 = exp2f(m1 - m1n);
            float su0 = 0.f, su1 = 0.f;
            #pragma unroll
            for (int nf = 0; nf < 8; ++nf) {
                s[nf][0] = exp2f(s[nf][0] - m0n);
                s[nf][1] = exp2f(s[nf][1] - m0n);
                s[nf][2] = exp2f(s[nf][2] - m1n);
                s[nf][3] = exp2f(s[nf][3] - m1n);
                su0 += s[nf][0] + s[nf][1];
                su1 += s[nf][2] + s[nf][3];
            }
            su0 += __shfl_xor_sync(0xFFFFFFFFu, su0, 1);
            su0 += __shfl_xor_sync(0xFFFFFFFFu, su0, 2);
            su1 += __shfl_xor_sync(0xFFFFFFFFu, su1, 1);
            su1 += __shfl_xor_sync(0xFFFFFFFFu, su1, 2);
            l0 = l0 * al0 + su0;  m0 = m0n;
            l1 = l1 * al1 + su1;  m1 = m1n;

            #pragma unroll
            for (int nf = 0; nf < 16; ++nf) {
                d[nf][0] *= al0; d[nf][1] *= al0;
                d[nf][2] *= al1; d[nf][3] *= al1;
            }

            #pragma unroll
            for (int j = 0; j < 4; ++j) {
                uint32_t pa0 = pack_h2(s[2*j][0],   s[2*j][1]);
                uint32_t pa1 = pack_h2(s[2*j][2],   s[2*j][3]);
                uint32_t pa2 = pack_h2(s[2*j+1][0], s[2*j+1][1]);
                uint32_t pa3 = pack_h2(s[2*j+1][2], s[2*j+1][3]);
                #pragma unroll
                for (int nfp = 0; nfp < 8; ++nfp) {
                    uint32_t vb0, vb1, vb2, vb3;
                    ldsm_x4(vb0, vb1, vb2, vb3,
                            vaddr + nfp * (16 * VST * 2) + j * 32);
                    mma_f16(d[2 * nfp],     pa0, pa1, pa2, pa3, vb0, vb1);
                    mma_f16(d[2 * nfp + 1], pa0, pa1, pa2, pa3, vb2, vb3);
                }
            }
        }
    }

    const float il0 = 1.f / l0, il1 = 1.f / l1;
    const int row0 = q0 + warp * 16 + lr;
    __half* o0 = Og + ((size_t)((b * S_ + row0) * H_ + h)) * D_;
    __half* o1 = Og + ((size_t)((b * S_ + row0 + 8) * H_ + h)) * D_;
    #pragma unroll
    for (int nf = 0; nf < 16; ++nf) {
        *reinterpret_cast<uint32_t*>(o0 + 8 * nf + 2 * lc) =
            pack_h2(d[nf][0] * il0, d[nf][1] * il0);
        *reinterpret_cast<uint32_t*>(o1 + 8 * nf + 2 * lc) =
            pack_h2(d[nf][2] * il1, d[nf][3] * il1);
    }
}

// ---------------------------------------------------------------------------
// Launcher
// ---------------------------------------------------------------------------
extern "C" void kernel_launch(void* const* d_in, const int* in_sizes, int n_in,
                              void* d_out, int out_size)
{
    const float* x  = (const float*)d_in[0];
    const float* wq = (const float*)d_in[1];
    const float* wk = (const float*)d_in[2];
    const float* wv = (const float*)d_in[3];
    const float* wo = (const float*)d_in[4];
    float* out = (float*)d_out;

    float *qp, *kp;
    __half *xh, *wqh, *wkh, *wvh, *woh, *oph, *qh, *kh, *vth;
    cudaGetSymbolAddress((void**)&qp, g_q);
    cudaGetSymbolAddress((void**)&kp, g_k);
    cudaGetSymbolAddress((void**)&xh, g_xh);
    cudaGetSymbolAddress((void**)&wqh, g_wqh);
    cudaGetSymbolAddress((void**)&wkh, g_wkh);
    cudaGetSymbolAddress((void**)&wvh, g_wvh);
    cudaGetSymbolAddress((void**)&woh, g_woh);
    cudaGetSymbolAddress((void**)&oph, g_oph);
    cudaGetSymbolAddress((void**)&qh, g_qh);
    cudaGetSymbolAddress((void**)&kh, g_kh);
    cudaGetSymbolAddress((void**)&vth, g_vth);

    cudaFuncSetAttribute(gemm_h2<false>, cudaFuncAttributeMaxDynamicSharedMemorySize,
                         GEMM_SMEM_BYTES);
    cudaFuncSetAttribute(gemm_h2<true>, cudaFuncAttributeMaxDynamicSharedMemorySize,
                         GEMM_SMEM_BYTES);
    cudaFuncSetAttribute(flash_h, cudaFuncAttributeMaxDynamicSharedMemorySize,
                         FLASH_SMEM_BYTES);

    const int NKV = HKV_ * D_;   // 1024

    // Convert inputs: x -> fp16 row-major; weights -> fp16 TRANSPOSED [N][K]
    {
        int n4 = (M_ * HID_) / 4;
        f2h_k<<<(n4 + 255) / 256, 256>>>(x, xh, n4);
        f2hT_k<<<dim3(HID_ / 32, HID_ / 32), 256>>>(wq, wqh, HID_, HID_);
        f2hT_k<<<dim3(HID_ / 32, HID_ / 32), 256>>>(wo, woh, HID_, HID_);
        f2hT_k<<<dim3(NKV / 32, HID_ / 32), 256>>>(wk, wkh, HID_, NKV);
        f2hT_k<<<dim3(NKV / 32, HID_ / 32), 256>>>(wv, wvh, HID_, NKV);
    }

    // QKV projections: Q,K fp32 out (RoPE precision), V fp16 out (direct)
    gemm_h2<false><<<dim3(HID_ / 256, M_ / 128), 256, GEMM_SMEM_BYTES>>>(xh, wqh, qp, M_, HID_, HID_);
    gemm_h2<false><<<dim3(NKV / 256, M_ / 128), 256, GEMM_SMEM_BYTES>>>(xh, wkh, kp, M_, NKV, HID_);
    gemm_h2<true ><<<dim3(NKV / 256, M_ / 128), 256, GEMM_SMEM_BYTES>>>(xh, wvh, oph, M_, NKV, HID_);

    // RoPE -> fp16 (Q pre-scaled by 1/sqrt(D)*log2e); V transpose (fp16 in)
    {
        const float qmul = 0.08838834764831845f * 1.4426950408889634f;
        int totq = B_ * S_ * H_ * (D_ / 2);
        rope_h_k<<<(totq + 255) / 256, 256>>>(qp, qh, H_, totq, qmul);
        int totk = B_ * S_ * HKV_ * (D_ / 2);
        rope_h_k<<<(totk + 255) / 256, 256>>>(kp, kh, HKV_, totk, 1.0f);
        vt_k<<<dim3(S_ / 32, D_ / 32, B_ * HKV_), 256>>>(oph, vth);
    }

    // Flash attention -> fp16 output (overwrites oph after vt consumed V)
    flash_h<<<dim3(S_ / 128, H_, B_), 256, FLASH_SMEM_BYTES>>>(qh, kh, vth, oph);

    // Output projection (fp32 out)
    gemm_h2<false><<<dim3(HID_ / 256, M_ / 128), 256, GEMM_SMEM_BYTES>>>(oph, woh, out, M_, HID_, HID_);
}

// round 15
// speedup vs baseline: 13.3300x; 1.1011x over previous
#include <cuda_runtime.h>
#include <cuda_fp16.h>
#include <cuda_bf16.h>
#include <mma.h>
#include <math.h>
#include <float.h>
#include <stdint.h>

using namespace nvcuda;

// Problem constants
#define B_  2
#define S_  2048
#define HID_ 4096
#define H_  32
#define HKV_ 8
#define D_  128
#define M_  (B_ * S_)   // 4096 rows of x

// Scratch (device globals)
__device__ float g_q[(size_t)B_ * S_ * H_ * D_];
__device__ float g_k[(size_t)B_ * S_ * HKV_ * D_];
// fp16 operands (weights stored TRANSPOSED [N][K])
__device__ __half g_xh [(size_t)M_ * HID_];
__device__ __half g_wqh[(size_t)HID_ * HID_];
__device__ __half g_wkh[(size_t)HID_ * (HKV_ * D_)];
__device__ __half g_wvh[(size_t)HID_ * (HKV_ * D_)];
__device__ __half g_woh[(size_t)HID_ * HID_];
__device__ __half g_oph[(size_t)M_ * HID_];   // first: V fp16; later: attn out fp16
__device__ __half g_qh [(size_t)B_ * S_ * H_ * D_];
__device__ __half g_kh [(size_t)B_ * S_ * HKV_ * D_];
__device__ __half g_vth[(size_t)B_ * HKV_ * D_ * S_];

// ---------------------------------------------------------------------------
// helpers
// ---------------------------------------------------------------------------
__device__ __forceinline__ uint32_t smem_u32(const void* p) {
    uint32_t a;
    asm("{ .reg .u64 t; cvta.to.shared.u64 t, %1; cvt.u32.u64 %0, t; }"
        : "=r"(a) : "l"(p));
    return a;
}
#define CP_ASYNC16(dst_u32, src_ptr) \
    asm volatile("cp.async.cg.shared.global [%0], [%1], 16;" \
                 :: "r"(dst_u32), "l"(src_ptr) : "memory")
#define CP_COMMIT() asm volatile("cp.async.commit_group;" ::: "memory")
#define CP_WAIT1()  asm volatile("cp.async.wait_group 1;" ::: "memory")
#define CP_WAIT0()  asm volatile("cp.async.wait_group 0;" ::: "memory")

__device__ __forceinline__ void mma_f16(float d[4], uint32_t a0, uint32_t a1,
                                        uint32_t a2, uint32_t a3,
                                        uint32_t b0, uint32_t b1) {
    asm volatile(
        "mma.sync.aligned.m16n8k16.row.col.f32.f16.f16.f32 "
        "{%0,%1,%2,%3}, {%4,%5,%6,%7}, {%8,%9}, {%0,%1,%2,%3};"
        : "+f"(d[0]), "+f"(d[1]), "+f"(d[2]), "+f"(d[3])
        : "r"(a0), "r"(a1), "r"(a2), "r"(a3), "r"(b0), "r"(b1));
}
__device__ __forceinline__ uint32_t pack_h2(float x, float y) {
    __half2 h = __floats2half2_rn(x, y);
    return *reinterpret_cast<uint32_t*>(&h);
}
__device__ __forceinline__ void ldsm_x4(uint32_t& r0, uint32_t& r1,
                                        uint32_t& r2, uint32_t& r3,
                                        uint32_t addr) {
    asm volatile("ldmatrix.sync.aligned.m8n8.x4.shared.b16 {%0,%1,%2,%3}, [%4];"
                 : "=r"(r0), "=r"(r1), "=r"(r2), "=r"(r3) : "r"(addr));
}

// ---------------------------------------------------------------------------
// Conversions
// ---------------------------------------------------------------------------
__global__ void f2h_k(const float* __restrict__ in,
                      __half* __restrict__ out, int n4)
{
    int i = blockIdx.x * blockDim.x + threadIdx.x;
    if (i >= n4) return;
    float4 v = reinterpret_cast<const float4*>(in)[i];
    reinterpret_cast<__half2*>(out)[2 * i]     = __floats2half2_rn(v.x, v.y);
    reinterpret_cast<__half2*>(out)[2 * i + 1] = __floats2half2_rn(v.z, v.w);
}

// Transpose + convert: in fp32 [R][C] -> out fp16 [C][R]
__global__ __launch_bounds__(256) void f2hT_k(const float* __restrict__ in,
                                              __half* __restrict__ out,
                                              int R, int C)
{
    __shared__ float t[32][33];
    const int tx = threadIdx.x & 31;
    const int ty = threadIdx.x >> 5;
    const int c0 = blockIdx.x * 32;
    const int r0 = blockIdx.y * 32;
    #pragma unroll
    for (int j = 0; j < 32; j += 8)
        t[ty + j][tx] = in[(size_t)(r0 + ty + j) * C + c0 + tx];
    __syncthreads();
    #pragma unroll
    for (int j = 0; j < 32; j += 8)
        out[(size_t)(c0 + ty + j) * R + r0 + tx] = __float2half_rn(t[tx][ty + j]);
}

// ---------------------------------------------------------------------------
// FP16 GEMM v3: C[M,N] = A[M,K](fp16) @ BT[N,K](fp16)^T, templated output.
// 128x128 block tile, BK=64, 256 threads (8 warps, 4 row x 2 col, 32x64 warp
// tile). 3-stage cp.async, 110.6KB smem -> 2 CTAs/SM for tail/bubble overlap.
// ---------------------------------------------------------------------------
constexpr int G3ST = 72;
constexpr int G3A_H = 128 * G3ST;               // 9216 halves
constexpr int G3STG_H = 2 * G3A_H;              // 18432 halves / stage
constexpr int GEMM_SMEM_BYTES = 3 * G3STG_H * 2; // 110592 B

template <bool HALF_OUT>
__global__ __launch_bounds__(256, 2) void gemm_h3(const __half* __restrict__ A,
                                                  const __half* __restrict__ BT,
                                                  void* __restrict__ Cv,
                                                  int M, int N, int K)
{
    extern __shared__ __half hsm[];
    const int tid  = threadIdx.x;
    const int warp = tid >> 5;
    const int lane = tid & 31;
    const int lr   = lane >> 2;
    const int lc   = lane & 3;
    const int g    = lane >> 3;
    const int li   = lane & 7;
    const int wr   = warp & 3;        // 0..3: 32-row strip
    const int wc   = warp >> 2;       // 0..1: 64-col strip

    const size_t bm0 = (size_t)blockIdx.y * 128;
    const size_t bn0 = (size_t)blockIdx.x * 128;
    const uint32_t sbase = smem_u32(hsm);

    auto issue_stage = [&](int slot, int k0) {
        const uint32_t sa = sbase + (uint32_t)(slot * G3STG_H) * 2u;
        const uint32_t sb = sa + (uint32_t)G3A_H * 2u;
        #pragma unroll
        for (int j = 0; j < 4; ++j) {
            int li2 = j * 256 + tid;
            int row = li2 >> 3;
            int c   = li2 & 7;
            const __half* src = A + (bm0 + row) * K + k0 + c * 8;
            CP_ASYNC16(sa + (uint32_t)(row * G3ST + c * 8) * 2u, src);
        }
        #pragma unroll
        for (int j = 0; j < 4; ++j) {
            int li2 = j * 256 + tid;
            int row = li2 >> 3;
            int c   = li2 & 7;
            const __half* src = BT + (bn0 + row) * K + k0 + c * 8;
            CP_ASYNC16(sb + (uint32_t)(row * G3ST + c * 8) * 2u, src);
        }
        CP_COMMIT();
    };

    float acc[2][8][4];
    #pragma unroll
    for (int mi = 0; mi < 2; ++mi)
        #pragma unroll
        for (int nf = 0; nf < 8; ++nf)
            #pragma unroll
            for (int e = 0; e < 4; ++e) acc[mi][nf][e] = 0.f;

    const int NIT = K >> 6;
    issue_stage(0, 0);
    issue_stage(1, 64);

    const uint32_t aoff = (uint32_t)((((g & 1) * 8 + li) * G3ST + (g >> 1) * 8) * 2);
    const uint32_t boff = (uint32_t)((((g >> 1) * 8 + li) * G3ST + (g & 1) * 8) * 2);

    for (int s = 0; s < NIT; ++s) {
        if (s >= NIT - 2) { CP_WAIT0(); } else { CP_WAIT1(); }
        __syncthreads();
        if (s + 2 < NIT) issue_stage((s + 2) % 3, (s + 2) * 64);

        const uint32_t abase = sbase + (uint32_t)((s % 3) * G3STG_H) * 2u +
                               (uint32_t)(wr * 32 * G3ST) * 2u + aoff;
        const uint32_t bbase = sbase + (uint32_t)((s % 3) * G3STG_H + G3A_H) * 2u +
                               (uint32_t)(wc * 64 * G3ST) * 2u + boff;

        #pragma unroll
        for (int ks = 0; ks < 4; ++ks) {
            uint32_t af[2][4];
            #pragma unroll
            for (int mi = 0; mi < 2; ++mi)
                ldsm_x4(af[mi][0], af[mi][1], af[mi][2], af[mi][3],
                        abase + (uint32_t)(mi * 16 * G3ST + ks * 16) * 2u);
            #pragma unroll
            for (int p = 0; p < 4; ++p) {
                uint32_t b0, b1, b2, b3;
                ldsm_x4(b0, b1, b2, b3,
                        bbase + (uint32_t)(p * 16 * G3ST + ks * 16) * 2u);
                #pragma unroll
                for (int mi = 0; mi < 2; ++mi) {
                    mma_f16(acc[mi][2 * p],     af[mi][0], af[mi][1],
                            af[mi][2], af[mi][3], b0, b1);
                    mma_f16(acc[mi][2 * p + 1], af[mi][0], af[mi][1],
                            af[mi][2], af[mi][3], b2, b3);
                }
            }
        }
    }

    // Epilogue
    #pragma unroll
    for (int mi = 0; mi < 2; ++mi) {
        const size_t r0 = bm0 + wr * 32 + mi * 16 + lr;
        #pragma unroll
        for (int nf = 0; nf < 8; ++nf) {
            const size_t col = bn0 + wc * 64 + nf * 8 + 2 * lc;
            if (HALF_OUT) {
                __half* C = (__half*)Cv;
                *reinterpret_cast<uint32_t*>(C + r0 * N + col) =
                    pack_h2(acc[mi][nf][0], acc[mi][nf][1]);
                *reinterpret_cast<uint32_t*>(C + (r0 + 8) * N + col) =
                    pack_h2(acc[mi][nf][2], acc[mi][nf][3]);
            } else {
                float* C = (float*)Cv;
                *reinterpret_cast<float2*>(C + r0 * N + col) =
                    make_float2(acc[mi][nf][0], acc[mi][nf][1]);
                *reinterpret_cast<float2*>(C + (r0 + 8) * N + col) =
                    make_float2(acc[mi][nf][2], acc[mi][nf][3]);
            }
        }
    }
}

// ---------------------------------------------------------------------------
// RoPE: read fp32, write scaled fp16.
// ---------------------------------------------------------------------------
__global__ void rope_h_k(const float* __restrict__ in, __half* __restrict__ out,
                         int nh, int total, float mul)
{
    int idx = blockIdx.x * blockDim.x + threadIdx.x;
    if (idx >= total) return;
    const int half = D_ / 2;
    int i = idx & (half - 1);
    int rest = idx >> 6;
    int h = rest % nh;
    rest /= nh;
    int s = rest % S_;
    int b = rest / S_;

    float inv = __expf(-logf(10000.0f) * (float)i / (float)half);
    float ang = (float)s * inv;
    float sn, cs;
    sincosf(ang, &sn, &cs);

    size_t base = ((size_t)((b * S_ + s) * nh + h)) * D_;
    float x1 = in[base + i];
    float x2 = in[base + i + half];
    out[base + i]        = __float2half_rn((x1 * cs - x2 * sn) * mul);
    out[base + i + half] = __float2half_rn((x2 * cs + x1 * sn) * mul);
}

// ---------------------------------------------------------------------------
// V transpose (fp16 in): [b][s][kvh][d] -> [b][kvh][d][s]
// ---------------------------------------------------------------------------
__global__ __launch_bounds__(256) void vt_k(const __half* __restrict__ in,
                                            __half* __restrict__ out)
{
    __shared__ __half t[32][34];
    const int tx = threadIdx.x & 31;
    const int ty = threadIdx.x >> 5;
    const int s0 = blockIdx.x * 32;
    const int d0 = blockIdx.y * 32;
    const int bk = blockIdx.z;
    const int b  = bk >> 3;
    const int kvh = bk & 7;

    #pragma unroll
    for (int j = 0; j < 32; j += 8)
        t[ty + j][tx] = in[((size_t)((b * S_ + s0 + ty + j) * HKV_ + kvh)) * D_ + d0 + tx];
    __syncthreads();
    #pragma unroll
    for (int j = 0; j < 32; j += 8)
        out[((size_t)(bk * D_ + d0 + ty + j)) * S_ + s0 + tx] = t[tx][ty + j];
}

// ---------------------------------------------------------------------------
// Flash attention (unchanged): fp16 mma + ldmatrix, FA2.
// ---------------------------------------------------------------------------
constexpr int KST = 136;
constexpr int VST = 72;
constexpr int QSM_HALVES = 128 * KST;
constexpr int KV_STG = 64 * KST + 128 * VST;
constexpr int FLASH_SMEM_BYTES = (QSM_HALVES + 2 * KV_STG) * 2;

__global__ __launch_bounds__(256, 2) void flash_h(const __half* __restrict__ Qg,
                                                  const __half* __restrict__ Kg,
                                                  const __half* __restrict__ Vtg,
                                                  __half* __restrict__ Og)
{
    extern __shared__ __half smh[];
    const int tid  = threadIdx.x;
    const int warp = tid >> 5;
    const int lane = tid & 31;
    const int lr   = lane >> 2;
    const int lc   = lane & 3;
    const int g    = lane >> 3;
    const int li   = lane & 7;
    const int qtile = gridDim.x - 1 - blockIdx.x;
    const int h    = blockIdx.y;
    const int b    = blockIdx.z;
    const int q0   = qtile * 128;
    const int kvh  = h >> 2;
    const uint32_t sbase = smem_u32(smh);

    #pragma unroll
    for (int it = 0; it < 8; ++it) {
        int li2  = it * 256 + tid;
        int row = li2 >> 4;
        int c   = li2 & 15;
        const __half* src = Qg + ((size_t)((b * S_ + q0 + row) * H_ + h)) * D_ + c * 8;
        CP_ASYNC16(sbase + (uint32_t)(row * KST + c * 8) * 2u, src);
    }
    CP_COMMIT();

    float d[16][4];
    #pragma unroll
    for (int i = 0; i < 16; ++i)
        #pragma unroll
        for (int j = 0; j < 4; ++j) d[i][j] = 0.f;
    float m0 = -1e30f, m1 = -1e30f, l0 = 0.f, l1 = 0.f;

    auto issue_kv = [&](int t) {
        const int s = t & 1;
        const uint32_t kb = sbase + (uint32_t)(QSM_HALVES + s * KV_STG) * 2u;
        const uint32_t vb = kb + (uint32_t)(64 * KST) * 2u;
        const int kv0 = t * 64;
        #pragma unroll
        for (int it = 0; it < 4; ++it) {
            int li2  = it * 256 + tid;
            int row = li2 >> 4;
            int c   = li2 & 15;
            const __half* src = Kg + ((size_t)((b * S_ + kv0 + row) * HKV_ + kvh)) * D_ + c * 8;
            CP_ASYNC16(kb + (uint32_t)(row * KST + c * 8) * 2u, src);
        }
        #pragma unroll
        for (int it = 0; it < 4; ++it) {
            int li2  = it * 256 + tid;
            int row = li2 >> 3;
            int c   = li2 & 7;
            const __half* src = Vtg + ((size_t)((b * HKV_ + kvh) * D_ + row)) * S_ + kv0 + c * 8;
            CP_ASYNC16(vb + (uint32_t)(row * VST + c * 8) * 2u, src);
        }
        CP_COMMIT();
    };

    const int tmax = 2 * qtile + 1;
    const int wrow_lo = q0 + warp * 16;
    const int wrow_hi = wrow_lo + 15;
    const uint32_t qaddr = sbase +
        (uint32_t)(((warp * 16 + (g & 1) * 8 + li) * KST + (g >> 1) * 8) * 2);
    issue_kv(0);

    for (int t = 0; t <= tmax; ++t) {
        CP_WAIT0();
        __syncthreads();
        if (t < tmax) issue_kv(t + 1);

        const int kv0 = t * 64;
        if (kv0 <= wrow_hi) {
            const uint32_t kwb = sbase +
                (uint32_t)((QSM_HALVES + (t & 1) * KV_STG) * 2);
            const uint32_t kaddr = kwb +
                (uint32_t)((((g >> 1) * 8 + li) * KST + (g & 1) * 8) * 2);
            const uint32_t vaddr = kwb + (uint32_t)(64 * KST * 2) +
                (uint32_t)((((g >> 1) * 8 + li) * VST + (g & 1) * 8) * 2);

            float s[8][4];
            #pragma unroll
            for (int nf = 0; nf < 8; ++nf)
                #pragma unroll
                for (int e = 0; e < 4; ++e) s[nf][e] = 0.f;
            #pragma unroll
            for (int j = 0; j < 8; ++j) {
                uint32_t qa0, qa1, qa2, qa3;
                ldsm_x4(qa0, qa1, qa2, qa3, qaddr + j * 32);
                #pragma unroll
                for (int nfp = 0; nfp < 4; ++nfp) {
                    uint32_t kb0, kb1, kb2, kb3;
                    ldsm_x4(kb0, kb1, kb2, kb3,
                            kaddr + nfp * (16 * KST * 2) + j * 32);
                    mma_f16(s[2 * nfp],     qa0, qa1, qa2, qa3, kb0, kb1);
                    mma_f16(s[2 * nfp + 1], qa0, qa1, qa2, qa3, kb2, kb3);
                }
            }

            if (kv0 + 63 > wrow_lo) {
                const int row0 = wrow_lo + lr;
                #pragma unroll
                for (int nf = 0; nf < 8; ++nf) {
                    int c0 = kv0 + 8 * nf + 2 * lc;
                    if (c0 > row0)         s[nf][0] = -1e30f;
                    if (c0 + 1 > row0)     s[nf][1] = -1e30f;
                    if (c0 > row0 + 8)     s[nf][2] = -1e30f;
                    if (c0 + 1 > row0 + 8) s[nf][3] = -1e30f;
                }
            }

            float mx0 = -1e30f, mx1 = -1e30f;
            #pragma unroll
            for (int nf = 0; nf < 8; ++nf) {
                mx0 = fmaxf(mx0, fmaxf(s[nf][0], s[nf][1]));
                mx1 = fmaxf(mx1, fmaxf(s[nf][2], s[nf][3]));
            }
            mx0 = fmaxf(mx0, __shfl_xor_sync(0xFFFFFFFFu, mx0, 1));
            mx0 = fmaxf(mx0, __shfl_xor_sync(0xFFFFFFFFu, mx0, 2));
            mx1 = fmaxf(mx1, __shfl_xor_sync(0xFFFFFFFFu, mx1, 1));
            mx1 = fmaxf(mx1, __shfl_xor_sync(0xFFFFFFFFu, mx1, 2));
            float m0n = fmaxf(m0, mx0), m1n = fmaxf(m1, mx1);
            float al0 = exp2f(m0 - m0n), al1 = exp2f(m1 - m1n);
            float su0 = 0.f, su1 = 0.f;
            #pragma unroll
            for (int nf = 0; nf < 8; ++nf) {
                s[nf][0] = exp2f(s[nf][0] - m0n);
                s[nf][1] = exp2f(s[nf][1] - m0n);
                s[nf][2] = exp2f(s[nf][2] - m1n);
                s[nf][3] = exp2f(s[nf][3] - m1n);
                su0 += s[nf][0] + s[nf][1];
                su1 += s[nf][2] + s[nf][3];
            }
            su0 += __shfl_xor_sync(0xFFFFFFFFu, su0, 1);
            su0 += __shfl_xor_sync(0xFFFFFFFFu, su0, 2);
            su1 += __shfl_xor_sync(0xFFFFFFFFu, su1, 1);
            su1 += __shfl_xor_sync(0xFFFFFFFFu, su1, 2);
            l0 = l0 * al0 + su0;  m0 = m0n;
            l1 = l1 * al1 + su1;  m1 = m1n;

            #pragma unroll
            for (int nf = 0; nf < 16; ++nf) {
                d[nf][0] *= al0; d[nf][1] *= al0;
                d[nf][2] *= al1; d[nf][3] *= al1;
            }

            #pragma unroll
            for (int j = 0; j < 4; ++j) {
                uint32_t pa0 = pack_h2(s[2*j][0],   s[2*j][1]);
                uint32_t pa1 = pack_h2(s[2*j][2],   s[2*j][3]);
                uint32_t pa2 = pack_h2(s[2*j+1][0], s[2*j+1][1]);
                uint32_t pa3 = pack_h2(s[2*j+1][2], s[2*j+1][3]);
                #pragma unroll
                for (int nfp = 0; nfp < 8; ++nfp) {
                    uint32_t vb0, vb1, vb2, vb3;
                    ldsm_x4(vb0, vb1, vb2, vb3,
                            vaddr + nfp * (16 * VST * 2) + j * 32);
                    mma_f16(d[2 * nfp],     pa0, pa1, pa2, pa3, vb0, vb1);
                    mma_f16(d[2 * nfp + 1], pa0, pa1, pa2, pa3, vb2, vb3);
                }
            }
        }
    }

    const float il0 = 1.f / l0, il1 = 1.f / l1;
    const int row0 = q0 + warp * 16 + lr;
    __half* o0 = Og + ((size_t)((b * S_ + row0) * H_ + h)) * D_;
    __half* o1 = Og + ((size_t)((b * S_ + row0 + 8) * H_ + h)) * D_;
    #pragma unroll
    for (int nf = 0; nf < 16; ++nf) {
        *reinterpret_cast<uint32_t*>(o0 + 8 * nf + 2 * lc) =
            pack_h2(d[nf][0] * il0, d[nf][1] * il0);
        *reinterpret_cast<uint32_t*>(o1 + 8 * nf + 2 * lc) =
            pack_h2(d[nf][2] * il1, d[nf][3] * il1);
    }
}

// ---------------------------------------------------------------------------
// Launcher
// ---------------------------------------------------------------------------
extern "C" void kernel_launch(void* const* d_in, const int* in_sizes, int n_in,
                              void* d_out, int out_size)
{
    const float* x  = (const float*)d_in[0];
    const float* wq = (const float*)d_in[1];
    const float* wk = (const float*)d_in[2];
    const float* wv = (const float*)d_in[3];
    const float* wo = (const float*)d_in[4];
    float* out = (float*)d_out;

    float *qp, *kp;
    __half *xh, *wqh, *wkh, *wvh, *woh, *oph, *qh, *kh, *vth;
    cudaGetSymbolAddress((void**)&qp, g_q);
    cudaGetSymbolAddress((void**)&kp, g_k);
    cudaGetSymbolAddress((void**)&xh, g_xh);
    cudaGetSymbolAddress((void**)&wqh, g_wqh);
    cudaGetSymbolAddress((void**)&wkh, g_wkh);
    cudaGetSymbolAddress((void**)&wvh, g_wvh);
    cudaGetSymbolAddress((void**)&woh, g_woh);
    cudaGetSymbolAddress((void**)&oph, g_oph);
    cudaGetSymbolAddress((void**)&qh, g_qh);
    cudaGetSymbolAddress((void**)&kh, g_kh);
    cudaGetSymbolAddress((void**)&vth, g_vth);

    cudaFuncSetAttribute(gemm_h3<false>, cudaFuncAttributeMaxDynamicSharedMemorySize,
                         GEMM_SMEM_BYTES);
    cudaFuncSetAttribute(gemm_h3<true>, cudaFuncAttributeMaxDynamicSharedMemorySize,
                         GEMM_SMEM_BYTES);
    cudaFuncSetAttribute(flash_h, cudaFuncAttributeMaxDynamicSharedMemorySize,
                         FLASH_SMEM_BYTES);

    const int NKV = HKV_ * D_;   // 1024

    // Convert inputs: x -> fp16 row-major; weights -> fp16 TRANSPOSED [N][K]
    {
        int n4 = (M_ * HID_) / 4;
        f2h_k<<<(n4 + 255) / 256, 256>>>(x, xh, n4);
        f2hT_k<<<dim3(HID_ / 32, HID_ / 32), 256>>>(wq, wqh, HID_, HID_);
        f2hT_k<<<dim3(HID_ / 32, HID_ / 32), 256>>>(wo, woh, HID_, HID_);
        f2hT_k<<<dim3(NKV / 32, HID_ / 32), 256>>>(wk, wkh, HID_, NKV);
        f2hT_k<<<dim3(NKV / 32, HID_ / 32), 256>>>(wv, wvh, HID_, NKV);
    }

    // QKV projections: Q,K fp32 out (RoPE precision), V fp16 out (direct)
    gemm_h3<false><<<dim3(HID_ / 128, M_ / 128), 256, GEMM_SMEM_BYTES>>>(xh, wqh, qp, M_, HID_, HID_);
    gemm_h3<false><<<dim3(NKV / 128, M_ / 128), 256, GEMM_SMEM_BYTES>>>(xh, wkh, kp, M_, NKV, HID_);
    gemm_h3<true ><<<dim3(NKV / 128, M_ / 128), 256, GEMM_SMEM_BYTES>>>(xh, wvh, oph, M_, NKV, HID_);

    // RoPE -> fp16 (Q pre-scaled by 1/sqrt(D)*log2e); V transpose (fp16 in)
    {
        const float qmul = 0.08838834764831845f * 1.4426950408889634f;
        int totq = B_ * S_ * H_ * (D_ / 2);
        rope_h_k<<<(totq + 255) / 256, 256>>>(qp, qh, H_, totq, qmul);
        int totk = B_ * S_ * HKV_ * (D_ / 2);
        rope_h_k<<<(totk + 255) / 256, 256>>>(kp, kh, HKV_, totk, 1.0f);
        vt_k<<<dim3(S_ / 32, D_ / 32, B_ * HKV_), 256>>>(oph, vth);
    }

    // Flash attention -> fp16 output (overwrites oph after vt consumed V)
    flash_h<<<dim3(S_ / 128, H_, B_), 256, FLASH_SMEM_BYTES>>>(qh, kh, vth, oph);

    // Output projection (fp32 out)
    gemm_h3<false><<<dim3(HID_ / 128, M_ / 128), 256, GEMM_SMEM_BYTES>>>(oph, woh, out, M_, HID_, HID_);
}

// round 16
// speedup vs baseline: 13.4604x; 1.0098x over previous
#include <cuda_runtime.h>
#include <cuda_fp16.h>
#include <cuda_bf16.h>
#include <mma.h>
#include <math.h>
#include <float.h>
#include <stdint.h>

using namespace nvcuda;

// Problem constants
#define B_  2
#define S_  2048
#define HID_ 4096
#define H_  32
#define HKV_ 8
#define D_  128
#define M_  (B_ * S_)   // 4096 rows of x
#define NKV_ (HKV_ * D_)  // 1024

// Scratch (device globals)
__device__ __half g_xh  [(size_t)M_ * HID_];
__device__ __half g_wqh [(size_t)HID_ * HID_];
__device__ __half g_wkvh[(size_t)(2 * NKV_) * HID_];   // [K rows | V rows] x [K]
__device__ __half g_woh [(size_t)HID_ * HID_];
__device__ __half g_oph [(size_t)M_ * HID_];   // phase 1: fused KV out [M][2048]; phase 2: attn out [M][4096]
__device__ __half g_qh  [(size_t)B_ * S_ * H_ * D_];
__device__ __half g_kh  [(size_t)B_ * S_ * HKV_ * D_];
__device__ __half g_vth [(size_t)B_ * HKV_ * D_ * S_];

// ---------------------------------------------------------------------------
// helpers
// ---------------------------------------------------------------------------
__device__ __forceinline__ uint32_t smem_u32(const void* p) {
    uint32_t a;
    asm("{ .reg .u64 t; cvta.to.shared.u64 t, %1; cvt.u32.u64 %0, t; }"
        : "=r"(a) : "l"(p));
    return a;
}
#define CP_ASYNC16(dst_u32, src_ptr) \
    asm volatile("cp.async.cg.shared.global [%0], [%1], 16;" \
                 :: "r"(dst_u32), "l"(src_ptr) : "memory")
#define CP_COMMIT() asm volatile("cp.async.commit_group;" ::: "memory")
#define CP_WAIT1()  asm volatile("cp.async.wait_group 1;" ::: "memory")
#define CP_WAIT0()  asm volatile("cp.async.wait_group 0;" ::: "memory")

__device__ __forceinline__ void mma_f16(float d[4], uint32_t a0, uint32_t a1,
                                        uint32_t a2, uint32_t a3,
                                        uint32_t b0, uint32_t b1) {
    asm volatile(
        "mma.sync.aligned.m16n8k16.row.col.f32.f16.f16.f32 "
        "{%0,%1,%2,%3}, {%4,%5,%6,%7}, {%8,%9}, {%0,%1,%2,%3};"
        : "+f"(d[0]), "+f"(d[1]), "+f"(d[2]), "+f"(d[3])
        : "r"(a0), "r"(a1), "r"(a2), "r"(a3), "r"(b0), "r"(b1));
}
__device__ __forceinline__ uint32_t pack_h2(float x, float y) {
    __half2 h = __floats2half2_rn(x, y);
    return *reinterpret_cast<uint32_t*>(&h);
}
__device__ __forceinline__ void ldsm_x4(uint32_t& r0, uint32_t& r1,
                                        uint32_t& r2, uint32_t& r3,
                                        uint32_t addr) {
    asm volatile("ldmatrix.sync.aligned.m8n8.x4.shared.b16 {%0,%1,%2,%3}, [%4];"
                 : "=r"(r0), "=r"(r1), "=r"(r2), "=r"(r3) : "r"(addr));
}

// ---------------------------------------------------------------------------
// Conversions
// ---------------------------------------------------------------------------
__global__ void f2h_k(const float* __restrict__ in,
                      __half* __restrict__ out, int n4)
{
    int i = blockIdx.x * blockDim.x + threadIdx.x;
    if (i >= n4) return;
    float4 v = reinterpret_cast<const float4*>(in)[i];
    reinterpret_cast<__half2*>(out)[2 * i]     = __floats2half2_rn(v.x, v.y);
    reinterpret_cast<__half2*>(out)[2 * i + 1] = __floats2half2_rn(v.z, v.w);
}

// Transpose + convert: in fp32 [R][C] -> out fp16 [C][R]
__global__ __launch_bounds__(256) void f2hT_k(const float* __restrict__ in,
                                              __half* __restrict__ out,
                                              int R, int C)
{
    __shared__ float t[32][33];
    const int tx = threadIdx.x & 31;
    const int ty = threadIdx.x >> 5;
    const int c0 = blockIdx.x * 32;
    const int r0 = blockIdx.y * 32;
    #pragma unroll
    for (int j = 0; j < 32; j += 8)
        t[ty + j][tx] = in[(size_t)(r0 + ty + j) * C + c0 + tx];
    __syncthreads();
    #pragma unroll
    for (int j = 0; j < 32; j += 8)
        out[(size_t)(c0 + ty + j) * R + r0 + tx] = __float2half_rn(t[tx][ty + j]);
}

// ---------------------------------------------------------------------------
// FP16 GEMM: C[M,N] = A[M,K](fp16) @ BT[N,K](fp16)^T, templated output.
// 128x128 block tile, BK=64, 256 threads (8 warps, 4x2, 32x64 warp tile).
// 3-stage cp.async, 110.6KB smem -> 2 CTAs/SM.
// ---------------------------------------------------------------------------
constexpr int G3ST = 72;
constexpr int G3A_H = 128 * G3ST;
constexpr int G3STG_H = 2 * G3A_H;
constexpr int GEMM_SMEM_BYTES = 3 * G3STG_H * 2;

template <bool HALF_OUT>
__global__ __launch_bounds__(256, 2) void gemm_h3(const __half* __restrict__ A,
                                                  const __half* __restrict__ BT,
                                                  void* __restrict__ Cv,
                                                  int M, int N, int K)
{
    extern __shared__ __half hsm[];
    const int tid  = threadIdx.x;
    const int warp = tid >> 5;
    const int lane = tid & 31;
    const int lr   = lane >> 2;
    const int lc   = lane & 3;
    const int g    = lane >> 3;
    const int li   = lane & 7;
    const int wr   = warp & 3;
    const int wc   = warp >> 2;

    const size_t bm0 = (size_t)blockIdx.y * 128;
    const size_t bn0 = (size_t)blockIdx.x * 128;
    const uint32_t sbase = smem_u32(hsm);

    auto issue_stage = [&](int slot, int k0) {
        const uint32_t sa = sbase + (uint32_t)(slot * G3STG_H) * 2u;
        const uint32_t sb = sa + (uint32_t)G3A_H * 2u;
        #pragma unroll
        for (int j = 0; j < 4; ++j) {
            int li2 = j * 256 + tid;
            int row = li2 >> 3;
            int c   = li2 & 7;
            const __half* src = A + (bm0 + row) * K + k0 + c * 8;
            CP_ASYNC16(sa + (uint32_t)(row * G3ST + c * 8) * 2u, src);
        }
        #pragma unroll
        for (int j = 0; j < 4; ++j) {
            int li2 = j * 256 + tid;
            int row = li2 >> 3;
            int c   = li2 & 7;
            const __half* src = BT + (bn0 + row) * K + k0 + c * 8;
            CP_ASYNC16(sb + (uint32_t)(row * G3ST + c * 8) * 2u, src);
        }
        CP_COMMIT();
    };

    float acc[2][8][4];
    #pragma unroll
    for (int mi = 0; mi < 2; ++mi)
        #pragma unroll
        for (int nf = 0; nf < 8; ++nf)
            #pragma unroll
            for (int e = 0; e < 4; ++e) acc[mi][nf][e] = 0.f;

    const int NIT = K >> 6;
    issue_stage(0, 0);
    issue_stage(1, 64);

    const uint32_t aoff = (uint32_t)((((g & 1) * 8 + li) * G3ST + (g >> 1) * 8) * 2);
    const uint32_t boff = (uint32_t)((((g >> 1) * 8 + li) * G3ST + (g & 1) * 8) * 2);

    for (int s = 0; s < NIT; ++s) {
        if (s >= NIT - 2) { CP_WAIT0(); } else { CP_WAIT1(); }
        __syncthreads();
        if (s + 2 < NIT) issue_stage((s + 2) % 3, (s + 2) * 64);

        const uint32_t abase = sbase + (uint32_t)((s % 3) * G3STG_H) * 2u +
                               (uint32_t)(wr * 32 * G3ST) * 2u + aoff;
        const uint32_t bbase = sbase + (uint32_t)((s % 3) * G3STG_H + G3A_H) * 2u +
                               (uint32_t)(wc * 64 * G3ST) * 2u + boff;

        #pragma unroll
        for (int ks = 0; ks < 4; ++ks) {
            uint32_t af[2][4];
            #pragma unroll
            for (int mi = 0; mi < 2; ++mi)
                ldsm_x4(af[mi][0], af[mi][1], af[mi][2], af[mi][3],
                        abase + (uint32_t)(mi * 16 * G3ST + ks * 16) * 2u);
            #pragma unroll
            for (int p = 0; p < 4; ++p) {
                uint32_t b0, b1, b2, b3;
                ldsm_x4(b0, b1, b2, b3,
                        bbase + (uint32_t)(p * 16 * G3ST + ks * 16) * 2u);
                #pragma unroll
                for (int mi = 0; mi < 2; ++mi) {
                    mma_f16(acc[mi][2 * p],     af[mi][0], af[mi][1],
                            af[mi][2], af[mi][3], b0, b1);
                    mma_f16(acc[mi][2 * p + 1], af[mi][0], af[mi][1],
                            af[mi][2], af[mi][3], b2, b3);
                }
            }
        }
    }

    // Epilogue
    #pragma unroll
    for (int mi = 0; mi < 2; ++mi) {
        const size_t r0 = bm0 + wr * 32 + mi * 16 + lr;
        #pragma unroll
        for (int nf = 0; nf < 8; ++nf) {
            const size_t col = bn0 + wc * 64 + nf * 8 + 2 * lc;
            if (HALF_OUT) {
                __half* C = (__half*)Cv;
                *reinterpret_cast<uint32_t*>(C + r0 * N + col) =
                    pack_h2(acc[mi][nf][0], acc[mi][nf][1]);
                *reinterpret_cast<uint32_t*>(C + (r0 + 8) * N + col) =
                    pack_h2(acc[mi][nf][2], acc[mi][nf][3]);
            } else {
                float* C = (float*)Cv;
                *reinterpret_cast<float2*>(C + r0 * N + col) =
                    make_float2(acc[mi][nf][0], acc[mi][nf][1]);
                *reinterpret_cast<float2*>(C + (r0 + 8) * N + col) =
                    make_float2(acc[mi][nf][2], acc[mi][nf][3]);
            }
        }
    }
}

// ---------------------------------------------------------------------------
// RoPE fp16->fp16: reads in[(b*S+s)*in_row + col_off + h*D + i], rotation in
// fp32, writes out in standard [b,s,nh,D] layout (scaled by mul).
// For Q: in == out (in-place, identical addressing).
// ---------------------------------------------------------------------------
__global__ void rope_hh_k(const __half* __restrict__ in, __half* __restrict__ out,
                          int nh, int in_row, int col_off, int total, float mul)
{
    int idx = blockIdx.x * blockDim.x + threadIdx.x;
    if (idx >= total) return;
    const int half = D_ / 2;
    int i = idx & (half - 1);
    int rest = idx >> 6;
    int h = rest % nh;
    rest /= nh;
    int s = rest % S_;
    int b = rest / S_;

    float inv = __expf(-logf(10000.0f) * (float)i / (float)half);
    float ang = (float)s * inv;
    float sn, cs;
    sincosf(ang, &sn, &cs);

    size_t ib = (size_t)(b * S_ + s) * in_row + col_off + h * D_;
    float x1 = __half2float(in[ib + i]);
    float x2 = __half2float(in[ib + i + half]);
    size_t ob = ((size_t)((b * S_ + s) * nh + h)) * D_;
    out[ob + i]        = __float2half_rn((x1 * cs - x2 * sn) * mul);
    out[ob + i + half] = __float2half_rn((x2 * cs + x1 * sn) * mul);
}

// ---------------------------------------------------------------------------
// V transpose from fused-KV buffer: in[(b*S+s)*2048 + 1024 + kvh*128 + d]
// -> out [b][kvh][d][s]
// ---------------------------------------------------------------------------
__global__ __launch_bounds__(256) void vt_kv_k(const __half* __restrict__ in,
                                               __half* __restrict__ out)
{
    __shared__ __half t[32][34];
    const int tx = threadIdx.x & 31;
    const int ty = threadIdx.x >> 5;
    const int s0 = blockIdx.x * 32;
    const int d0 = blockIdx.y * 32;
    const int bk = blockIdx.z;
    const int b  = bk >> 3;
    const int kvh = bk & 7;

    #pragma unroll
    for (int j = 0; j < 32; j += 8)
        t[ty + j][tx] = in[(size_t)(b * S_ + s0 + ty + j) * (2 * NKV_) +
                           NKV_ + kvh * D_ + d0 + tx];
    __syncthreads();
    #pragma unroll
    for (int j = 0; j < 32; j += 8)
        out[((size_t)(bk * D_ + d0 + ty + j)) * S_ + s0 + tx] = t[tx][ty + j];
}

// ---------------------------------------------------------------------------
// Flash attention (unchanged): fp16 mma + ldmatrix, FA2.
// ---------------------------------------------------------------------------
constexpr int KST = 136;
constexpr int VST = 72;
constexpr int QSM_HALVES = 128 * KST;
constexpr int KV_STG = 64 * KST + 128 * VST;
constexpr int FLASH_SMEM_BYTES = (QSM_HALVES + 2 * KV_STG) * 2;

__global__ __launch_bounds__(256, 2) void flash_h(const __half* __restrict__ Qg,
                                                  const __half* __restrict__ Kg,
                                                  const __half* __restrict__ Vtg,
                                                  __half* __restrict__ Og)
{
    extern __shared__ __half smh[];
    const int tid  = threadIdx.x;
    const int warp = tid >> 5;
    const int lane = tid & 31;
    const int lr   = lane >> 2;
    const int lc   = lane & 3;
    const int g    = lane >> 3;
    const int li   = lane & 7;
    const int qtile = gridDim.x - 1 - blockIdx.x;
    const int h    = blockIdx.y;
    const int b    = blockIdx.z;
    const int q0   = qtile * 128;
    const int kvh  = h >> 2;
    const uint32_t sbase = smem_u32(smh);

    #pragma unroll
    for (int it = 0; it < 8; ++it) {
        int li2  = it * 256 + tid;
        int row = li2 >> 4;
        int c   = li2 & 15;
        const __half* src = Qg + ((size_t)((b * S_ + q0 + row) * H_ + h)) * D_ + c * 8;
        CP_ASYNC16(sbase + (uint32_t)(row * KST + c * 8) * 2u, src);
    }
    CP_COMMIT();

    float d[16][4];
    #pragma unroll
    for (int i = 0; i < 16; ++i)
        #pragma unroll
        for (int j = 0; j < 4; ++j) d[i][j] = 0.f;
    float m0 = -1e30f, m1 = -1e30f, l0 = 0.f, l1 = 0.f;

    auto issue_kv = [&](int t) {
        const int s = t & 1;
        const uint32_t kb = sbase + (uint32_t)(QSM_HALVES + s * KV_STG) * 2u;
        const uint32_t vb = kb + (uint32_t)(64 * KST) * 2u;
        const int kv0 = t * 64;
        #pragma unroll
        for (int it = 0; it < 4; ++it) {
            int li2  = it * 256 + tid;
            int row = li2 >> 4;
            int c   = li2 & 15;
            const __half* src = Kg + ((size_t)((b * S_ + kv0 + row) * HKV_ + kvh)) * D_ + c * 8;
            CP_ASYNC16(kb + (uint32_t)(row * KST + c * 8) * 2u, src);
        }
        #pragma unroll
        for (int it = 0; it < 4; ++it) {
            int li2  = it * 256 + tid;
            int row = li2 >> 3;
            int c   = li2 & 7;
            const __half* src = Vtg + ((size_t)((b * HKV_ + kvh) * D_ + row)) * S_ + kv0 + c * 8;
            CP_ASYNC16(vb + (uint32_t)(row * VST + c * 8) * 2u, src);
        }
        CP_COMMIT();
    };

    const int tmax = 2 * qtile + 1;
    const int wrow_lo = q0 + warp * 16;
    const int wrow_hi = wrow_lo + 15;
    const uint32_t qaddr = sbase +
        (uint32_t)(((warp * 16 + (g & 1) * 8 + li) * KST + (g >> 1) * 8) * 2);
    issue_kv(0);

    for (int t = 0; t <= tmax; ++t) {
        CP_WAIT0();
        __syncthreads();
        if (t < tmax) issue_kv(t + 1);

        const int kv0 = t * 64;
        if (kv0 <= wrow_hi) {
            const uint32_t kwb = sbase +
                (uint32_t)((QSM_HALVES + (t & 1) * KV_STG) * 2);
            const uint32_t kaddr = kwb +
                (uint32_t)((((g >> 1) * 8 + li) * KST + (g & 1) * 8) * 2);
            const uint32_t vaddr = kwb + (uint32_t)(64 * KST * 2) +
                (uint32_t)((((g >> 1) * 8 + li) * VST + (g & 1) * 8) * 2);

            float s[8][4];
            #pragma unroll
            for (int nf = 0; nf < 8; ++nf)
                #pragma unroll
                for (int e = 0; e < 4; ++e) s[nf][e] = 0.f;
            #pragma unroll
            for (int j = 0; j < 8; ++j) {
                uint32_t qa0, qa1, qa2, qa3;
                ldsm_x4(qa0, qa1, qa2, qa3, qaddr + j * 32);
                #pragma unroll
                for (int nfp = 0; nfp < 4; ++nfp) {
                    uint32_t kb0, kb1, kb2, kb3;
                    ldsm_x4(kb0, kb1, kb2, kb3,
                            kaddr + nfp * (16 * KST * 2) + j * 32);
                    mma_f16(s[2 * nfp],     qa0, qa1, qa2, qa3, kb0, kb1);
                    mma_f16(s[2 * nfp + 1], qa0, qa1, qa2, qa3, kb2, kb3);
                }
            }

            if (kv0 + 63 > wrow_lo) {
                const int row0 = wrow_lo + lr;
                #pragma unroll
                for (int nf = 0; nf < 8; ++nf) {
                    int c0 = kv0 + 8 * nf + 2 * lc;
                    if (c0 > row0)         s[nf][0] = -1e30f;
                    if (c0 + 1 > row0)     s[nf][1] = -1e30f;
                    if (c0 > row0 + 8)     s[nf][2] = -1e30f;
                    if (c0 + 1 > row0 + 8) s[nf][3] = -1e30f;
                }
            }

            float mx0 = -1e30f, mx1 = -1e30f;
            #pragma unroll
            for (int nf = 0; nf < 8; ++nf) {
                mx0 = fmaxf(mx0, fmaxf(s[nf][0], s[nf][1]));
                mx1 = fmaxf(mx1, fmaxf(s[nf][2], s[nf][3]));
            }
            mx0 = fmaxf(mx0, __shfl_xor_sync(0xFFFFFFFFu, mx0, 1));
            mx0 = fmaxf(mx0, __shfl_xor_sync(0xFFFFFFFFu, mx0, 2));
            mx1 = fmaxf(mx1, __shfl_xor_sync(0xFFFFFFFFu, mx1, 1));
            mx1 = fmaxf(mx1, __shfl_xor_sync(0xFFFFFFFFu, mx1, 2));
            float m0n = fmaxf(m0, mx0), m1n = fmaxf(m1, mx1);
            float al0 = exp2f(m0 - m0n), al1 = exp2f(m1 - m1n);
            float su0 = 0.f, su1 = 0.f;
            #pragma unroll
            for (int nf = 0; nf < 8; ++nf) {
                s[nf][0] = exp2f(s[nf][0] - m0n);
                s[nf][1] = exp2f(s[nf][1] - m0n);
                s[nf][2] = exp2f(s[nf][2] - m1n);
                s[nf][3] = exp2f(s[nf][3] - m1n);
                su0 += s[nf][0] + s[nf][1];
                su1 += s[nf][2] + s[nf][3];
            }
            su0 += __shfl_xor_sync(0xFFFFFFFFu, su0, 1);
            su0 += __shfl_xor_sync(0xFFFFFFFFu, su0, 2);
            su1 += __shfl_xor_sync(0xFFFFFFFFu, su1, 1);
            su1 += __shfl_xor_sync(0xFFFFFFFFu, su1, 2);
            l0 = l0 * al0 + su0;  m0 = m0n;
            l1 = l1 * al1 + su1;  m1 = m1n;

            #pragma unroll
            for (int nf = 0; nf < 16; ++nf) {
                d[nf][0] *= al0; d[nf][1] *= al0;
                d[nf][2] *= al1; d[nf][3] *= al1;
            }

            #pragma unroll
            for (int j = 0; j < 4; ++j) {
                uint32_t pa0 = pack_h2(s[2*j][0],   s[2*j][1]);
                uint32_t pa1 = pack_h2(s[2*j][2],   s[2*j][3]);
                uint32_t pa2 = pack_h2(s[2*j+1][0], s[2*j+1][1]);
                uint32_t pa3 = pack_h2(s[2*j+1][2], s[2*j+1][3]);
                #pragma unroll
                for (int nfp = 0; nfp < 8; ++nfp) {
                    uint32_t vb0, vb1, vb2, vb3;
                    ldsm_x4(vb0, vb1, vb2, vb3,
                            vaddr + nfp * (16 * VST * 2) + j * 32);
                    mma_f16(d[2 * nfp],     pa0, pa1, pa2, pa3, vb0, vb1);
                    mma_f16(d[2 * nfp + 1], pa0, pa1, pa2, pa3, vb2, vb3);
                }
            }
        }
    }

    const float il0 = 1.f / l0, il1 = 1.f / l1;
    const int row0 = q0 + warp * 16 + lr;
    __half* o0 = Og + ((size_t)((b * S_ + row0) * H_ + h)) * D_;
    __half* o1 = Og + ((size_t)((b * S_ + row0 + 8) * H_ + h)) * D_;
    #pragma unroll
    for (int nf = 0; nf < 16; ++nf) {
        *reinterpret_cast<uint32_t*>(o0 + 8 * nf + 2 * lc) =
            pack_h2(d[nf][0] * il0, d[nf][1] * il0);
        *reinterpret_cast<uint32_t*>(o1 + 8 * nf + 2 * lc) =
            pack_h2(d[nf][2] * il1, d[nf][3] * il1);
    }
}

// ---------------------------------------------------------------------------
// Launcher
// ---------------------------------------------------------------------------
extern "C" void kernel_launch(void* const* d_in, const int* in_sizes, int n_in,
                              void* d_out, int out_size)
{
    const float* x  = (const float*)d_in[0];
    const float* wq = (const float*)d_in[1];
    const float* wk = (const float*)d_in[2];
    const float* wv = (const float*)d_in[3];
    const float* wo = (const float*)d_in[4];
    float* out = (float*)d_out;

    __half *xh, *wqh, *wkvh, *woh, *oph, *qh, *kh, *vth;
    cudaGetSymbolAddress((void**)&xh, g_xh);
    cudaGetSymbolAddress((void**)&wqh, g_wqh);
    cudaGetSymbolAddress((void**)&wkvh, g_wkvh);
    cudaGetSymbolAddress((void**)&woh, g_woh);
    cudaGetSymbolAddress((void**)&oph, g_oph);
    cudaGetSymbolAddress((void**)&qh, g_qh);
    cudaGetSymbolAddress((void**)&kh, g_kh);
    cudaGetSymbolAddress((void**)&vth, g_vth);

    cudaFuncSetAttribute(gemm_h3<false>, cudaFuncAttributeMaxDynamicSharedMemorySize,
                         GEMM_SMEM_BYTES);
    cudaFuncSetAttribute(gemm_h3<true>, cudaFuncAttributeMaxDynamicSharedMemorySize,
                         GEMM_SMEM_BYTES);
    cudaFuncSetAttribute(flash_h, cudaFuncAttributeMaxDynamicSharedMemorySize,
                         FLASH_SMEM_BYTES);

    // Convert inputs: x -> fp16 row-major; weights -> fp16 TRANSPOSED [N][K],
    // K/V weights concatenated into one [2*NKV][HID] buffer.
    {
        int n4 = (M_ * HID_) / 4;
        f2h_k<<<(n4 + 255) / 256, 256>>>(x, xh, n4);
        f2hT_k<<<dim3(HID_ / 32, HID_ / 32), 256>>>(wq, wqh, HID_, HID_);
        f2hT_k<<<dim3(HID_ / 32, HID_ / 32), 256>>>(wo, woh, HID_, HID_);
        f2hT_k<<<dim3(NKV_ / 32, HID_ / 32), 256>>>(wk, wkvh, HID_, NKV_);
        f2hT_k<<<dim3(NKV_ / 32, HID_ / 32), 256>>>(wv, wkvh + (size_t)NKV_ * HID_, HID_, NKV_);
    }

    // Projections: Q -> qh (fp16, pre-rope); fused K|V -> oph[M][2048] (fp16)
    gemm_h3<true><<<dim3(HID_ / 128, M_ / 128), 256, GEMM_SMEM_BYTES>>>(xh, wqh, qh, M_, HID_, HID_);
    gemm_h3<true><<<dim3((2 * NKV_) / 128, M_ / 128), 256, GEMM_SMEM_BYTES>>>(xh, wkvh, oph, M_, 2 * NKV_, HID_);

    // RoPE (fp16 in/out): Q in-place (scaled by 1/sqrt(D)*log2e), K from fused
    // buffer -> kh; V transpose from fused buffer -> vth.
    {
        const float qmul = 0.08838834764831845f * 1.4426950408889634f;
        int totq = B_ * S_ * H_ * (D_ / 2);
        rope_hh_k<<<(totq + 255) / 256, 256>>>(qh, qh, H_, HID_, 0, totq, qmul);
        int totk = B_ * S_ * HKV_ * (D_ / 2);
        rope_hh_k<<<(totk + 255) / 256, 256>>>(oph, kh, HKV_, 2 * NKV_, 0, totk, 1.0f);
        vt_kv_k<<<dim3(S_ / 32, D_ / 32, B_ * HKV_), 256>>>(oph, vth);
    }

    // Flash attention -> fp16 output (overwrites oph after rope/vt consumed it)
    flash_h<<<dim3(S_ / 128, H_, B_), 256, FLASH_SMEM_BYTES>>>(qh, kh, vth, oph);

    // Output projection (fp32 out)
    gemm_h3<false><<<dim3(HID_ / 128, M_ / 128), 256, GEMM_SMEM_BYTES>>>(oph, woh, out, M_, HID_, HID_);
}

// round 17
// speedup vs baseline: 13.5420x; 1.0061x over previous
#include <cuda_runtime.h>
#include <cuda_fp16.h>
#include <cuda_bf16.h>
#include <mma.h>
#include <math.h>
#include <float.h>
#include <stdint.h>

using namespace nvcuda;

// Problem constants
#define B_  2
#define S_  2048
#define HID_ 4096
#define H_  32
#define HKV_ 8
#define D_  128
#define M_  (B_ * S_)    // 4096 rows of x
#define NKV_ (HKV_ * D_) // 1024
#define NFUSE_ (HID_ + 2 * NKV_)  // 6144: Q | K | V columns

// Scratch (device globals)
__device__ __half g_xh   [(size_t)M_ * HID_];
__device__ __half g_wfull[(size_t)NFUSE_ * HID_];  // [Q rows | K rows | V rows] x [K]
__device__ __half g_woh  [(size_t)HID_ * HID_];
__device__ __half g_fused[(size_t)M_ * NFUSE_];    // fused QKV projection output
__device__ __half g_oph  [(size_t)M_ * HID_];      // attn output
__device__ __half g_qh   [(size_t)B_ * S_ * H_ * D_];
__device__ __half g_kh   [(size_t)B_ * S_ * HKV_ * D_];
__device__ __half g_vth  [(size_t)B_ * HKV_ * D_ * S_];

// ---------------------------------------------------------------------------
// helpers
// ---------------------------------------------------------------------------
__device__ __forceinline__ uint32_t smem_u32(const void* p) {
    uint32_t a;
    asm("{ .reg .u64 t; cvta.to.shared.u64 t, %1; cvt.u32.u64 %0, t; }"
        : "=r"(a) : "l"(p));
    return a;
}
#define CP_ASYNC16(dst_u32, src_ptr) \
    asm volatile("cp.async.cg.shared.global [%0], [%1], 16;" \
                 :: "r"(dst_u32), "l"(src_ptr) : "memory")
#define CP_COMMIT() asm volatile("cp.async.commit_group;" ::: "memory")
#define CP_WAIT1()  asm volatile("cp.async.wait_group 1;" ::: "memory")
#define CP_WAIT0()  asm volatile("cp.async.wait_group 0;" ::: "memory")

__device__ __forceinline__ void mma_f16(float d[4], uint32_t a0, uint32_t a1,
                                        uint32_t a2, uint32_t a3,
                                        uint32_t b0, uint32_t b1) {
    asm volatile(
        "mma.sync.aligned.m16n8k16.row.col.f32.f16.f16.f32 "
        "{%0,%1,%2,%3}, {%4,%5,%6,%7}, {%8,%9}, {%0,%1,%2,%3};"
        : "+f"(d[0]), "+f"(d[1]), "+f"(d[2]), "+f"(d[3])
        : "r"(a0), "r"(a1), "r"(a2), "r"(a3), "r"(b0), "r"(b1));
}
__device__ __forceinline__ uint32_t pack_h2(float x, float y) {
    __half2 h = __floats2half2_rn(x, y);
    return *reinterpret_cast<uint32_t*>(&h);
}
__device__ __forceinline__ void ldsm_x4(uint32_t& r0, uint32_t& r1,
                                        uint32_t& r2, uint32_t& r3,
                                        uint32_t addr) {
    asm volatile("ldmatrix.sync.aligned.m8n8.x4.shared.b16 {%0,%1,%2,%3}, [%4];"
                 : "=r"(r0), "=r"(r1), "=r"(r2), "=r"(r3) : "r"(addr));
}

// ---------------------------------------------------------------------------
// Conversions
// ---------------------------------------------------------------------------
__global__ void f2h_k(const float* __restrict__ in,
                      __half* __restrict__ out, int n4)
{
    int i = blockIdx.x * blockDim.x + threadIdx.x;
    if (i >= n4) return;
    float4 v = reinterpret_cast<const float4*>(in)[i];
    reinterpret_cast<__half2*>(out)[2 * i]     = __floats2half2_rn(v.x, v.y);
    reinterpret_cast<__half2*>(out)[2 * i + 1] = __floats2half2_rn(v.z, v.w);
}

// Transpose + convert: in fp32 [R][C] -> out fp16 [C][R]
__global__ __launch_bounds__(256) void f2hT_k(const float* __restrict__ in,
                                              __half* __restrict__ out,
                                              int R, int C)
{
    __shared__ float t[32][33];
    const int tx = threadIdx.x & 31;
    const int ty = threadIdx.x >> 5;
    const int c0 = blockIdx.x * 32;
    const int r0 = blockIdx.y * 32;
    #pragma unroll
    for (int j = 0; j < 32; j += 8)
        t[ty + j][tx] = in[(size_t)(r0 + ty + j) * C + c0 + tx];
    __syncthreads();
    #pragma unroll
    for (int j = 0; j < 32; j += 8)
        out[(size_t)(c0 + ty + j) * R + r0 + tx] = __float2half_rn(t[tx][ty + j]);
}

// ---------------------------------------------------------------------------
// FP16 GEMM: C[M,N] = A[M,K](fp16) @ BT[N,K](fp16)^T, templated output.
// 128x128 block tile, BK=64, 256 threads (8 warps, 4x2, 32x64 warp tile).
// 3-stage cp.async, 110.6KB smem -> 2 CTAs/SM.
// ---------------------------------------------------------------------------
constexpr int G3ST = 72;
constexpr int G3A_H = 128 * G3ST;
constexpr int G3STG_H = 2 * G3A_H;
constexpr int GEMM_SMEM_BYTES = 3 * G3STG_H * 2;

template <bool HALF_OUT>
__global__ __launch_bounds__(256, 2) void gemm_h3(const __half* __restrict__ A,
                                                  const __half* __restrict__ BT,
                                                  void* __restrict__ Cv,
                                                  int M, int N, int K)
{
    extern __shared__ __half hsm[];
    const int tid  = threadIdx.x;
    const int warp = tid >> 5;
    const int lane = tid & 31;
    const int lr   = lane >> 2;
    const int lc   = lane & 3;
    const int g    = lane >> 3;
    const int li   = lane & 7;
    const int wr   = warp & 3;
    const int wc   = warp >> 2;

    const size_t bm0 = (size_t)blockIdx.y * 128;
    const size_t bn0 = (size_t)blockIdx.x * 128;
    const uint32_t sbase = smem_u32(hsm);

    auto issue_stage = [&](int slot, int k0) {
        const uint32_t sa = sbase + (uint32_t)(slot * G3STG_H) * 2u;
        const uint32_t sb = sa + (uint32_t)G3A_H * 2u;
        #pragma unroll
        for (int j = 0; j < 4; ++j) {
            int li2 = j * 256 + tid;
            int row = li2 >> 3;
            int c   = li2 & 7;
            const __half* src = A + (bm0 + row) * K + k0 + c * 8;
            CP_ASYNC16(sa + (uint32_t)(row * G3ST + c * 8) * 2u, src);
        }
        #pragma unroll
        for (int j = 0; j < 4; ++j) {
            int li2 = j * 256 + tid;
            int row = li2 >> 3;
            int c   = li2 & 7;
            const __half* src = BT + (bn0 + row) * K + k0 + c * 8;
            CP_ASYNC16(sb + (uint32_t)(row * G3ST + c * 8) * 2u, src);
        }
        CP_COMMIT();
    };

    float acc[2][8][4];
    #pragma unroll
    for (int mi = 0; mi < 2; ++mi)
        #pragma unroll
        for (int nf = 0; nf < 8; ++nf)
            #pragma unroll
            for (int e = 0; e < 4; ++e) acc[mi][nf][e] = 0.f;

    const int NIT = K >> 6;
    issue_stage(0, 0);
    issue_stage(1, 64);

    const uint32_t aoff = (uint32_t)((((g & 1) * 8 + li) * G3ST + (g >> 1) * 8) * 2);
    const uint32_t boff = (uint32_t)((((g >> 1) * 8 + li) * G3ST + (g & 1) * 8) * 2);

    for (int s = 0; s < NIT; ++s) {
        if (s >= NIT - 2) { CP_WAIT0(); } else { CP_WAIT1(); }
        __syncthreads();
        if (s + 2 < NIT) issue_stage((s + 2) % 3, (s + 2) * 64);

        const uint32_t abase = sbase + (uint32_t)((s % 3) * G3STG_H) * 2u +
                               (uint32_t)(wr * 32 * G3ST) * 2u + aoff;
        const uint32_t bbase = sbase + (uint32_t)((s % 3) * G3STG_H + G3A_H) * 2u +
                               (uint32_t)(wc * 64 * G3ST) * 2u + boff;

        #pragma unroll
        for (int ks = 0; ks < 4; ++ks) {
            uint32_t af[2][4];
            #pragma unroll
            for (int mi = 0; mi < 2; ++mi)
                ldsm_x4(af[mi][0], af[mi][1], af[mi][2], af[mi][3],
                        abase + (uint32_t)(mi * 16 * G3ST + ks * 16) * 2u);
            #pragma unroll
            for (int p = 0; p < 4; ++p) {
                uint32_t b0, b1, b2, b3;
                ldsm_x4(b0, b1, b2, b3,
                        bbase + (uint32_t)(p * 16 * G3ST + ks * 16) * 2u);
                #pragma unroll
                for (int mi = 0; mi < 2; ++mi) {
                    mma_f16(acc[mi][2 * p],     af[mi][0], af[mi][1],
                            af[mi][2], af[mi][3], b0, b1);
                    mma_f16(acc[mi][2 * p + 1], af[mi][0], af[mi][1],
                            af[mi][2], af[mi][3], b2, b3);
                }
            }
        }
    }

    // Epilogue
    #pragma unroll
    for (int mi = 0; mi < 2; ++mi) {
        const size_t r0 = bm0 + wr * 32 + mi * 16 + lr;
        #pragma unroll
        for (int nf = 0; nf < 8; ++nf) {
            const size_t col = bn0 + wc * 64 + nf * 8 + 2 * lc;
            if (HALF_OUT) {
                __half* C = (__half*)Cv;
                *reinterpret_cast<uint32_t*>(C + r0 * N + col) =
                    pack_h2(acc[mi][nf][0], acc[mi][nf][1]);
                *reinterpret_cast<uint32_t*>(C + (r0 + 8) * N + col) =
                    pack_h2(acc[mi][nf][2], acc[mi][nf][3]);
            } else {
                float* C = (float*)Cv;
                *reinterpret_cast<float2*>(C + r0 * N + col) =
                    make_float2(acc[mi][nf][0], acc[mi][nf][1]);
                *reinterpret_cast<float2*>(C + (r0 + 8) * N + col) =
                    make_float2(acc[mi][nf][2], acc[mi][nf][3]);
            }
        }
    }
}

// ---------------------------------------------------------------------------
// RoPE fp16->fp16: reads in[(b*S+s)*in_row + col_off + h*D + i], rotation in
// fp32, writes out in standard [b,s,nh,D] layout (scaled by mul).
// ---------------------------------------------------------------------------
__global__ void rope_hh_k(const __half* __restrict__ in, __half* __restrict__ out,
                          int nh, int in_row, int col_off, int total, float mul)
{
    int idx = blockIdx.x * blockDim.x + threadIdx.x;
    if (idx >= total) return;
    const int half = D_ / 2;
    int i = idx & (half - 1);
    int rest = idx >> 6;
    int h = rest % nh;
    rest /= nh;
    int s = rest % S_;
    int b = rest / S_;

    float inv = __expf(-logf(10000.0f) * (float)i / (float)half);
    float ang = (float)s * inv;
    float sn, cs;
    sincosf(ang, &sn, &cs);

    size_t ib = (size_t)(b * S_ + s) * in_row + col_off + h * D_;
    float x1 = __half2float(in[ib + i]);
    float x2 = __half2float(in[ib + i + half]);
    size_t ob = ((size_t)((b * S_ + s) * nh + h)) * D_;
    out[ob + i]        = __float2half_rn((x1 * cs - x2 * sn) * mul);
    out[ob + i + half] = __float2half_rn((x2 * cs + x1 * sn) * mul);
}

// ---------------------------------------------------------------------------
// V transpose from fused-QKV buffer: in[(b*S+s)*NFUSE + 5120 + kvh*128 + d]
// -> out [b][kvh][d][s]
// ---------------------------------------------------------------------------
__global__ __launch_bounds__(256) void vt_kv_k(const __half* __restrict__ in,
                                               __half* __restrict__ out)
{
    __shared__ __half t[32][34];
    const int tx = threadIdx.x & 31;
    const int ty = threadIdx.x >> 5;
    const int s0 = blockIdx.x * 32;
    const int d0 = blockIdx.y * 32;
    const int bk = blockIdx.z;
    const int b  = bk >> 3;
    const int kvh = bk & 7;

    #pragma unroll
    for (int j = 0; j < 32; j += 8)
        t[ty + j][tx] = in[(size_t)(b * S_ + s0 + ty + j) * NFUSE_ +
                           HID_ + NKV_ + kvh * D_ + d0 + tx];
    __syncthreads();
    #pragma unroll
    for (int j = 0; j < 32; j += 8)
        out[((size_t)(bk * D_ + d0 + ty + j)) * S_ + s0 + tx] = t[tx][ty + j];
}

// ---------------------------------------------------------------------------
// Flash attention (unchanged): fp16 mma + ldmatrix, FA2.
// ---------------------------------------------------------------------------
constexpr int KST = 136;
constexpr int VST = 72;
constexpr int QSM_HALVES = 128 * KST;
constexpr int KV_STG = 64 * KST + 128 * VST;
constexpr int FLASH_SMEM_BYTES = (QSM_HALVES + 2 * KV_STG) * 2;

__global__ __launch_bounds__(256, 2) void flash_h(const __half* __restrict__ Qg,
                                                  const __half* __restrict__ Kg,
                                                  const __half* __restrict__ Vtg,
                                                  __half* __restrict__ Og)
{
    extern __shared__ __half smh[];
    const int tid  = threadIdx.x;
    const int warp = tid >> 5;
    const int lane = tid & 31;
    const int lr   = lane >> 2;
    const int lc   = lane & 3;
    const int g    = lane >> 3;
    const int li   = lane & 7;
    const int qtile = gridDim.x - 1 - blockIdx.x;
    const int h    = blockIdx.y;
    const int b    = blockIdx.z;
    const int q0   = qtile * 128;
    const int kvh  = h >> 2;
    const uint32_t sbase = smem_u32(smh);

    #pragma unroll
    for (int it = 0; it < 8; ++it) {
        int li2  = it * 256 + tid;
        int row = li2 >> 4;
        int c   = li2 & 15;
        const __half* src = Qg + ((size_t)((b * S_ + q0 + row) * H_ + h)) * D_ + c * 8;
        CP_ASYNC16(sbase + (uint32_t)(row * KST + c * 8) * 2u, src);
    }
    CP_COMMIT();

    float d[16][4];
    #pragma unroll
    for (int i = 0; i < 16; ++i)
        #pragma unroll
        for (int j = 0; j < 4; ++j) d[i][j] = 0.f;
    float m0 = -1e30f, m1 = -1e30f, l0 = 0.f, l1 = 0.f;

    auto issue_kv = [&](int t) {
        const int s = t & 1;
        const uint32_t kb = sbase + (uint32_t)(QSM_HALVES + s * KV_STG) * 2u;
        const uint32_t vb = kb + (uint32_t)(64 * KST) * 2u;
        const int kv0 = t * 64;
        #pragma unroll
        for (int it = 0; it < 4; ++it) {
            int li2  = it * 256 + tid;
            int row = li2 >> 4;
            int c   = li2 & 15;
            const __half* src = Kg + ((size_t)((b * S_ + kv0 + row) * HKV_ + kvh)) * D_ + c * 8;
            CP_ASYNC16(kb + (uint32_t)(row * KST + c * 8) * 2u, src);
        }
        #pragma unroll
        for (int it = 0; it < 4; ++it) {
            int li2  = it * 256 + tid;
            int row = li2 >> 3;
            int c   = li2 & 7;
            const __half* src = Vtg + ((size_t)((b * HKV_ + kvh) * D_ + row)) * S_ + kv0 + c * 8;
            CP_ASYNC16(vb + (uint32_t)(row * VST + c * 8) * 2u, src);
        }
        CP_COMMIT();
    };

    const int tmax = 2 * qtile + 1;
    const int wrow_lo = q0 + warp * 16;
    const int wrow_hi = wrow_lo + 15;
    const uint32_t qaddr = sbase +
        (uint32_t)(((warp * 16 + (g & 1) * 8 + li) * KST + (g >> 1) * 8) * 2);
    issue_kv(0);

    for (int t = 0; t <= tmax; ++t) {
        CP_WAIT0();
        __syncthreads();
        if (t < tmax) issue_kv(t + 1);

        const int kv0 = t * 64;
        if (kv0 <= wrow_hi) {
            const uint32_t kwb = sbase +
                (uint32_t)((QSM_HALVES + (t & 1) * KV_STG) * 2);
            const uint32_t kaddr = kwb +
                (uint32_t)((((g >> 1) * 8 + li) * KST + (g & 1) * 8) * 2);
            const uint32_t vaddr = kwb + (uint32_t)(64 * KST * 2) +
                (uint32_t)((((g >> 1) * 8 + li) * VST + (g & 1) * 8) * 2);

            float s[8][4];
            #pragma unroll
            for (int nf = 0; nf < 8; ++nf)
                #pragma unroll
                for (int e = 0; e < 4; ++e) s[nf][e] = 0.f;
            #pragma unroll
            for (int j = 0; j < 8; ++j) {
                uint32_t qa0, qa1, qa2, qa3;
                ldsm_x4(qa0, qa1, qa2, qa3, qaddr + j * 32);
                #pragma unroll
                for (int nfp = 0; nfp < 4; ++nfp) {
                    uint32_t kb0, kb1, kb2, kb3;
                    ldsm_x4(kb0, kb1, kb2, kb3,
                            kaddr + nfp * (16 * KST * 2) + j * 32);
                    mma_f16(s[2 * nfp],     qa0, qa1, qa2, qa3, kb0, kb1);
                    mma_f16(s[2 * nfp + 1], qa0, qa1, qa2, qa3, kb2, kb3);
                }
            }

            if (kv0 + 63 > wrow_lo) {
                const int row0 = wrow_lo + lr;
                #pragma unroll
                for (int nf = 0; nf < 8; ++nf) {
                    int c0 = kv0 + 8 * nf + 2 * lc;
                    if (c0 > row0)         s[nf][0] = -1e30f;
                    if (c0 + 1 > row0)     s[nf][1] = -1e30f;
                    if (c0 > row0 + 8)     s[nf][2] = -1e30f;
                    if (c0 + 1 > row0 + 8) s[nf][3] = -1e30f;
                }
            }

            float mx0 = -1e30f, mx1 = -1e30f;
            #pragma unroll
            for (int nf = 0; nf < 8; ++nf) {
                mx0 = fmaxf(mx0, fmaxf(s[nf][0], s[nf][1]));
                mx1 = fmaxf(mx1, fmaxf(s[nf][2], s[nf][3]));
            }
            mx0 = fmaxf(mx0, __shfl_xor_sync(0xFFFFFFFFu, mx0, 1));
            mx0 = fmaxf(mx0, __shfl_xor_sync(0xFFFFFFFFu, mx0, 2));
            mx1 = fmaxf(mx1, __shfl_xor_sync(0xFFFFFFFFu, mx1, 1));
            mx1 = fmaxf(mx1, __shfl_xor_sync(0xFFFFFFFFu, mx1, 2));
            float m0n = fmaxf(m0, mx0), m1n = fmaxf(m1, mx1);
            float al0 = exp2f(m0 - m0n), al1 = exp2f(m1 - m1n);
            float su0 = 0.f, su1 = 0.f;
            #pragma unroll
            for (int nf = 0; nf < 8; ++nf) {
                s[nf][0] = exp2f(s[nf][0] - m0n);
                s[nf][1] = exp2f(s[nf][1] - m0n);
                s[nf][2] = exp2f(s[nf][2] - m1n);
                s[nf][3] = exp2f(s[nf][3] - m1n);
                su0 += s[nf][0] + s[nf][1];
                su1 += s[nf][2] + s[nf][3];
            }
            su0 += __shfl_xor_sync(0xFFFFFFFFu, su0, 1);
            su0 += __shfl_xor_sync(0xFFFFFFFFu, su0, 2);
            su1 += __shfl_xor_sync(0xFFFFFFFFu, su1, 1);
            su1 += __shfl_xor_sync(0xFFFFFFFFu, su1, 2);
            l0 = l0 * al0 + su0;  m0 = m0n;
            l1 = l1 * al1 + su1;  m1 = m1n;

            #pragma unroll
            for (int nf = 0; nf < 16; ++nf) {
                d[nf][0] *= al0; d[nf][1] *= al0;
                d[nf][2] *= al1; d[nf][3] *= al1;
            }

            #pragma unroll
            for (int j = 0; j < 4; ++j) {
                uint32_t pa0 = pack_h2(s[2*j][0],   s[2*j][1]);
                uint32_t pa1 = pack_h2(s[2*j][2],   s[2*j][3]);
                uint32_t pa2 = pack_h2(s[2*j+1][0], s[2*j+1][1]);
                uint32_t pa3 = pack_h2(s[2*j+1][2], s[2*j+1][3]);
                #pragma unroll
                for (int nfp = 0; nfp < 8; ++nfp) {
                    uint32_t vb0, vb1, vb2, vb3;
                    ldsm_x4(vb0, vb1, vb2, vb3,
                            vaddr + nfp * (16 * VST * 2) + j * 32);
                    mma_f16(d[2 * nfp],     pa0, pa1, pa2, pa3, vb0, vb1);
                    mma_f16(d[2 * nfp + 1], pa0, pa1, pa2, pa3, vb2, vb3);
                }
            }
        }
    }

    const float il0 = 1.f / l0, il1 = 1.f / l1;
    const int row0 = q0 + warp * 16 + lr;
    __half* o0 = Og + ((size_t)((b * S_ + row0) * H_ + h)) * D_;
    __half* o1 = Og + ((size_t)((b * S_ + row0 + 8) * H_ + h)) * D_;
    #pragma unroll
    for (int nf = 0; nf < 16; ++nf) {
        *reinterpret_cast<uint32_t*>(o0 + 8 * nf + 2 * lc) =
            pack_h2(d[nf][0] * il0, d[nf][1] * il0);
        *reinterpret_cast<uint32_t*>(o1 + 8 * nf + 2 * lc) =
            pack_h2(d[nf][2] * il1, d[nf][3] * il1);
    }
}

// ---------------------------------------------------------------------------
// Launcher
// ---------------------------------------------------------------------------
extern "C" void kernel_launch(void* const* d_in, const int* in_sizes, int n_in,
                              void* d_out, int out_size)
{
    const float* x  = (const float*)d_in[0];
    const float* wq = (const float*)d_in[1];
    const float* wk = (const float*)d_in[2];
    const float* wv = (const float*)d_in[3];
    const float* wo = (const float*)d_in[4];
    float* out = (float*)d_out;

    __half *xh, *wfull, *woh, *fused, *oph, *qh, *kh, *vth;
    cudaGetSymbolAddress((void**)&xh, g_xh);
    cudaGetSymbolAddress((void**)&wfull, g_wfull);
    cudaGetSymbolAddress((void**)&woh, g_woh);
    cudaGetSymbolAddress((void**)&fused, g_fused);
    cudaGetSymbolAddress((void**)&oph, g_oph);
    cudaGetSymbolAddress((void**)&qh, g_qh);
    cudaGetSymbolAddress((void**)&kh, g_kh);
    cudaGetSymbolAddress((void**)&vth, g_vth);

    cudaFuncSetAttribute(gemm_h3<false>, cudaFuncAttributeMaxDynamicSharedMemorySize,
                         GEMM_SMEM_BYTES);
    cudaFuncSetAttribute(gemm_h3<true>, cudaFuncAttributeMaxDynamicSharedMemorySize,
                         GEMM_SMEM_BYTES);
    cudaFuncSetAttribute(flash_h, cudaFuncAttributeMaxDynamicSharedMemorySize,
                         FLASH_SMEM_BYTES);

    // Convert inputs: x -> fp16; all projection weights -> one fused
    // TRANSPOSED buffer [Q(4096) | K(1024) | V(1024)] x [4096].
    {
        int n4 = (M_ * HID_) / 4;
        f2h_k<<<(n4 + 255) / 256, 256>>>(x, xh, n4);
        f2hT_k<<<dim3(HID_ / 32, HID_ / 32), 256>>>(wq, wfull, HID_, HID_);
        f2hT_k<<<dim3(NKV_ / 32, HID_ / 32), 256>>>(wk, wfull + (size_t)HID_ * HID_, HID_, NKV_);
        f2hT_k<<<dim3(NKV_ / 32, HID_ / 32), 256>>>(wv, wfull + (size_t)(HID_ + NKV_) * HID_, HID_, NKV_);
        f2hT_k<<<dim3(HID_ / 32, HID_ / 32), 256>>>(wo, woh, HID_, HID_);
    }

    // Fused QKV projection: one GEMM, N = 6144
    gemm_h3<true><<<dim3(NFUSE_ / 128, M_ / 128), 256, GEMM_SMEM_BYTES>>>(
        xh, wfull, fused, M_, NFUSE_, HID_);

    // RoPE (fp16 in/out) from fused buffer; V transpose from fused buffer
    {
        const float qmul = 0.08838834764831845f * 1.4426950408889634f;
        int totq = B_ * S_ * H_ * (D_ / 2);
        rope_hh_k<<<(totq + 255) / 256, 256>>>(fused, qh, H_, NFUSE_, 0, totq, qmul);
        int totk = B_ * S_ * HKV_ * (D_ / 2);
        rope_hh_k<<<(totk + 255) / 256, 256>>>(fused, kh, HKV_, NFUSE_, HID_, totk, 1.0f);
        vt_kv_k<<<dim3(S_ / 32, D_ / 32, B_ * HKV_), 256>>>(fused, vth);
    }

    // Flash attention -> fp16 output
    flash_h<<<dim3(S_ / 128, H_, B_), 256, FLASH_SMEM_BYTES>>>(qh, kh, vth, oph);

    // Output projection (fp32 out)
    gemm_h3<false><<<dim3(HID_ / 128, M_ / 128), 256, GEMM_SMEM_BYTES>>>(oph, woh, out, M_, HID_, HID_);
}